// round 1
// baseline (speedup 1.0000x reference)
#include <cuda_runtime.h>

#define TPB 256

// smem pitches (floats), all multiples of 4 for float4 access
#define LDX 68    // sx:  64 x 64  (also reused for att2 64x64)
#define LDH 260   // h:   64 x 256 (hidden buffers / att_in)
#define LDM 132   // m1/m2: 64 x 128

// smem layout (floats)
#define OFF_SX    0
#define OFF_H     (OFF_SX + 64*LDX)          // 4352
#define OFF_M1    (OFF_H  + 64*LDH)          // 20992
#define OFF_M2    (OFF_M1 + 64*LDM)          // 29440
#define OFF_WB    (OFF_M2 + 64*LDM)          // 37888
#define OFF_GS    (OFF_WB + 16384)           // 54272
#define OFF_VIS   (OFF_GS + 128)             // 54400
#define OFF_ES    (OFF_VIS + 64)             // 54464
#define OFF_WSM   (OFF_ES + 64)              // 54528
#define OFF_RED   (OFF_WSM + 64)             // 54592
#define OFF_JOINT (OFF_RED + 32)             // 54624
#define OFF_H3    (OFF_JOINT + 144)          // 54768
#define OFF_M3    (OFF_H3 + 256)             // 55024
#define SMEM_FLOATS (OFF_M3 + 128)           // 55152
#define SMEM_BYTES  (SMEM_FLOATS * 4)        // 220608

// 64 x N GEMM: C = act(A[64xK] @ B[KxN] + bias)
// A in smem (pitch lda), B in global (L2-resident), staged into wb in 64-row chunks.
// Thread tile: 4 rows x (N/16) cols; columns interleaved as tc*4 + s*64 so that
// B float4 loads are bank-conflict-free and A loads broadcast.
template<int N, bool RELU>
__device__ __forceinline__ void gemm64(
    const float* __restrict__ A, int lda,
    const float* __restrict__ Bg, const float* __restrict__ bias,
    float* __restrict__ C, int ldc, int K, float* __restrict__ wb)
{
    constexpr int NS = N / 64;   // 4-wide column slices per thread
    const int tid = threadIdx.x;
    const int tr  = tid >> 4;    // 0..15
    const int tc  = tid & 15;    // 0..15
    const int r0  = tr * 4;

    float acc[4][NS * 4];
    #pragma unroll
    for (int r = 0; r < 4; r++)
        #pragma unroll
        for (int c = 0; c < NS * 4; c++) acc[r][c] = 0.0f;

    for (int kc = 0; kc < K; kc += 64) {
        // stage B chunk: 64 x N floats (contiguous rows)
        const float* src = Bg + kc * N;
        #pragma unroll
        for (int i = tid * 4; i < 64 * N; i += TPB * 4) {
            *(float4*)(wb + i) = *(const float4*)(src + i);
        }
        __syncthreads();

        #pragma unroll 4
        for (int k4 = 0; k4 < 64; k4 += 4) {
            float4 av[4];
            #pragma unroll
            for (int r = 0; r < 4; r++)
                av[r] = *(const float4*)(A + (r0 + r) * lda + kc + k4);
            const float* avf = reinterpret_cast<const float*>(av);

            #pragma unroll
            for (int kk = 0; kk < 4; kk++) {
                const float a0 = avf[0 * 4 + kk];
                const float a1 = avf[1 * 4 + kk];
                const float a2 = avf[2 * 4 + kk];
                const float a3 = avf[3 * 4 + kk];
                #pragma unroll
                for (int s = 0; s < NS; s++) {
                    const float4 b4 = *(const float4*)(wb + (k4 + kk) * N + s * 64 + tc * 4);
                    acc[0][s*4+0] += a0 * b4.x; acc[0][s*4+1] += a0 * b4.y;
                    acc[0][s*4+2] += a0 * b4.z; acc[0][s*4+3] += a0 * b4.w;
                    acc[1][s*4+0] += a1 * b4.x; acc[1][s*4+1] += a1 * b4.y;
                    acc[1][s*4+2] += a1 * b4.z; acc[1][s*4+3] += a1 * b4.w;
                    acc[2][s*4+0] += a2 * b4.x; acc[2][s*4+1] += a2 * b4.y;
                    acc[2][s*4+2] += a2 * b4.z; acc[2][s*4+3] += a2 * b4.w;
                    acc[3][s*4+0] += a3 * b4.x; acc[3][s*4+1] += a3 * b4.y;
                    acc[3][s*4+2] += a3 * b4.z; acc[3][s*4+3] += a3 * b4.w;
                }
            }
        }
        __syncthreads();
    }

    // epilogue: bias + optional relu, write to C
    #pragma unroll
    for (int s = 0; s < NS; s++) {
        const int c = s * 64 + tc * 4;
        const float4 bb = *(const float4*)(bias + c);
        #pragma unroll
        for (int r = 0; r < 4; r++) {
            float4 v;
            v.x = acc[r][s*4+0] + bb.x;
            v.y = acc[r][s*4+1] + bb.y;
            v.z = acc[r][s*4+2] + bb.z;
            v.w = acc[r][s*4+3] + bb.w;
            if (RELU) {
                v.x = fmaxf(v.x, 0.f); v.y = fmaxf(v.y, 0.f);
                v.z = fmaxf(v.z, 0.f); v.w = fmaxf(v.w, 0.f);
            }
            *(float4*)(C + (r0 + r) * ldc + c) = v;
        }
    }
    __syncthreads();
}

__global__ void __launch_bounds__(TPB)
value_net_kernel(
    const float* __restrict__ state,
    const float* __restrict__ w1a, const float* __restrict__ b1a,
    const float* __restrict__ w1b, const float* __restrict__ b1b,
    const float* __restrict__ w2a, const float* __restrict__ b2a,
    const float* __restrict__ w2b, const float* __restrict__ b2b,
    const float* __restrict__ wa1, const float* __restrict__ ba1,
    const float* __restrict__ wa2, const float* __restrict__ ba2,
    const float* __restrict__ wa3, const float* __restrict__ ba3,
    const float* __restrict__ w3a, const float* __restrict__ b3a,
    const float* __restrict__ w3b, const float* __restrict__ b3b,
    const float* __restrict__ w3c, const float* __restrict__ b3c,
    float* __restrict__ out)
{
    extern __shared__ float sm[];
    float* sx    = sm + OFF_SX;
    float* h     = sm + OFF_H;
    float* m1    = sm + OFF_M1;
    float* m2    = sm + OFF_M2;
    float* wb    = sm + OFF_WB;
    float* gs    = sm + OFF_GS;
    float* visf  = sm + OFF_VIS;
    float* es    = sm + OFF_ES;
    float* wsm   = sm + OFF_WSM;
    float* red   = sm + OFF_RED;
    float* joint = sm + OFF_JOINT;
    float* h3    = sm + OFF_H3;
    float* m3    = sm + OFF_M3;

    const int b   = blockIdx.x;
    const int tid = threadIdx.x;
    const float* gx = state + (size_t)b * 64 * 64;

    // ---- load state (64x64) into pitched smem, extract vis + self_state ----
    #pragma unroll
    for (int i = tid * 4; i < 4096; i += TPB * 4) {
        float4 v = *(const float4*)(gx + i);
        int row = i >> 6, col = i & 63;
        *(float4*)(sx + row * LDX + col) = v;
    }
    if (tid < 64) visf[tid] = (gx[tid * 64 + 61] > 0.0f) ? 1.0f : 0.0f;
    if (tid < 9)  joint[tid] = gx[tid];  // state[b,0,0:9]
    __syncthreads();

    // ---- MLP1: 64 -> 256 (relu) -> 128 (relu) ----
    gemm64<256, true >(sx, LDX, w1a, b1a, h,  LDH, 64,  wb);
    gemm64<128, true >(h,  LDH, w1b, b1b, m1, LDM, 256, wb);
    // ---- MLP2 (uses un-masked m1): 128 -> 256 (relu) -> 128 (no relu) ----
    gemm64<256, true >(m1, LDM, w2a, b2a, h,  LDH, 128, wb);
    gemm64<128, false>(h,  LDH, w2b, b2b, m2, LDM, 256, wb);

    // ---- visibility mask on m1 and m2 ----
    for (int i = tid; i < 64 * 128; i += TPB) {
        int n = i >> 7, c = i & 127;
        float v = visf[n];
        m1[n * LDM + c] *= v;
        m2[n * LDM + c] *= v;
    }
    __syncthreads();

    // ---- gs = mean over n of masked m1 ----
    if (tid < 128) {
        float s = 0.0f;
        #pragma unroll 8
        for (int n = 0; n < 64; n++) s += m1[n * LDM + tid];
        gs[tid] = s * (1.0f / 64.0f);
    }
    __syncthreads();

    // ---- att_in = [m1 | gs] into h (64x256) ----
    for (int i = tid; i < 64 * 128; i += TPB) {
        int n = i >> 7, c = i & 127;
        h[n * LDH + c]       = m1[n * LDM + c];
        h[n * LDH + 128 + c] = gs[c];
    }
    __syncthreads();

    // ---- attention MLP: 256 -> 128 (relu) -> 64 (relu) ----
    gemm64<128, true>(h,  LDH, wa1, ba1, m1, LDM, 256, wb);
    gemm64<64,  true>(m1, LDM, wa2, ba2, sx, LDX, 128, wb);  // att2 into sx

    // ---- scores: 64 -> 1, then masked exp ----
    if (tid < 64) {
        float s = ba3[0];
        #pragma unroll 8
        for (int i = 0; i < 64; i++) s += sx[tid * LDX + i] * wa3[i];
        es[tid] = (s != 0.0f) ? expf(s) : 0.0f;
    }
    __syncthreads();
    if (tid < 64) {
        float v = es[tid];
        #pragma unroll
        for (int o = 16; o > 0; o >>= 1) v += __shfl_xor_sync(0xffffffffu, v, o);
        if ((tid & 31) == 0) red[tid >> 5] = v;
    }
    __syncthreads();
    {
        float ssum = red[0] + red[1];
        if (tid < 64) wsm[tid] = es[tid] / ssum;
    }
    __syncthreads();

    // ---- weighted = sum_n wsm[n] * m2[n,:] -> joint[9:137] ----
    if (tid < 128) {
        float acc = 0.0f;
        #pragma unroll 8
        for (int n = 0; n < 64; n++) acc += wsm[n] * m2[n * LDM + tid];
        joint[9 + tid] = acc;
    }
    __syncthreads();

    // ---- final MLP: 137 -> 256 (relu) -> 128 (relu) -> 1 ----
    {
        float acc = b3a[tid];
        for (int i = 0; i < 137; i++) acc += joint[i] * w3a[i * 256 + tid];
        h3[tid] = fmaxf(acc, 0.0f);
    }
    __syncthreads();
    if (tid < 128) {
        float acc = b3b[tid];
        #pragma unroll 8
        for (int i = 0; i < 256; i++) acc += h3[i] * w3b[i * 128 + tid];
        m3[tid] = fmaxf(acc, 0.0f);
    }
    __syncthreads();
    if (tid < 128) {
        float v = m3[tid] * w3c[tid];
        #pragma unroll
        for (int o = 16; o > 0; o >>= 1) v += __shfl_xor_sync(0xffffffffu, v, o);
        if ((tid & 31) == 0) red[tid >> 5] = v;
    }
    __syncthreads();
    if (tid == 0) out[b] = red[0] + red[1] + red[2] + red[3] + b3c[0];
}

extern "C" void kernel_launch(void* const* d_in, const int* in_sizes, int n_in,
                              void* d_out, int out_size)
{
    (void)in_sizes; (void)n_in; (void)out_size;
    const float* state = (const float*)d_in[0];
    const float* w1a = (const float*)d_in[1];  const float* b1a = (const float*)d_in[2];
    const float* w1b = (const float*)d_in[3];  const float* b1b = (const float*)d_in[4];
    const float* w2a = (const float*)d_in[5];  const float* b2a = (const float*)d_in[6];
    const float* w2b = (const float*)d_in[7];  const float* b2b = (const float*)d_in[8];
    const float* wa1 = (const float*)d_in[9];  const float* ba1 = (const float*)d_in[10];
    const float* wa2 = (const float*)d_in[11]; const float* ba2 = (const float*)d_in[12];
    const float* wa3 = (const float*)d_in[13]; const float* ba3 = (const float*)d_in[14];
    const float* w3a = (const float*)d_in[15]; const float* b3a = (const float*)d_in[16];
    const float* w3b = (const float*)d_in[17]; const float* b3b = (const float*)d_in[18];
    const float* w3c = (const float*)d_in[19]; const float* b3c = (const float*)d_in[20];
    float* out = (float*)d_out;

    cudaFuncSetAttribute(value_net_kernel,
                         cudaFuncAttributeMaxDynamicSharedMemorySize, SMEM_BYTES);

    value_net_kernel<<<4096, TPB, SMEM_BYTES>>>(
        state,
        w1a, b1a, w1b, b1b, w2a, b2a, w2b, b2b,
        wa1, ba1, wa2, ba2, wa3, ba3,
        w3a, b3a, w3b, b3b, w3c, b3c,
        out);
}

// round 4
// speedup vs baseline: 1.6635x; 1.6635x over previous
#include <cuda_runtime.h>
#include <cuda_bf16.h>
#include <cstdint>

#define TPB 256

// ===================== PTX wrappers (sm_100 base ISA) =====================
__device__ __forceinline__ uint32_t smem_u32(const void* p){
    uint32_t a;
    asm("{ .reg .u64 t; cvta.to.shared.u64 t, %1; cvt.u32.u64 %0, t; }":"=r"(a):"l"(p));
    return a;
}
#define LDSM4(r, a) \
    asm volatile("ldmatrix.sync.aligned.m8n8.x4.shared.b16 {%0,%1,%2,%3}, [%4];" \
        :"=r"((r)[0]),"=r"((r)[1]),"=r"((r)[2]),"=r"((r)[3]):"r"(a))
#define LDSM2(r, a) \
    asm volatile("ldmatrix.sync.aligned.m8n8.x2.shared.b16 {%0,%1}, [%2];" \
        :"=r"((r)[0]),"=r"((r)[1]):"r"(a))
#define MMA_BF16(c, a, b) \
    asm volatile("mma.sync.aligned.m16n8k16.row.col.f32.bf16.bf16.f32 " \
        "{%0,%1,%2,%3},{%4,%5,%6,%7},{%8,%9},{%0,%1,%2,%3};" \
        :"+f"((c)[0]),"+f"((c)[1]),"+f"((c)[2]),"+f"((c)[3]) \
        :"r"((a)[0]),"r"((a)[1]),"r"((a)[2]),"r"((a)[3]),"r"((b)[0]),"r"((b)[1]))

__device__ __forceinline__ void split2(float v0, float v1, uint32_t& hi, uint32_t& lo){
    __nv_bfloat16 h0 = __float2bfloat16(v0), h1 = __float2bfloat16(v1);
    float r0 = v0 - __bfloat162float(h0), r1 = v1 - __bfloat162float(h1);
    __nv_bfloat162 H; H.x = h0; H.y = h1;
    __nv_bfloat162 L; L.x = __float2bfloat16(r0); L.y = __float2bfloat16(r1);
    hi = *(uint32_t*)&H; lo = *(uint32_t*)&L;
}

// ===================== pre-split, transposed weights =====================
// Per layer: W^T stored N rows x PK cols (PK = K+8), bf16, hi plane then lo plane.
// Layers: 0:w1a(64,256) 1:w1b(256,128) 2:w2a(128,256) 3:w2b(256,128)
//         4:wa1[:128](128,128) 5:wa2(128,64)
__device__ __align__(128) uint8_t g_wb[587776];

__global__ void prep_kernel(const float* __restrict__ w1a, const float* __restrict__ w1b,
                            const float* __restrict__ w2a, const float* __restrict__ w2b,
                            const float* __restrict__ wa1, const float* __restrict__ wa2)
{
    const float* W[6] = {w1a, w1b, w2a, w2b, wa1, wa2};
    const int   K[6]  = {64, 256, 128, 256, 128, 128};
    const int   N[6]  = {256, 128, 256, 128, 128, 64};
    const int   EO[7] = {0, 16384, 49152, 81920, 114688, 131072, 139264};
    const int   BO[6] = {0, 73728, 208896, 348160, 483328, 552960};
    for (int idx = blockIdx.x*blockDim.x + threadIdx.x; idx < 139264;
         idx += gridDim.x*blockDim.x) {
        int l = 0;
        while (idx >= EO[l+1]) l++;
        int e = idx - EO[l];
        int k = e % K[l], n = e / K[l];
        int PK = K[l] + 8;
        float w = W[l][(size_t)k * N[l] + n];
        __nv_bfloat16 h = __float2bfloat16(w);
        float rr = w - __bfloat162float(h);
        __nv_bfloat16 lo = __float2bfloat16(rr);
        uint8_t* base = g_wb + BO[l];
        *(__nv_bfloat16*)(base + ((size_t)n*PK + k)*2) = h;
        *(__nv_bfloat16*)(base + (size_t)N[l]*PK*2 + ((size_t)n*PK + k)*2) = lo;
    }
}

// ===================== smem layout =====================
#define OFF_WBUF    0
#define WBUF_B      69632
#define OFF_ABIG_HI 69632
#define OFF_ABIG_LO 103424
#define ABIG_P      528
#define OFF_AM1_HI  137216
#define OFF_AM1_LO  154624
#define AM1_P       272
#define OFF_AX_HI   172032
#define OFF_AX_LO   181248
#define AX_P        144
#define OFF_F       190464
// float indices inside F region
#define F_B1A   0
#define F_B1B   256
#define F_B2A   384
#define F_B2B   640
#define F_BA2   768
#define F_WA3   832
#define F_VIS   896
#define F_GS    960
#define F_GSB   1088
#define F_JOINT 1216
#define F_SPART 1360
#define F_COEF  1488
#define F_RED   1552
#define F_H3    1568
#define F_COUNT 1824
#define SMEM_BYTES (OFF_F + F_COUNT*4)   // 197760

// ===================== warp MMA GEMM =====================
// C(64 x NH) += A(64 x KD) @ B ; warps: 4 in M (16 rows), 2 in N (NH/2 cols).
template<int KD, int NH>
__device__ __forceinline__ void gemm_mma(uint32_t ahi, uint32_t alo, int apitch,
                                         uint32_t bhi, uint32_t blo, int bpitch,
                                         float (*acc)[4])
{
    const int lane = threadIdx.x & 31;
    const int wid  = threadIdx.x >> 5;
    const int mw   = wid & 3, nw = wid >> 2;
    constexpr int NT = NH / 16;
    uint32_t aoff = (uint32_t)((mw*16 + (lane & 15)) * apitch + ((lane >> 4) << 4));
    uint32_t boff = (uint32_t)((nw*(NH/2) + (lane & 7)) * bpitch + (((lane >> 3) & 1) << 4));
    uint32_t a_hi = ahi + aoff, a_lo = alo + aoff;
    uint32_t b_hi = bhi + boff, b_lo = blo + boff;
    #pragma unroll
    for (int k = 0; k < KD/16; k++){
        uint32_t ah[4], al[4];
        LDSM4(ah, a_hi + k*32);
        LDSM4(al, a_lo + k*32);
        #pragma unroll
        for (int t = 0; t < NT; t++){
            uint32_t bhf[2], blf[2];
            LDSM2(bhf, b_hi + t*8*bpitch + k*32);
            LDSM2(blf, b_lo + t*8*bpitch + k*32);
            MMA_BF16(acc[t], ah, bhf);
            MMA_BF16(acc[t], al, bhf);
            MMA_BF16(acc[t], ah, blf);
        }
    }
}

__device__ __forceinline__ void cp16(uint8_t* dst, const uint8_t* src, int bytes){
    for (int i = threadIdx.x*16; i < bytes; i += TPB*16)
        *(int4*)(dst + i) = *(const int4*)(src + i);
}

__global__ void __launch_bounds__(TPB, 1)
value_net_mma(const float* __restrict__ state,
              const float* __restrict__ b1a, const float* __restrict__ b1b,
              const float* __restrict__ b2a, const float* __restrict__ b2b,
              const float* __restrict__ wa1, const float* __restrict__ ba1,
              const float* __restrict__ ba2,
              const float* __restrict__ wa3, const float* __restrict__ ba3,
              const float* __restrict__ w3a, const float* __restrict__ b3a,
              const float* __restrict__ w3b, const float* __restrict__ b3b,
              const float* __restrict__ w3c, const float* __restrict__ b3c,
              float* __restrict__ out)
{
    extern __shared__ __align__(128) uint8_t sm[];
    float* F = (float*)(sm + OFF_F);
    const int tid  = threadIdx.x;
    const int lane = tid & 31;
    const int wid  = tid >> 5;
    const int mw   = wid & 3, nw = wid >> 2;
    const int r0   = mw*16 + (lane >> 2);

    const uint32_t sb  = smem_u32(sm);
    const uint32_t WB  = sb + OFF_WBUF;
    const uint32_t ABH = sb + OFF_ABIG_HI, ABL = sb + OFF_ABIG_LO;
    const uint32_t AMH = sb + OFF_AM1_HI,  AML = sb + OFF_AM1_LO;
    const uint32_t AXH = sb + OFF_AX_HI,   AXL = sb + OFF_AX_LO;

    // ---- load x (64x64), split to bf16 planes; vis; self_state; bias staging ----
    const float* gx = state + (size_t)blockIdx.x * 4096;
    {
        int row = tid >> 2, cs = (tid & 3) * 16;
        float4 v[4];
        #pragma unroll
        for (int j = 0; j < 4; j++) v[j] = *(const float4*)(gx + row*64 + cs + 4*j);
        const float* vf = (const float*)v;
        uint32_t hi[8], lo[8];
        #pragma unroll
        for (int j = 0; j < 8; j++) split2(vf[2*j], vf[2*j+1], hi[j], lo[j]);
        uint8_t* ph = sm + OFF_AX_HI + row*AX_P + cs*2;
        uint8_t* pl = sm + OFF_AX_LO + row*AX_P + cs*2;
        *(int4*)ph = *(int4*)hi; *(int4*)(ph+16) = *(int4*)(hi+4);
        *(int4*)pl = *(int4*)lo; *(int4*)(pl+16) = *(int4*)(lo+4);
        if ((tid & 3) == 3) F[F_VIS + row] = (v[3].y > 0.f) ? 1.f : 0.f;
        if (tid < 9) F[F_JOINT + tid] = gx[tid];
        F[F_B1A + tid] = b1a[tid];
        if (tid < 128) F[F_B1B + tid] = b1b[tid];
        F[F_B2A + tid] = b2a[tid];
        if (tid < 128) F[F_B2B + tid] = b2b[tid];
        if (tid < 64)  F[F_BA2 + tid] = ba2[tid];
        if (tid < 64)  F[F_WA3 + tid] = wa3[tid];
        if (tid < 128) F[F_GS + tid] = 0.f;
    }

    // ================= L0: h1 = relu(x @ w1a + b1a)  K=64 N=256 =================
    {
        const int PB = 144, HB = 128*144;        // half: 128 rows, pitch 72 el
        #pragma unroll
        for (int half = 0; half < 2; half++){
            cp16(sm + OFF_WBUF, g_wb + 0      + half*HB, HB);
            cp16(sm + OFF_WBUF + HB, g_wb + 73728/2*0 + 36864 + half*HB, HB);
            __syncthreads();
            float acc[8][4] = {};
            gemm_mma<64,128>(AXH, AXL, AX_P, WB, WB + HB, PB, acc);
            int hoff = half*128;
            #pragma unroll
            for (int t = 0; t < 8; t++){
                int c = hoff + nw*64 + t*8 + (lane & 3)*2;
                float v0 = fmaxf(acc[t][0] + F[F_B1A+c],   0.f);
                float v1 = fmaxf(acc[t][1] + F[F_B1A+c+1], 0.f);
                float v2 = fmaxf(acc[t][2] + F[F_B1A+c],   0.f);
                float v3 = fmaxf(acc[t][3] + F[F_B1A+c+1], 0.f);
                uint32_t h, l;
                split2(v0, v1, h, l);
                *(uint32_t*)(sm + OFF_ABIG_HI + r0*ABIG_P + c*2) = h;
                *(uint32_t*)(sm + OFF_ABIG_LO + r0*ABIG_P + c*2) = l;
                split2(v2, v3, h, l);
                *(uint32_t*)(sm + OFF_ABIG_HI + (r0+8)*ABIG_P + c*2) = h;
                *(uint32_t*)(sm + OFF_ABIG_LO + (r0+8)*ABIG_P + c*2) = l;
            }
            __syncthreads();
        }
    }

    // ================= L1: m1 = relu(h1 @ w1b + b1b)  K=256 N=128 ===============
    {
        const int PB = 528, HB = 64*528;         // half: 64 rows, pitch 264 el
        #pragma unroll
        for (int half = 0; half < 2; half++){
            cp16(sm + OFF_WBUF, g_wb + 73728 + half*HB, HB);
            cp16(sm + OFF_WBUF + HB, g_wb + 73728 + 67584 + half*HB, HB);
            __syncthreads();
            float acc[4][4] = {};
            gemm_mma<256,64>(ABH, ABL, ABIG_P, WB, WB + HB, PB, acc);
            int hoff = half*64;
            float visA = F[F_VIS + r0], visB = F[F_VIS + r0 + 8];
            #pragma unroll
            for (int t = 0; t < 4; t++){
                int c = hoff + nw*32 + t*8 + (lane & 3)*2;
                float v0 = fmaxf(acc[t][0] + F[F_B1B+c],   0.f);
                float v1 = fmaxf(acc[t][1] + F[F_B1B+c+1], 0.f);
                float v2 = fmaxf(acc[t][2] + F[F_B1B+c],   0.f);
                float v3 = fmaxf(acc[t][3] + F[F_B1B+c+1], 0.f);
                uint32_t h, l;
                split2(v0, v1, h, l);   // store UNMASKED m1
                *(uint32_t*)(sm + OFF_AM1_HI + r0*AM1_P + c*2) = h;
                *(uint32_t*)(sm + OFF_AM1_LO + r0*AM1_P + c*2) = l;
                split2(v2, v3, h, l);
                *(uint32_t*)(sm + OFF_AM1_HI + (r0+8)*AM1_P + c*2) = h;
                *(uint32_t*)(sm + OFF_AM1_LO + (r0+8)*AM1_P + c*2) = l;
                // gs accumulation (masked)
                float p0 = v0*visA + v2*visB;
                float p1 = v1*visA + v3*visB;
                #pragma unroll
                for (int o = 4; o <= 16; o <<= 1){
                    p0 += __shfl_xor_sync(0xffffffffu, p0, o);
                    p1 += __shfl_xor_sync(0xffffffffu, p1, o);
                }
                if (lane < 4){
                    atomicAdd(&F[F_GS + c],     p0);
                    atomicAdd(&F[F_GS + c + 1], p1);
                }
            }
            __syncthreads();
        }
    }
    // gs mean + gs-folded bias for L4
    if (tid < 128) F[F_GS + tid] *= (1.f/64.f);
    __syncthreads();
    if (tid < 128){
        float a = ba1[tid];
        #pragma unroll 8
        for (int j = 0; j < 128; j++) a += F[F_GS + j] * wa1[(128 + j)*128 + tid];
        F[F_GSB + tid] = a;
    }
    __syncthreads();

    // ================= L4: att1 = relu(vis*(m1 @ wa1[:128]) + gsbias) K=128 N=128
    {
        const int PB = 272, HB = 64*272;
        #pragma unroll
        for (int half = 0; half < 2; half++){
            cp16(sm + OFF_WBUF, g_wb + 483328 + half*HB, HB);
            cp16(sm + OFF_WBUF + HB, g_wb + 483328 + 34816 + half*HB, HB);
            __syncthreads();
            float acc[4][4] = {};
            gemm_mma<128,64>(AMH, AML, AM1_P, WB, WB + HB, PB, acc);
            int hoff = half*64;
            float visA = F[F_VIS + r0], visB = F[F_VIS + r0 + 8];
            #pragma unroll
            for (int t = 0; t < 4; t++){
                int c = hoff + nw*32 + t*8 + (lane & 3)*2;
                float g0 = F[F_GSB+c], g1 = F[F_GSB+c+1];
                float v0 = fmaxf(acc[t][0]*visA + g0, 0.f);
                float v1 = fmaxf(acc[t][1]*visA + g1, 0.f);
                float v2 = fmaxf(acc[t][2]*visB + g0, 0.f);
                float v3 = fmaxf(acc[t][3]*visB + g1, 0.f);
                uint32_t h, l;
                split2(v0, v1, h, l);
                *(uint32_t*)(sm + OFF_ABIG_HI + r0*ABIG_P + c*2) = h;
                *(uint32_t*)(sm + OFF_ABIG_LO + r0*ABIG_P + c*2) = l;
                split2(v2, v3, h, l);
                *(uint32_t*)(sm + OFF_ABIG_HI + (r0+8)*ABIG_P + c*2) = h;
                *(uint32_t*)(sm + OFF_ABIG_LO + (r0+8)*ABIG_P + c*2) = l;
            }
            __syncthreads();
        }
    }

    // ================= L5: scores partials  K=128 N=64 ==========================
    {
        const int PB = 272, HB = 64*272;
        cp16(sm + OFF_WBUF, g_wb + 552960, HB);
        cp16(sm + OFF_WBUF + HB, g_wb + 552960 + 17408, HB);
        __syncthreads();
        float acc[4][4] = {};
        gemm_mma<128,64>(ABH, ABL, ABIG_P, WB, WB + HB, PB, acc);
        float s0 = 0.f, s1 = 0.f;
        #pragma unroll
        for (int t = 0; t < 4; t++){
            int c = nw*32 + t*8 + (lane & 3)*2;
            float w0 = F[F_WA3+c], w1 = F[F_WA3+c+1];
            s0 += fmaxf(acc[t][0] + F[F_BA2+c],   0.f)*w0
                + fmaxf(acc[t][1] + F[F_BA2+c+1], 0.f)*w1;
            s1 += fmaxf(acc[t][2] + F[F_BA2+c],   0.f)*w0
                + fmaxf(acc[t][3] + F[F_BA2+c+1], 0.f)*w1;
        }
        s0 += __shfl_xor_sync(0xffffffffu, s0, 1);
        s0 += __shfl_xor_sync(0xffffffffu, s0, 2);
        s1 += __shfl_xor_sync(0xffffffffu, s1, 1);
        s1 += __shfl_xor_sync(0xffffffffu, s1, 2);
        if ((lane & 3) == 0){
            F[F_SPART + nw*64 + r0]     = s0;
            F[F_SPART + nw*64 + r0 + 8] = s1;
        }
        __syncthreads();
    }
    // ---- softmax + coefficients ----
    float e_reg = 0.f;
    if (tid < 64){
        float s = F[F_SPART + tid] + F[F_SPART + 64 + tid] + ba3[0];
        e_reg = (s != 0.f) ? expf(s) : 0.f;
        float t1 = e_reg;
        #pragma unroll
        for (int o = 16; o > 0; o >>= 1) t1 += __shfl_xor_sync(0xffffffffu, t1, o);
        if (lane == 0) F[F_RED + (tid >> 5)] = t1;
    }
    __syncthreads();
    if (tid < 64){
        float ssum = F[F_RED] + F[F_RED+1];
        float coef = (e_reg / ssum) * F[F_VIS + tid];
        F[F_COEF + tid] = coef;
        float t2 = coef;
        #pragma unroll
        for (int o = 16; o > 0; o >>= 1) t2 += __shfl_xor_sync(0xffffffffu, t2, o);
        if (lane == 0) F[F_RED + 4 + (tid >> 5)] = t2;
    }
    __syncthreads();
    if (tid < 128){
        float csum = F[F_RED+4] + F[F_RED+5];
        F[F_JOINT + 9 + tid] = F[F_B2B + tid] * csum;
    }
    __syncthreads();

    // ================= L2: h2 = relu(m1 @ w2a + b2a)  K=128 N=256 ===============
    {
        const int PB = 272, HB = 128*272;
        #pragma unroll
        for (int half = 0; half < 2; half++){
            cp16(sm + OFF_WBUF, g_wb + 208896 + half*HB, HB);
            cp16(sm + OFF_WBUF + HB, g_wb + 208896 + 69632 + half*HB, HB);
            __syncthreads();
            float acc[8][4] = {};
            gemm_mma<128,128>(AMH, AML, AM1_P, WB, WB + HB, PB, acc);
            int hoff = half*128;
            #pragma unroll
            for (int t = 0; t < 8; t++){
                int c = hoff + nw*64 + t*8 + (lane & 3)*2;
                float v0 = fmaxf(acc[t][0] + F[F_B2A+c],   0.f);
                float v1 = fmaxf(acc[t][1] + F[F_B2A+c+1], 0.f);
                float v2 = fmaxf(acc[t][2] + F[F_B2A+c],   0.f);
                float v3 = fmaxf(acc[t][3] + F[F_B2A+c+1], 0.f);
                uint32_t h, l;
                split2(v0, v1, h, l);
                *(uint32_t*)(sm + OFF_ABIG_HI + r0*ABIG_P + c*2) = h;
                *(uint32_t*)(sm + OFF_ABIG_LO + r0*ABIG_P + c*2) = l;
                split2(v2, v3, h, l);
                *(uint32_t*)(sm + OFF_ABIG_HI + (r0+8)*ABIG_P + c*2) = h;
                *(uint32_t*)(sm + OFF_ABIG_LO + (r0+8)*ABIG_P + c*2) = l;
            }
            __syncthreads();
        }
    }

    // ========= L3: weighted += coef . (h2 @ w2b)  K=256 N=128 (regs only) =======
    {
        const int PB = 528, HB = 64*528;
        float cA = F[F_COEF + r0], cB = F[F_COEF + r0 + 8];
        #pragma unroll
        for (int half = 0; half < 2; half++){
            cp16(sm + OFF_WBUF, g_wb + 348160 + half*HB, HB);
            cp16(sm + OFF_WBUF + HB, g_wb + 348160 + 67584 + half*HB, HB);
            __syncthreads();
            float acc[4][4] = {};
            gemm_mma<256,64>(ABH, ABL, ABIG_P, WB, WB + HB, PB, acc);
            int hoff = half*64;
            #pragma unroll
            for (int t = 0; t < 4; t++){
                int c = hoff + nw*32 + t*8 + (lane & 3)*2;
                float p0 = cA*acc[t][0] + cB*acc[t][2];
                float p1 = cA*acc[t][1] + cB*acc[t][3];
                #pragma unroll
                for (int o = 4; o <= 16; o <<= 1){
                    p0 += __shfl_xor_sync(0xffffffffu, p0, o);
                    p1 += __shfl_xor_sync(0xffffffffu, p1, o);
                }
                if (lane < 4){
                    atomicAdd(&F[F_JOINT + 9 + c],     p0);
                    atomicAdd(&F[F_JOINT + 9 + c + 1], p1);
                }
            }
            __syncthreads();
        }
    }

    // ================= final MLP: 137 -> 256 -> 128 -> 1 (fp32) ================
    {
        float a = b3a[tid];
        #pragma unroll 8
        for (int i = 0; i < 137; i++) a += F[F_JOINT + i] * w3a[i*256 + tid];
        F[F_H3 + tid] = fmaxf(a, 0.f);
    }
    __syncthreads();
    if (tid < 128){
        float a = b3b[tid];
        #pragma unroll 8
        for (int i = 0; i < 256; i++) a += F[F_H3 + i] * w3b[i*128 + tid];
        float p = fmaxf(a, 0.f) * w3c[tid];
        #pragma unroll
        for (int o = 16; o > 0; o >>= 1) p += __shfl_xor_sync(0xffffffffu, p, o);
        if (lane == 0) F[F_RED + wid] = p;
    }
    __syncthreads();
    if (tid == 0)
        out[blockIdx.x] = F[F_RED] + F[F_RED+1] + F[F_RED+2] + F[F_RED+3] + b3c[0];
}

extern "C" void kernel_launch(void* const* d_in, const int* in_sizes, int n_in,
                              void* d_out, int out_size)
{
    (void)in_sizes; (void)n_in; (void)out_size;
    const float* state = (const float*)d_in[0];
    const float* w1a = (const float*)d_in[1];  const float* b1a = (const float*)d_in[2];
    const float* w1b = (const float*)d_in[3];  const float* b1b = (const float*)d_in[4];
    const float* w2a = (const float*)d_in[5];  const float* b2a = (const float*)d_in[6];
    const float* w2b = (const float*)d_in[7];  const float* b2b = (const float*)d_in[8];
    const float* wa1 = (const float*)d_in[9];  const float* ba1 = (const float*)d_in[10];
    const float* wa2 = (const float*)d_in[11]; const float* ba2 = (const float*)d_in[12];
    const float* wa3 = (const float*)d_in[13]; const float* ba3 = (const float*)d_in[14];
    const float* w3a = (const float*)d_in[15]; const float* b3a = (const float*)d_in[16];
    const float* w3b = (const float*)d_in[17]; const float* b3b = (const float*)d_in[18];
    const float* w3c = (const float*)d_in[19]; const float* b3c = (const float*)d_in[20];
    float* out = (float*)d_out;

    prep_kernel<<<128, 256>>>(w1a, w1b, w2a, w2b, wa1, wa2);

    cudaFuncSetAttribute(value_net_mma,
                         cudaFuncAttributeMaxDynamicSharedMemorySize, SMEM_BYTES);
    value_net_mma<<<4096, TPB, SMEM_BYTES>>>(
        state, b1a, b1b, b2a, b2b, wa1, ba1, ba2, wa3, ba3,
        w3a, b3a, w3b, b3b, w3c, b3c, out);
}

// round 5
// speedup vs baseline: 3.1055x; 1.8669x over previous
#include <cuda_runtime.h>
#include <cuda_bf16.h>
#include <cstdint>

#define TPB 256

// ===================== PTX wrappers =====================
__device__ __forceinline__ uint32_t smem_u32(const void* p){
    uint32_t a;
    asm("{ .reg .u64 t; cvta.to.shared.u64 t, %1; cvt.u32.u64 %0, t; }":"=r"(a):"l"(p));
    return a;
}
#define LDSM4(r, a) \
    asm volatile("ldmatrix.sync.aligned.m8n8.x4.shared.b16 {%0,%1,%2,%3}, [%4];" \
        :"=r"((r)[0]),"=r"((r)[1]),"=r"((r)[2]),"=r"((r)[3]):"r"(a))
#define MMA_BF16(c, a, b) \
    asm volatile("mma.sync.aligned.m16n8k16.row.col.f32.bf16.bf16.f32 " \
        "{%0,%1,%2,%3},{%4,%5,%6,%7},{%8,%9},{%0,%1,%2,%3};" \
        :"+f"((c)[0]),"+f"((c)[1]),"+f"((c)[2]),"+f"((c)[3]) \
        :"r"((a)[0]),"r"((a)[1]),"r"((a)[2]),"r"((a)[3]),"r"((b)[0]),"r"((b)[1]))

__device__ __forceinline__ uint32_t pack_hi(float v0, float v1){
    return __byte_perm(__float_as_uint(v0), __float_as_uint(v1), 0x7632);
}
__device__ __forceinline__ uint32_t pack_lo(float v0, float v1){
    float l0 = v0 - __uint_as_float(__float_as_uint(v0) & 0xFFFF0000u);
    float l1 = v1 - __uint_as_float(__float_as_uint(v1) & 0xFFFF0000u);
    __nv_bfloat162 L = __floats2bfloat162_rn(l0, l1);
    return *(uint32_t*)&L;
}
// swizzled activation store: plane pitch P bytes, row r, column pair at nc (even)
__device__ __forceinline__ void swst(uint8_t* plane, int P, int r, int nc, uint32_t v){
    *(uint32_t*)(plane + r*P + ((((nc>>3) ^ (r&7)) << 4) | ((nc<<1) & 15))) = v;
}

// ===================== fragment-packed weights =====================
// Per layer: blocks of 512B = one (n8-tile T, k16-step s) warp fragment:
//   lane*16B = {bh0, bh1, bl0, bl1} (hi/lo planes, k-halves)
__device__ __align__(128) uint8_t g_wb[557056];

__constant__ const int c_dummy = 0;

__global__ void prep_kernel(const float* __restrict__ w1a, const float* __restrict__ w1b,
                            const float* __restrict__ w2a, const float* __restrict__ w2b,
                            const float* __restrict__ wa1, const float* __restrict__ wa2)
{
    const float* W[6] = {w1a, w1b, w2a, w2b, wa1, wa2};
    const int   NN[6] = {256, 128, 256, 128, 128, 64};
    const int   KS[6] = {4, 16, 8, 16, 8, 8};          // K/16
    const int   EO[7] = {0, 4096, 12288, 20480, 28672, 32768, 34816}; // blocks
    const int   BO[6] = {0, 65536, 196608, 327680, 458752, 524288};   // bytes
    int idx = blockIdx.x * blockDim.x + threadIdx.x;
    if (idx >= 34816) return;
    int l = 0;
    while (idx >= EO[l+1]) l++;
    int e = idx - EO[l];
    int lane = e & 31, qq = e >> 5;
    int s = qq % KS[l], T = qq / KS[l];
    int tg = lane & 3, g = lane >> 2;
    int n = T*8 + g;
    int k0 = s*16 + 2*tg;
    int N = NN[l];
    const float* Wl = W[l];
    float w0 = Wl[(k0  )*N + n], w1 = Wl[(k0+1)*N + n];
    float w2 = Wl[(k0+8)*N + n], w3 = Wl[(k0+9)*N + n];
    __nv_bfloat16 h0 = __float2bfloat16(w0), h1 = __float2bfloat16(w1);
    __nv_bfloat16 h2 = __float2bfloat16(w2), h3 = __float2bfloat16(w3);
    __nv_bfloat162 H0; H0.x = h0; H0.y = h1;
    __nv_bfloat162 H1; H1.x = h2; H1.y = h3;
    __nv_bfloat162 L0; L0.x = __float2bfloat16(w0 - __bfloat162float(h0));
                       L0.y = __float2bfloat16(w1 - __bfloat162float(h1));
    __nv_bfloat162 L1; L1.x = __float2bfloat16(w2 - __bfloat162float(h2));
                       L1.y = __float2bfloat16(w3 - __bfloat162float(h3));
    uint4 o;
    o.x = *(uint32_t*)&H0; o.y = *(uint32_t*)&H1;
    o.z = *(uint32_t*)&L0; o.w = *(uint32_t*)&L1;
    *(uint4*)(g_wb + BO[l] + (size_t)e*16) = o;
}

// ===================== smem layout =====================
#define OFF_BH   0          // big act hi: 128 x 512B
#define OFF_BL   65536
#define OFF_MH   131072     // m1/x hi: 128 x 256B
#define OFF_ML   163840
#define OFF_F    196608
// float indices in F
#define F_B1A   0
#define F_B1B   256
#define F_B2A   384
#define F_B2B   640
#define F_BA2   768
#define F_WA3   832
#define F_VIS   896
#define F_GS    1024
#define F_SPART 1280
#define F_COEF  1792
#define F_GSB   1920
#define F_JOINT 2176      // [2][160]
#define F_RED   2496
#define F_H3    2528      // [2][256]
#define F_TOT   3040
#define SMEM_BYTES (OFF_F + F_TOT*4)   // 208768

// ===================== GEMM: M=128, warp tile 64(M) x NT*8(N) =====================
template<int KSTEPS, int NT>
__device__ __forceinline__ void gemm(uint32_t aH, uint32_t aL, int P,
                                     const uint4* __restrict__ Bf,
                                     int mw, int nw, int lane,
                                     float (&acc)[4][NT][4])
{
    #pragma unroll
    for (int m = 0; m < 4; m++)
        #pragma unroll
        for (int t = 0; t < NT; t++)
            #pragma unroll
            for (int j = 0; j < 4; j++) acc[m][t][j] = 0.f;

    const uint32_t rowoff = (uint32_t)((mw*64 + (lane & 15)) * P);
    const uint32_t chi = (uint32_t)(lane >> 4);
    const uint32_t swr = (uint32_t)(lane & 7);
    const uint4* bp = Bf + (size_t)(nw*NT)*KSTEPS*32 + lane;

    #pragma unroll 2
    for (int s = 0; s < KSTEPS; s++){
        uint32_t co = (((2u*s + chi) ^ swr) << 4);
        uint32_t AH[4][4], AL[4][4];
        #pragma unroll
        for (int m = 0; m < 4; m++){
            LDSM4(AH[m], aH + rowoff + (uint32_t)(m*16*P) + co);
            LDSM4(AL[m], aL + rowoff + (uint32_t)(m*16*P) + co);
        }
        const uint4* bps = bp + (size_t)s*32;
        #pragma unroll
        for (int t = 0; t < NT; t++){
            uint4 bb = __ldg(bps + (size_t)t*KSTEPS*32);
            uint32_t BH[2] = {bb.x, bb.y};
            uint32_t BL[2] = {bb.z, bb.w};
            #pragma unroll
            for (int m = 0; m < 4; m++){
                MMA_BF16(acc[m][t], AH[m], BH);
                MMA_BF16(acc[m][t], AL[m], BH);
                MMA_BF16(acc[m][t], AH[m], BL);
            }
        }
    }
}

__global__ void __launch_bounds__(TPB, 1)
value_net_mma(const float* __restrict__ state,
              const float* __restrict__ b1a, const float* __restrict__ b1b,
              const float* __restrict__ b2a, const float* __restrict__ b2b,
              const float* __restrict__ wa1, const float* __restrict__ ba1,
              const float* __restrict__ ba2,
              const float* __restrict__ wa3, const float* __restrict__ ba3,
              const float* __restrict__ w3a, const float* __restrict__ b3a,
              const float* __restrict__ w3b, const float* __restrict__ b3b,
              const float* __restrict__ w3c, const float* __restrict__ b3c,
              float* __restrict__ out)
{
    extern __shared__ __align__(128) uint8_t sm[];
    float* F = (float*)(sm + OFF_F);
    const int tid  = threadIdx.x;
    const int lane = tid & 31;
    const int wid  = tid >> 5;
    const int mw   = wid & 1;          // batch / M-half
    const int nw   = wid >> 1;         // N quarter
    const int g    = lane >> 2;
    const int tg   = lane & 3;
    const int R0   = mw * 64;

    const uint32_t sb = smem_u32(sm);
    const uint32_t BH_ = sb + OFF_BH, BL_ = sb + OFF_BL;
    const uint32_t MH_ = sb + OFF_MH, ML_ = sb + OFF_ML;
    uint8_t* pBH = sm + OFF_BH; uint8_t* pBL = sm + OFF_BL;
    uint8_t* pMH = sm + OFF_MH; uint8_t* pML = sm + OFF_ML;

    const uint4* B0 = (const uint4*)(g_wb + 0);
    const uint4* B1 = (const uint4*)(g_wb + 65536);
    const uint4* B2 = (const uint4*)(g_wb + 196608);
    const uint4* B3 = (const uint4*)(g_wb + 327680);
    const uint4* B4 = (const uint4*)(g_wb + 458752);
    const uint4* B5 = (const uint4*)(g_wb + 524288);

    // ---- stage x (2 batches = 128 rows x 64) into M planes + scalars ----
    {
        int row = tid >> 1, half = tid & 1;
        const float* xr = state + (size_t)blockIdx.x*8192 + row*64 + half*32;
        float xv[32];
        #pragma unroll
        for (int j = 0; j < 8; j++) ((float4*)xv)[j] = __ldg((const float4*)(xr + 4*j));
        #pragma unroll
        for (int j = 0; j < 16; j++){
            int nc = half*32 + 2*j;
            swst(pMH, 256, row, nc, pack_hi(xv[2*j], xv[2*j+1]));
            swst(pML, 256, row, nc, pack_lo(xv[2*j], xv[2*j+1]));
        }
        if (half) F[F_VIS + row] = (xv[29] > 0.f) ? 1.f : 0.f;
        if (tid == 0 || tid == 128){
            #pragma unroll
            for (int i = 0; i < 9; i++) F[F_JOINT + (row>>6)*160 + i] = xv[i];
        }
        F[F_B1A + tid] = __ldg(&b1a[tid]);
        F[F_B2A + tid] = __ldg(&b2a[tid]);
        if (tid < 128){ F[F_B1B + tid] = __ldg(&b1b[tid]); F[F_B2B + tid] = __ldg(&b2b[tid]); }
        if (tid < 64){ F[F_BA2 + tid] = __ldg(&ba2[tid]); F[F_WA3 + tid] = __ldg(&wa3[tid]); }
    }
    __syncthreads();

    // ============ L0: h1 = relu(x @ w1a + b1a)  K=64 N=256 ============
    {
        float acc[4][8][4];
        gemm<4,8>(MH_, ML_, 256, B0, mw, nw, lane, acc);
        #pragma unroll
        for (int t = 0; t < 8; t++){
            int c = nw*64 + t*8 + 2*tg;
            float bb0 = F[F_B1A + c], bb1 = F[F_B1A + c + 1];
            #pragma unroll
            for (int m = 0; m < 4; m++){
                int rA = R0 + m*16 + g, rB = rA + 8;
                float v0 = fmaxf(acc[m][t][0] + bb0, 0.f);
                float v1 = fmaxf(acc[m][t][1] + bb1, 0.f);
                float v2 = fmaxf(acc[m][t][2] + bb0, 0.f);
                float v3 = fmaxf(acc[m][t][3] + bb1, 0.f);
                swst(pBH, 512, rA, c, pack_hi(v0, v1));
                swst(pBL, 512, rA, c, pack_lo(v0, v1));
                swst(pBH, 512, rB, c, pack_hi(v2, v3));
                swst(pBL, 512, rB, c, pack_lo(v2, v3));
            }
        }
    }
    __syncthreads();

    // ============ L1: m1 = relu(h1 @ w1b + b1b)  K=256 N=128 ============
    {
        float acc[4][4][4];
        gemm<16,4>(BH_, BL_, 512, B1, mw, nw, lane, acc);
        float visA[4], visB[4];
        #pragma unroll
        for (int m = 0; m < 4; m++){
            visA[m] = F[F_VIS + R0 + m*16 + g];
            visB[m] = F[F_VIS + R0 + m*16 + g + 8];
        }
        #pragma unroll
        for (int t = 0; t < 4; t++){
            int c = nw*32 + t*8 + 2*tg;
            float bb0 = F[F_B1B + c], bb1 = F[F_B1B + c + 1];
            float g0 = 0.f, g1 = 0.f;
            #pragma unroll
            for (int m = 0; m < 4; m++){
                int rA = R0 + m*16 + g, rB = rA + 8;
                float v0 = fmaxf(acc[m][t][0] + bb0, 0.f);
                float v1 = fmaxf(acc[m][t][1] + bb1, 0.f);
                float v2 = fmaxf(acc[m][t][2] + bb0, 0.f);
                float v3 = fmaxf(acc[m][t][3] + bb1, 0.f);
                swst(pMH, 256, rA, c, pack_hi(v0, v1));   // UNMASKED m1
                swst(pML, 256, rA, c, pack_lo(v0, v1));
                swst(pMH, 256, rB, c, pack_hi(v2, v3));
                swst(pML, 256, rB, c, pack_lo(v2, v3));
                g0 += v0*visA[m] + v2*visB[m];
                g1 += v1*visA[m] + v3*visB[m];
            }
            #pragma unroll
            for (int o = 4; o <= 16; o <<= 1){
                g0 += __shfl_xor_sync(0xffffffffu, g0, o);
                g1 += __shfl_xor_sync(0xffffffffu, g1, o);
            }
            if (lane < 4){   // g==0, tg==lane
                F[F_GS + mw*128 + c]     = g0;
                F[F_GS + mw*128 + c + 1] = g1;
            }
        }
    }
    __syncthreads();
    // gsb[b][n] = ba1[n] + (1/64) * sum_j gs_raw[b][j] * wa1[128+j][n]
    {
        int b = tid >> 7, n = tid & 127;
        float a0 = 0.f, a1 = 0.f;
        const float* gsr = &F[F_GS + b*128];
        #pragma unroll 8
        for (int j = 0; j < 128; j += 2){
            a0 += gsr[j]   * __ldg(&wa1[(128 + j)*128 + n]);
            a1 += gsr[j+1] * __ldg(&wa1[(129 + j)*128 + n]);
        }
        F[F_GSB + tid] = (a0 + a1) * (1.f/64.f) + __ldg(&ba1[n]);
    }
    __syncthreads();

    // ============ L4: att1 = relu(vis*(m1 @ wa1a) + gsb)  K=128 N=128 ============
    {
        float acc[4][4][4];
        gemm<8,4>(MH_, ML_, 256, B4, mw, nw, lane, acc);
        float visA[4], visB[4];
        #pragma unroll
        for (int m = 0; m < 4; m++){
            visA[m] = F[F_VIS + R0 + m*16 + g];
            visB[m] = F[F_VIS + R0 + m*16 + g + 8];
        }
        #pragma unroll
        for (int t = 0; t < 4; t++){
            int c = nw*32 + t*8 + 2*tg;
            float g0 = F[F_GSB + mw*128 + c], g1 = F[F_GSB + mw*128 + c + 1];
            #pragma unroll
            for (int m = 0; m < 4; m++){
                int rA = R0 + m*16 + g, rB = rA + 8;
                float v0 = fmaxf(acc[m][t][0]*visA[m] + g0, 0.f);
                float v1 = fmaxf(acc[m][t][1]*visA[m] + g1, 0.f);
                float v2 = fmaxf(acc[m][t][2]*visB[m] + g0, 0.f);
                float v3 = fmaxf(acc[m][t][3]*visB[m] + g1, 0.f);
                swst(pBH, 512, rA, c, pack_hi(v0, v1));
                swst(pBL, 512, rA, c, pack_lo(v0, v1));
                swst(pBH, 512, rB, c, pack_hi(v2, v3));
                swst(pBL, 512, rB, c, pack_lo(v2, v3));
            }
        }
    }
    __syncthreads();

    // ============ L5: score partials  K=128 N=64 ============
    {
        float acc[4][2][4];
        gemm<8,2>(BH_, BL_, 512, B5, mw, nw, lane, acc);
        float pA[4] = {0,0,0,0}, pB[4] = {0,0,0,0};
        #pragma unroll
        for (int t = 0; t < 2; t++){
            int c = nw*16 + t*8 + 2*tg;
            float a2 = F[F_BA2 + c], a3 = F[F_BA2 + c + 1];
            float w0 = F[F_WA3 + c], w1 = F[F_WA3 + c + 1];
            #pragma unroll
            for (int m = 0; m < 4; m++){
                pA[m] += fmaxf(acc[m][t][0] + a2, 0.f)*w0 + fmaxf(acc[m][t][1] + a3, 0.f)*w1;
                pB[m] += fmaxf(acc[m][t][2] + a2, 0.f)*w0 + fmaxf(acc[m][t][3] + a3, 0.f)*w1;
            }
        }
        #pragma unroll
        for (int m = 0; m < 4; m++){
            #pragma unroll
            for (int o = 1; o <= 2; o <<= 1){
                pA[m] += __shfl_xor_sync(0xffffffffu, pA[m], o);
                pB[m] += __shfl_xor_sync(0xffffffffu, pB[m], o);
            }
        }
        if (tg == 0){
            #pragma unroll
            for (int m = 0; m < 4; m++){
                F[F_SPART + nw*128 + R0 + m*16 + g]     = pA[m];
                F[F_SPART + nw*128 + R0 + m*16 + g + 8] = pB[m];
            }
        }
    }
    __syncthreads();

    // ---- softmax + coefficients + joint init ----
    {
        float e = 0.f;
        if (tid < 128){
            float s = F[F_SPART + tid] + F[F_SPART + 128 + tid]
                    + F[F_SPART + 256 + tid] + F[F_SPART + 384 + tid] + __ldg(&ba3[0]);
            e = (s != 0.f) ? expf(s) : 0.f;
            float t1 = e;
            #pragma unroll
            for (int o = 16; o > 0; o >>= 1) t1 += __shfl_xor_sync(0xffffffffu, t1, o);
            if (lane == 0) F[F_RED + wid] = t1;
        }
        __syncthreads();
        if (tid < 128){
            int b = tid >> 6;
            float ssum = F[F_RED + 2*b] + F[F_RED + 2*b + 1];
            float coef = (e / ssum) * F[F_VIS + tid];
            F[F_COEF + tid] = coef;
            float t2 = coef;
            #pragma unroll
            for (int o = 16; o > 0; o >>= 1) t2 += __shfl_xor_sync(0xffffffffu, t2, o);
            if (lane == 0) F[F_RED + 8 + wid] = t2;
        }
        __syncthreads();
        {
            int b = tid >> 7, c = tid & 127;
            float csum = F[F_RED + 8 + 2*b] + F[F_RED + 8 + 2*b + 1];
            F[F_JOINT + b*160 + 9 + c] = csum * F[F_B2B + c];
        }
    }
    __syncthreads();

    // ============ L2: h2 = relu(m1 @ w2a + b2a)  K=128 N=256 ============
    {
        float acc[4][8][4];
        gemm<8,8>(MH_, ML_, 256, B2, mw, nw, lane, acc);
        #pragma unroll
        for (int t = 0; t < 8; t++){
            int c = nw*64 + t*8 + 2*tg;
            float bb0 = F[F_B2A + c], bb1 = F[F_B2A + c + 1];
            #pragma unroll
            for (int m = 0; m < 4; m++){
                int rA = R0 + m*16 + g, rB = rA + 8;
                float v0 = fmaxf(acc[m][t][0] + bb0, 0.f);
                float v1 = fmaxf(acc[m][t][1] + bb1, 0.f);
                float v2 = fmaxf(acc[m][t][2] + bb0, 0.f);
                float v3 = fmaxf(acc[m][t][3] + bb1, 0.f);
                swst(pBH, 512, rA, c, pack_hi(v0, v1));
                swst(pBL, 512, rA, c, pack_lo(v0, v1));
                swst(pBH, 512, rB, c, pack_hi(v2, v3));
                swst(pBL, 512, rB, c, pack_lo(v2, v3));
            }
        }
    }
    __syncthreads();

    // ============ L3: joint += coef . (h2 @ w2b)  K=256 N=128 ============
    {
        float acc[4][4][4];
        gemm<16,4>(BH_, BL_, 512, B3, mw, nw, lane, acc);
        float cA[4], cB[4];
        #pragma unroll
        for (int m = 0; m < 4; m++){
            cA[m] = F[F_COEF + R0 + m*16 + g];
            cB[m] = F[F_COEF + R0 + m*16 + g + 8];
        }
        #pragma unroll
        for (int t = 0; t < 4; t++){
            int c = nw*32 + t*8 + 2*tg;
            float w0 = 0.f, w1 = 0.f;
            #pragma unroll
            for (int m = 0; m < 4; m++){
                w0 += cA[m]*acc[m][t][0] + cB[m]*acc[m][t][2];
                w1 += cA[m]*acc[m][t][1] + cB[m]*acc[m][t][3];
            }
            #pragma unroll
            for (int o = 4; o <= 16; o <<= 1){
                w0 += __shfl_xor_sync(0xffffffffu, w0, o);
                w1 += __shfl_xor_sync(0xffffffffu, w1, o);
            }
            if (lane < 4){
                F[F_JOINT + mw*160 + 9 + c]     += w0;
                F[F_JOINT + mw*160 + 9 + c + 1] += w1;
            }
        }
    }
    __syncthreads();

    // ============ final MLP: 137 -> 256 -> 128 -> 1 (fp32), 2 batches ============
    #pragma unroll
    for (int b = 0; b < 2; b++){
        float a0 = __ldg(&b3a[tid]), a1 = 0.f;
        const float* J = &F[F_JOINT + b*160];
        #pragma unroll 4
        for (int i = 0; i < 136; i += 2){
            a0 += J[i]   * __ldg(&w3a[i*256 + tid]);
            a1 += J[i+1] * __ldg(&w3a[(i+1)*256 + tid]);
        }
        a0 += J[136] * __ldg(&w3a[136*256 + tid]);
        F[F_H3 + b*256 + tid] = fmaxf(a0 + a1, 0.f);
    }
    __syncthreads();
    {
        int b = tid >> 7, n = tid & 127;
        float a0 = __ldg(&b3b[n]), a1 = 0.f;
        const float* H = &F[F_H3 + b*256];
        #pragma unroll 4
        for (int i = 0; i < 256; i += 2){
            a0 += H[i]   * __ldg(&w3b[i*128 + n]);
            a1 += H[i+1] * __ldg(&w3b[(i+1)*128 + n]);
        }
        float p = fmaxf(a0 + a1, 0.f) * __ldg(&w3c[n]);
        #pragma unroll
        for (int o = 16; o > 0; o >>= 1) p += __shfl_xor_sync(0xffffffffu, p, o);
        if (lane == 0) F[F_RED + wid] = p;
    }
    __syncthreads();
    if (tid < 2){
        out[blockIdx.x*2 + tid] = F[F_RED + tid*4] + F[F_RED + tid*4 + 1]
                                + F[F_RED + tid*4 + 2] + F[F_RED + tid*4 + 3]
                                + __ldg(&b3c[0]);
    }
}

extern "C" void kernel_launch(void* const* d_in, const int* in_sizes, int n_in,
                              void* d_out, int out_size)
{
    (void)in_sizes; (void)n_in; (void)out_size;
    const float* state = (const float*)d_in[0];
    const float* w1a = (const float*)d_in[1];  const float* b1a = (const float*)d_in[2];
    const float* w1b = (const float*)d_in[3];  const float* b1b = (const float*)d_in[4];
    const float* w2a = (const float*)d_in[5];  const float* b2a = (const float*)d_in[6];
    const float* w2b = (const float*)d_in[7];  const float* b2b = (const float*)d_in[8];
    const float* wa1 = (const float*)d_in[9];  const float* ba1 = (const float*)d_in[10];
    const float* wa2 = (const float*)d_in[11]; const float* ba2 = (const float*)d_in[12];
    const float* wa3 = (const float*)d_in[13]; const float* ba3 = (const float*)d_in[14];
    const float* w3a = (const float*)d_in[15]; const float* b3a = (const float*)d_in[16];
    const float* w3b = (const float*)d_in[17]; const float* b3b = (const float*)d_in[18];
    const float* w3c = (const float*)d_in[19]; const float* b3c = (const float*)d_in[20];
    float* out = (float*)d_out;

    prep_kernel<<<(34816 + 255)/256, 256>>>(w1a, w1b, w2a, w2b, wa1, wa2);

    cudaFuncSetAttribute(value_net_mma,
                         cudaFuncAttributeMaxDynamicSharedMemorySize, SMEM_BYTES);
    value_net_mma<<<2048, TPB, SMEM_BYTES>>>(
        state, b1a, b1b, b2a, b2b, wa1, ba1, ba2, wa3, ba3,
        w3a, b3a, w3b, b3b, w3c, b3c, out);
}

// round 7
// speedup vs baseline: 3.2779x; 1.0555x over previous
#include <cuda_runtime.h>
#include <cuda_bf16.h>
#include <cstdint>

#define TPB 512

// ===================== PTX wrappers =====================
__device__ __forceinline__ uint32_t smem_u32(const void* p){
    uint32_t a;
    asm("{ .reg .u64 t; cvta.to.shared.u64 t, %1; cvt.u32.u64 %0, t; }":"=r"(a):"l"(p));
    return a;
}
#define LDSM4(r, a) \
    asm volatile("ldmatrix.sync.aligned.m8n8.x4.shared.b16 {%0,%1,%2,%3}, [%4];" \
        :"=r"((r)[0]),"=r"((r)[1]),"=r"((r)[2]),"=r"((r)[3]):"r"(a))
#define MMA_BF16(c, a, b) \
    asm volatile("mma.sync.aligned.m16n8k16.row.col.f32.bf16.bf16.f32 " \
        "{%0,%1,%2,%3},{%4,%5,%6,%7},{%8,%9},{%0,%1,%2,%3};" \
        :"+f"((c)[0]),"+f"((c)[1]),"+f"((c)[2]),"+f"((c)[3]) \
        :"r"((a)[0]),"r"((a)[1]),"r"((a)[2]),"r"((a)[3]),"r"((b)[0]),"r"((b)[1]))

__device__ __forceinline__ uint32_t pack_hi(float v0, float v1){
    return __byte_perm(__float_as_uint(v0), __float_as_uint(v1), 0x7632);
}
__device__ __forceinline__ uint32_t pack_lo(float v0, float v1){
    float l0 = v0 - __uint_as_float(__float_as_uint(v0) & 0xFFFF0000u);
    float l1 = v1 - __uint_as_float(__float_as_uint(v1) & 0xFFFF0000u);
    __nv_bfloat162 L = __floats2bfloat162_rn(l0, l1);
    return *(uint32_t*)&L;
}
__device__ __forceinline__ void swst(uint8_t* plane, int P, int r, int nc, uint32_t v){
    *(uint32_t*)(plane + r*P + ((((nc>>3) ^ (r&7)) << 4) | ((nc<<1) & 15))) = v;
}

// ===================== fragment-packed weights =====================
__device__ __align__(128) uint8_t g_wb[557056];

__global__ void prep_kernel(const float* __restrict__ w1a, const float* __restrict__ w1b,
                            const float* __restrict__ w2a, const float* __restrict__ w2b,
                            const float* __restrict__ wa1, const float* __restrict__ wa2)
{
    const float* W[6] = {w1a, w1b, w2a, w2b, wa1, wa2};
    const int   NN[6] = {256, 128, 256, 128, 128, 64};
    const int   KS[6] = {4, 16, 8, 16, 8, 8};
    const int   EO[7] = {0, 4096, 12288, 20480, 28672, 32768, 34816};
    const int   BO[6] = {0, 65536, 196608, 327680, 458752, 524288};
    int idx = blockIdx.x * blockDim.x + threadIdx.x;
    if (idx >= 34816) return;
    int l = 0;
    while (idx >= EO[l+1]) l++;
    int e = idx - EO[l];
    int lane = e & 31, qq = e >> 5;
    int s = qq % KS[l], T = qq / KS[l];
    int tg = lane & 3, g = lane >> 2;
    int n = T*8 + g;
    int k0 = s*16 + 2*tg;
    int N = NN[l];
    const float* Wl = W[l];
    float w0 = Wl[(k0  )*N + n], w1 = Wl[(k0+1)*N + n];
    float w2 = Wl[(k0+8)*N + n], w3 = Wl[(k0+9)*N + n];
    __nv_bfloat16 h0 = __float2bfloat16(w0), h1 = __float2bfloat16(w1);
    __nv_bfloat16 h2 = __float2bfloat16(w2), h3 = __float2bfloat16(w3);
    __nv_bfloat162 H0; H0.x = h0; H0.y = h1;
    __nv_bfloat162 H1; H1.x = h2; H1.y = h3;
    __nv_bfloat162 L0; L0.x = __float2bfloat16(w0 - __bfloat162float(h0));
                       L0.y = __float2bfloat16(w1 - __bfloat162float(h1));
    __nv_bfloat162 L1; L1.x = __float2bfloat16(w2 - __bfloat162float(h2));
                       L1.y = __float2bfloat16(w3 - __bfloat162float(h3));
    uint4 o;
    o.x = *(uint32_t*)&H0; o.y = *(uint32_t*)&H1;
    o.z = *(uint32_t*)&L0; o.w = *(uint32_t*)&L1;
    *(uint4*)(g_wb + BO[l] + (size_t)e*16) = o;
}

// ===================== smem layout =====================
#define OFF_BH   0          // big act hi: 128 x 512B
#define OFF_BL   65536
#define OFF_MH   131072     // m1/x hi: 128 x 256B
#define OFF_ML   163840
#define OFF_F    196608
#define F_B1A   0
#define F_B1B   256
#define F_B2A   384
#define F_B2B   640
#define F_BA2   768
#define F_WA3   832
#define F_VIS   896
#define F_GSP   1024      // [4][128] per-mw gs partials
#define F_SPART 1536      // [4][128]
#define F_COEF  2048
#define F_GSB   2176      // [2][128]
#define F_JP    2432      // [4][128] per-mw joint partials
#define F_JOINT 2944      // [2][160]
#define F_RED   3264
#define F_H3    3296      // [2][256]
#define F_TOT   3808
#define SMEM_BYTES (OFF_F + F_TOT*4)   // 211840

// ===================== GEMM: M=128, 16 warps 4(M)x4(N), warp tile 32 x NT*8 ====
template<int KSTEPS, int NT>
__device__ __forceinline__ void gemm(uint32_t aH, uint32_t aL, int P,
                                     const uint4* __restrict__ Bf,
                                     int mw, int nw, int lane,
                                     float (&acc)[2][NT][4])
{
    #pragma unroll
    for (int m = 0; m < 2; m++)
        #pragma unroll
        for (int t = 0; t < NT; t++)
            #pragma unroll
            for (int j = 0; j < 4; j++) acc[m][t][j] = 0.f;

    const uint32_t rowoff = (uint32_t)((mw*32 + (lane & 15)) * P);
    const uint32_t chi = (uint32_t)(lane >> 4);
    const uint32_t swr = (uint32_t)(lane & 7);
    const uint4* bp = Bf + (size_t)(nw*NT)*KSTEPS*32 + lane;

    #pragma unroll 2
    for (int s = 0; s < KSTEPS; s++){
        uint32_t co = (((2u*s + chi) ^ swr) << 4);
        uint32_t AH[2][4], AL[2][4];
        #pragma unroll
        for (int m = 0; m < 2; m++){
            LDSM4(AH[m], aH + rowoff + (uint32_t)(m*16*P) + co);
            LDSM4(AL[m], aL + rowoff + (uint32_t)(m*16*P) + co);
        }
        const uint4* bps = bp + (size_t)s*32;
        #pragma unroll
        for (int t = 0; t < NT; t++){
            uint4 bb = __ldg(bps + (size_t)t*KSTEPS*32);
            uint32_t BH[2] = {bb.x, bb.y};
            uint32_t BL[2] = {bb.z, bb.w};
            #pragma unroll
            for (int m = 0; m < 2; m++){
                MMA_BF16(acc[m][t], AH[m], BH);
                MMA_BF16(acc[m][t], AL[m], BH);
                MMA_BF16(acc[m][t], AH[m], BL);
            }
        }
    }
}

__global__ void __launch_bounds__(TPB, 1)
value_net_mma(const float* __restrict__ state,
              const float* __restrict__ b1a, const float* __restrict__ b1b,
              const float* __restrict__ b2a, const float* __restrict__ b2b,
              const float* __restrict__ wa1, const float* __restrict__ ba1,
              const float* __restrict__ ba2,
              const float* __restrict__ wa3, const float* __restrict__ ba3,
              const float* __restrict__ w3a, const float* __restrict__ b3a,
              const float* __restrict__ w3b, const float* __restrict__ b3b,
              const float* __restrict__ w3c, const float* __restrict__ b3c,
              float* __restrict__ out)
{
    extern __shared__ __align__(128) uint8_t sm[];
    float* F = (float*)(sm + OFF_F);
    const int tid  = threadIdx.x;
    const int lane = tid & 31;
    const int wid  = tid >> 5;
    const int mw   = wid & 3;          // M group (32 rows)
    const int nw   = wid >> 2;         // N group
    const int g    = lane >> 2;
    const int tg   = lane & 3;
    const int R0   = mw * 32;
    const int bat  = mw >> 1;          // batch of this mw

    const uint32_t sb = smem_u32(sm);
    const uint32_t BH_ = sb + OFF_BH, BL_ = sb + OFF_BL;
    const uint32_t MH_ = sb + OFF_MH, ML_ = sb + OFF_ML;
    uint8_t* pBH = sm + OFF_BH; uint8_t* pBL = sm + OFF_BL;
    uint8_t* pMH = sm + OFF_MH; uint8_t* pML = sm + OFF_ML;

    const uint4* B0 = (const uint4*)(g_wb + 0);
    const uint4* B1 = (const uint4*)(g_wb + 65536);
    const uint4* B2 = (const uint4*)(g_wb + 196608);
    const uint4* B3 = (const uint4*)(g_wb + 327680);
    const uint4* B4 = (const uint4*)(g_wb + 458752);
    const uint4* B5 = (const uint4*)(g_wb + 524288);

    // ---- stage x (128 rows x 64) + scalars ----
    {
        int row = tid >> 2, qd = tid & 3;
        const float* xr = state + (size_t)blockIdx.x*8192 + row*64 + qd*16;
        float xv[16];
        #pragma unroll
        for (int j = 0; j < 4; j++) ((float4*)xv)[j] = __ldg((const float4*)(xr + 4*j));
        #pragma unroll
        for (int j = 0; j < 8; j++){
            int nc = qd*16 + 2*j;
            swst(pMH, 256, row, nc, pack_hi(xv[2*j], xv[2*j+1]));
            swst(pML, 256, row, nc, pack_lo(xv[2*j], xv[2*j+1]));
        }
        if (qd == 3) F[F_VIS + row] = (xv[13] > 0.f) ? 1.f : 0.f;   // col 61
        if ((tid & 255) == 0){
            #pragma unroll
            for (int i = 0; i < 9; i++) F[F_JOINT + (row>>6)*160 + i] = xv[i];
        }
        if (tid < 256){ F[F_B1A + tid] = __ldg(&b1a[tid]); F[F_B2A + tid] = __ldg(&b2a[tid]); }
        if (tid < 128){ F[F_B1B + tid] = __ldg(&b1b[tid]); F[F_B2B + tid] = __ldg(&b2b[tid]); }
        if (tid < 64){  F[F_BA2 + tid] = __ldg(&ba2[tid]); F[F_WA3 + tid] = __ldg(&wa3[tid]); }
    }
    __syncthreads();

    // ============ L0: h1 = relu(x @ w1a + b1a)  K=64 N=256 ============
    {
        float acc[2][8][4];
        gemm<4,8>(MH_, ML_, 256, B0, mw, nw, lane, acc);
        #pragma unroll
        for (int t = 0; t < 8; t++){
            int c = nw*64 + t*8 + 2*tg;
            float bb0 = F[F_B1A + c], bb1 = F[F_B1A + c + 1];
            #pragma unroll
            for (int m = 0; m < 2; m++){
                int rA = R0 + m*16 + g, rB = rA + 8;
                float v0 = fmaxf(acc[m][t][0] + bb0, 0.f);
                float v1 = fmaxf(acc[m][t][1] + bb1, 0.f);
                float v2 = fmaxf(acc[m][t][2] + bb0, 0.f);
                float v3 = fmaxf(acc[m][t][3] + bb1, 0.f);
                swst(pBH, 512, rA, c, pack_hi(v0, v1));
                swst(pBL, 512, rA, c, pack_lo(v0, v1));
                swst(pBH, 512, rB, c, pack_hi(v2, v3));
                swst(pBL, 512, rB, c, pack_lo(v2, v3));
            }
        }
    }
    __syncthreads();

    // ============ L1: m1 = relu(h1 @ w1b + b1b)  K=256 N=128 ============
    {
        float acc[2][4][4];
        gemm<16,4>(BH_, BL_, 512, B1, mw, nw, lane, acc);
        float visA[2], visB[2];
        #pragma unroll
        for (int m = 0; m < 2; m++){
            visA[m] = F[F_VIS + R0 + m*16 + g];
            visB[m] = F[F_VIS + R0 + m*16 + g + 8];
        }
        #pragma unroll
        for (int t = 0; t < 4; t++){
            int c = nw*32 + t*8 + 2*tg;
            float bb0 = F[F_B1B + c], bb1 = F[F_B1B + c + 1];
            float g0 = 0.f, g1 = 0.f;
            #pragma unroll
            for (int m = 0; m < 2; m++){
                int rA = R0 + m*16 + g, rB = rA + 8;
                float v0 = fmaxf(acc[m][t][0] + bb0, 0.f);
                float v1 = fmaxf(acc[m][t][1] + bb1, 0.f);
                float v2 = fmaxf(acc[m][t][2] + bb0, 0.f);
                float v3 = fmaxf(acc[m][t][3] + bb1, 0.f);
                swst(pMH, 256, rA, c, pack_hi(v0, v1));   // UNMASKED m1
                swst(pML, 256, rA, c, pack_lo(v0, v1));
                swst(pMH, 256, rB, c, pack_hi(v2, v3));
                swst(pML, 256, rB, c, pack_lo(v2, v3));
                g0 += v0*visA[m] + v2*visB[m];
                g1 += v1*visA[m] + v3*visB[m];
            }
            #pragma unroll
            for (int o = 4; o <= 16; o <<= 1){
                g0 += __shfl_xor_sync(0xffffffffu, g0, o);
                g1 += __shfl_xor_sync(0xffffffffu, g1, o);
            }
            if (lane < 4){   // g==0, tg==lane
                F[F_GSP + mw*128 + c]     = g0;
                F[F_GSP + mw*128 + c + 1] = g1;
            }
        }
    }
    __syncthreads();
    // gsb[b][n] = ba1[n] + (1/64) * sum_j (gsp[2b][j]+gsp[2b+1][j]) * wa1[128+j][n]
    if (tid < 256){
        int b = tid >> 7, n = tid & 127;
        const float* g0p = &F[F_GSP + (2*b)*128];
        const float* g1p = &F[F_GSP + (2*b+1)*128];
        float a0 = 0.f, a1 = 0.f;
        #pragma unroll 8
        for (int j = 0; j < 128; j += 2){
            a0 += (g0p[j]   + g1p[j]  ) * __ldg(&wa1[(128 + j)*128 + n]);
            a1 += (g0p[j+1] + g1p[j+1]) * __ldg(&wa1[(129 + j)*128 + n]);
        }
        F[F_GSB + tid] = (a0 + a1) * (1.f/64.f) + __ldg(&ba1[n]);
    }
    __syncthreads();

    // ============ L4: att1 = relu(vis*(m1 @ wa1a) + gsb)  K=128 N=128 ============
    {
        float acc[2][4][4];
        gemm<8,4>(MH_, ML_, 256, B4, mw, nw, lane, acc);
        float visA[2], visB[2];
        #pragma unroll
        for (int m = 0; m < 2; m++){
            visA[m] = F[F_VIS + R0 + m*16 + g];
            visB[m] = F[F_VIS + R0 + m*16 + g + 8];
        }
        #pragma unroll
        for (int t = 0; t < 4; t++){
            int c = nw*32 + t*8 + 2*tg;
            float g0 = F[F_GSB + bat*128 + c], g1 = F[F_GSB + bat*128 + c + 1];
            #pragma unroll
            for (int m = 0; m < 2; m++){
                int rA = R0 + m*16 + g, rB = rA + 8;
                float v0 = fmaxf(acc[m][t][0]*visA[m] + g0, 0.f);
                float v1 = fmaxf(acc[m][t][1]*visA[m] + g1, 0.f);
                float v2 = fmaxf(acc[m][t][2]*visB[m] + g0, 0.f);
                float v3 = fmaxf(acc[m][t][3]*visB[m] + g1, 0.f);
                swst(pBH, 512, rA, c, pack_hi(v0, v1));
                swst(pBL, 512, rA, c, pack_lo(v0, v1));
                swst(pBH, 512, rB, c, pack_hi(v2, v3));
                swst(pBL, 512, rB, c, pack_lo(v2, v3));
            }
        }
    }
    __syncthreads();

    // ============ L5: score partials  K=128 N=64 ============
    {
        float acc[2][2][4];
        gemm<8,2>(BH_, BL_, 512, B5, mw, nw, lane, acc);
        float pA[2] = {0,0}, pB[2] = {0,0};
        #pragma unroll
        for (int t = 0; t < 2; t++){
            int c = nw*16 + t*8 + 2*tg;
            float a2 = F[F_BA2 + c], a3 = F[F_BA2 + c + 1];
            float w0 = F[F_WA3 + c], w1 = F[F_WA3 + c + 1];
            #pragma unroll
            for (int m = 0; m < 2; m++){
                pA[m] += fmaxf(acc[m][t][0] + a2, 0.f)*w0 + fmaxf(acc[m][t][1] + a3, 0.f)*w1;
                pB[m] += fmaxf(acc[m][t][2] + a2, 0.f)*w0 + fmaxf(acc[m][t][3] + a3, 0.f)*w1;
            }
        }
        #pragma unroll
        for (int m = 0; m < 2; m++){
            #pragma unroll
            for (int o = 1; o <= 2; o <<= 1){
                pA[m] += __shfl_xor_sync(0xffffffffu, pA[m], o);
                pB[m] += __shfl_xor_sync(0xffffffffu, pB[m], o);
            }
        }
        if (tg == 0){
            #pragma unroll
            for (int m = 0; m < 2; m++){
                F[F_SPART + nw*128 + R0 + m*16 + g]     = pA[m];
                F[F_SPART + nw*128 + R0 + m*16 + g + 8] = pB[m];
            }
        }
    }
    __syncthreads();

    // ---- softmax + coefficients + joint init ----
    {
        float e = 0.f;
        if (tid < 128){
            float s = F[F_SPART + tid] + F[F_SPART + 128 + tid]
                    + F[F_SPART + 256 + tid] + F[F_SPART + 384 + tid] + __ldg(&ba3[0]);
            e = (s != 0.f) ? expf(s) : 0.f;
            float t1 = e;
            #pragma unroll
            for (int o = 16; o > 0; o >>= 1) t1 += __shfl_xor_sync(0xffffffffu, t1, o);
            if (lane == 0) F[F_RED + wid] = t1;
        }
        __syncthreads();
        if (tid < 128){
            int b = tid >> 6;
            float ssum = F[F_RED + 2*b] + F[F_RED + 2*b + 1];
            float coef = (e / ssum) * F[F_VIS + tid];
            F[F_COEF + tid] = coef;
            float t2 = coef;
            #pragma unroll
            for (int o = 16; o > 0; o >>= 1) t2 += __shfl_xor_sync(0xffffffffu, t2, o);
            if (lane == 0) F[F_RED + 8 + wid] = t2;
        }
        __syncthreads();
        if (tid < 256){
            int b = tid >> 7, c = tid & 127;
            float csum = F[F_RED + 8 + 2*b] + F[F_RED + 8 + 2*b + 1];
            F[F_JOINT + b*160 + 9 + c] = csum * F[F_B2B + c];
        }
    }
    __syncthreads();

    // ============ L2: h2 = relu(m1 @ w2a + b2a)  K=128 N=256 ============
    {
        float acc[2][8][4];
        gemm<8,8>(MH_, ML_, 256, B2, mw, nw, lane, acc);
        #pragma unroll
        for (int t = 0; t < 8; t++){
            int c = nw*64 + t*8 + 2*tg;
            float bb0 = F[F_B2A + c], bb1 = F[F_B2A + c + 1];
            #pragma unroll
            for (int m = 0; m < 2; m++){
                int rA = R0 + m*16 + g, rB = rA + 8;
                float v0 = fmaxf(acc[m][t][0] + bb0, 0.f);
                float v1 = fmaxf(acc[m][t][1] + bb1, 0.f);
                float v2 = fmaxf(acc[m][t][2] + bb0, 0.f);
                float v3 = fmaxf(acc[m][t][3] + bb1, 0.f);
                swst(pBH, 512, rA, c, pack_hi(v0, v1));
                swst(pBL, 512, rA, c, pack_lo(v0, v1));
                swst(pBH, 512, rB, c, pack_hi(v2, v3));
                swst(pBL, 512, rB, c, pack_lo(v2, v3));
            }
        }
    }
    __syncthreads();

    // ============ L3: jp[mw] = coef . (h2 @ w2b)  K=256 N=128 ============
    {
        float acc[2][4][4];
        gemm<16,4>(BH_, BL_, 512, B3, mw, nw, lane, acc);
        float cA[2], cB[2];
        #pragma unroll
        for (int m = 0; m < 2; m++){
            cA[m] = F[F_COEF + R0 + m*16 + g];
            cB[m] = F[F_COEF + R0 + m*16 + g + 8];
        }
        #pragma unroll
        for (int t = 0; t < 4; t++){
            int c = nw*32 + t*8 + 2*tg;
            float w0 = 0.f, w1 = 0.f;
            #pragma unroll
            for (int m = 0; m < 2; m++){
                w0 += cA[m]*acc[m][t][0] + cB[m]*acc[m][t][2];
                w1 += cA[m]*acc[m][t][1] + cB[m]*acc[m][t][3];
            }
            #pragma unroll
            for (int o = 4; o <= 16; o <<= 1){
                w0 += __shfl_xor_sync(0xffffffffu, w0, o);
                w1 += __shfl_xor_sync(0xffffffffu, w1, o);
            }
            if (lane < 4){
                F[F_JP + mw*128 + c]     = w0;
                F[F_JP + mw*128 + c + 1] = w1;
            }
        }
    }
    __syncthreads();
    if (tid < 256){
        int b = tid >> 7, c = tid & 127;
        F[F_JOINT + b*160 + 9 + c] += F[F_JP + (2*b)*128 + c] + F[F_JP + (2*b+1)*128 + c];
    }
    __syncthreads();

    // ============ final MLP: 137 -> 256 -> 128 -> 1 (fp32), 2 batches ============
    {
        int b = tid >> 8, n = tid & 255;
        float a0 = __ldg(&b3a[n]), a1 = 0.f;
        const float* J = &F[F_JOINT + b*160];
        #pragma unroll 4
        for (int i = 0; i < 136; i += 2){
            a0 += J[i]   * __ldg(&w3a[i*256 + n]);
            a1 += J[i+1] * __ldg(&w3a[(i+1)*256 + n]);
        }
        a0 += J[136] * __ldg(&w3a[136*256 + n]);
        F[F_H3 + b*256 + n] = fmaxf(a0 + a1, 0.f);
    }
    __syncthreads();
    if (tid < 256){
        int b = tid >> 7, n = tid & 127;
        float a0 = __ldg(&b3b[n]), a1 = 0.f;
        const float* H = &F[F_H3 + b*256];
        #pragma unroll 4
        for (int i = 0; i < 256; i += 2){
            a0 += H[i]   * __ldg(&w3b[i*128 + n]);
            a1 += H[i+1] * __ldg(&w3b[(i+1)*128 + n]);
        }
        float p = fmaxf(a0 + a1, 0.f) * __ldg(&w3c[n]);
        #pragma unroll
        for (int o = 16; o > 0; o >>= 1) p += __shfl_xor_sync(0xffffffffu, p, o);
        if (lane == 0) F[F_RED + wid] = p;
    }
    __syncthreads();
    if (tid < 2){
        out[blockIdx.x*2 + tid] = F[F_RED + tid*4] + F[F_RED + tid*4 + 1]
                                + F[F_RED + tid*4 + 2] + F[F_RED + tid*4 + 3]
                                + __ldg(&b3c[0]);
    }
}

extern "C" void kernel_launch(void* const* d_in, const int* in_sizes, int n_in,
                              void* d_out, int out_size)
{
    (void)in_sizes; (void)n_in; (void)out_size;
    const float* state = (const float*)d_in[0];
    const float* w1a = (const float*)d_in[1];  const float* b1a = (const float*)d_in[2];
    const float* w1b = (const float*)d_in[3];  const float* b1b = (const float*)d_in[4];
    const float* w2a = (const float*)d_in[5];  const float* b2a = (const float*)d_in[6];
    const float* w2b = (const float*)d_in[7];  const float* b2b = (const float*)d_in[8];
    const float* wa1 = (const float*)d_in[9];  const float* ba1 = (const float*)d_in[10];
    const float* wa2 = (const float*)d_in[11]; const float* ba2 = (const float*)d_in[12];
    const float* wa3 = (const float*)d_in[13]; const float* ba3 = (const float*)d_in[14];
    const float* w3a = (const float*)d_in[15]; const float* b3a = (const float*)d_in[16];
    const float* w3b = (const float*)d_in[17]; const float* b3b = (const float*)d_in[18];
    const float* w3c = (const float*)d_in[19]; const float* b3c = (const float*)d_in[20];
    float* out = (float*)d_out;

    prep_kernel<<<(34816 + 255)/256, 256>>>(w1a, w1b, w2a, w2b, wa1, wa2);

    cudaFuncSetAttribute(value_net_mma,
                         cudaFuncAttributeMaxDynamicSharedMemorySize, SMEM_BYTES);
    value_net_mma<<<2048, TPB, SMEM_BYTES>>>(
        state, b1a, b1b, b2a, b2b, wa1, ba1, ba2, wa3, ba3,
        w3a, b3a, w3b, b3b, w3c, b3c, out);
}

// round 8
// speedup vs baseline: 3.6458x; 1.1123x over previous
#include <cuda_runtime.h>
#include <cuda_bf16.h>
#include <cstdint>

#define TPB 256

// ===================== PTX wrappers =====================
__device__ __forceinline__ uint32_t smem_u32(const void* p){
    uint32_t a;
    asm("{ .reg .u64 t; cvta.to.shared.u64 t, %1; cvt.u32.u64 %0, t; }":"=r"(a):"l"(p));
    return a;
}
#define LDSM4(r, a) \
    asm volatile("ldmatrix.sync.aligned.m8n8.x4.shared.b16 {%0,%1,%2,%3}, [%4];" \
        :"=r"((r)[0]),"=r"((r)[1]),"=r"((r)[2]),"=r"((r)[3]):"r"(a))
#define MMA_BF16(c, a, b) \
    asm volatile("mma.sync.aligned.m16n8k16.row.col.f32.bf16.bf16.f32 " \
        "{%0,%1,%2,%3},{%4,%5,%6,%7},{%8,%9},{%0,%1,%2,%3};" \
        :"+f"((c)[0]),"+f"((c)[1]),"+f"((c)[2]),"+f"((c)[3]) \
        :"r"((a)[0]),"r"((a)[1]),"r"((a)[2]),"r"((a)[3]),"r"((b)[0]),"r"((b)[1]))

__device__ __forceinline__ uint32_t pack_hi(float v0, float v1){
    return __byte_perm(__float_as_uint(v0), __float_as_uint(v1), 0x7632);
}
__device__ __forceinline__ uint32_t pack_lo(float v0, float v1){
    float l0 = v0 - __uint_as_float(__float_as_uint(v0) & 0xFFFF0000u);
    float l1 = v1 - __uint_as_float(__float_as_uint(v1) & 0xFFFF0000u);
    __nv_bfloat162 L = __floats2bfloat162_rn(l0, l1);
    return *(uint32_t*)&L;
}
__device__ __forceinline__ void swst(uint8_t* plane, int P, int r, int nc, uint32_t v){
    *(uint32_t*)(plane + r*P + ((((nc>>3) ^ (r&7)) << 4) | ((nc<<1) & 15))) = v;
}

// ===================== fragment-packed weights =====================
__device__ __align__(128) uint8_t g_wb[557056];

__global__ void prep_kernel(const float* __restrict__ w1a, const float* __restrict__ w1b,
                            const float* __restrict__ w2a, const float* __restrict__ w2b,
                            const float* __restrict__ wa1, const float* __restrict__ wa2)
{
    const float* W[6] = {w1a, w1b, w2a, w2b, wa1, wa2};
    const int   NN[6] = {256, 128, 256, 128, 128, 64};
    const int   KS[6] = {4, 16, 8, 16, 8, 8};
    const int   EO[7] = {0, 4096, 12288, 20480, 28672, 32768, 34816};
    const int   BO[6] = {0, 65536, 196608, 327680, 458752, 524288};
    int idx = blockIdx.x * blockDim.x + threadIdx.x;
    if (idx >= 34816) return;
    int l = 0;
    while (idx >= EO[l+1]) l++;
    int e = idx - EO[l];
    int lane = e & 31, qq = e >> 5;
    int s = qq % KS[l], T = qq / KS[l];
    int tg = lane & 3, g = lane >> 2;
    int n = T*8 + g;
    int k0 = s*16 + 2*tg;
    int N = NN[l];
    const float* Wl = W[l];
    float w0 = Wl[(k0  )*N + n], w1 = Wl[(k0+1)*N + n];
    float w2 = Wl[(k0+8)*N + n], w3 = Wl[(k0+9)*N + n];
    __nv_bfloat16 h0 = __float2bfloat16(w0), h1 = __float2bfloat16(w1);
    __nv_bfloat16 h2 = __float2bfloat16(w2), h3 = __float2bfloat16(w3);
    __nv_bfloat162 H0; H0.x = h0; H0.y = h1;
    __nv_bfloat162 H1; H1.x = h2; H1.y = h3;
    __nv_bfloat162 L0; L0.x = __float2bfloat16(w0 - __bfloat162float(h0));
                       L0.y = __float2bfloat16(w1 - __bfloat162float(h1));
    __nv_bfloat162 L1; L1.x = __float2bfloat16(w2 - __bfloat162float(h2));
                       L1.y = __float2bfloat16(w3 - __bfloat162float(h3));
    uint4 o;
    o.x = *(uint32_t*)&H0; o.y = *(uint32_t*)&H1;
    o.z = *(uint32_t*)&L0; o.w = *(uint32_t*)&L1;
    *(uint4*)(g_wb + BO[l] + (size_t)e*16) = o;
}

// ===================== smem layout (per CTA, ~105 KB) =====================
#define OFF_BH   0          // big act hi: 64 x 512B
#define OFF_BL   32768
#define OFF_MH   65536      // m1/x hi: 64 x 256B
#define OFF_ML   81920
#define OFF_F    98304
#define F_B1A   0
#define F_B1B   256
#define F_B2A   384
#define F_B2B   640
#define F_BA2   768
#define F_WA3   832
#define F_VIS   896
#define F_GSP   960       // [2][128] per-mw gs partials
#define F_SPART 1216      // [4][64]
#define F_COEF  1472
#define F_GSB   1536      // [128]
#define F_JP    1664      // [2][128]
#define F_JOINT 1920      // [160]
#define F_RED   2080
#define F_H3    2096      // [256]
#define F_TOT   2352
#define SMEM_BYTES (OFF_F + F_TOT*4)   // 107712

// ========== GEMM: M=64, 8 warps 2(M)x4(N), warp tile 32 x NT*8 ==========
template<int KSTEPS, int NT>
__device__ __forceinline__ void gemm(uint32_t aH, uint32_t aL, int P,
                                     const uint4* __restrict__ Bf,
                                     int mw, int nw, int lane,
                                     float (&acc)[2][NT][4])
{
    #pragma unroll
    for (int m = 0; m < 2; m++)
        #pragma unroll
        for (int t = 0; t < NT; t++)
            #pragma unroll
            for (int j = 0; j < 4; j++) acc[m][t][j] = 0.f;

    const uint32_t rowoff = (uint32_t)((mw*32 + (lane & 15)) * P);
    const uint32_t chi = (uint32_t)(lane >> 4);
    const uint32_t swr = (uint32_t)(lane & 7);
    const uint4* bp = Bf + (size_t)(nw*NT)*KSTEPS*32 + lane;

    #pragma unroll 2
    for (int s = 0; s < KSTEPS; s++){
        uint32_t co = (((2u*s + chi) ^ swr) << 4);
        uint32_t AH[2][4], AL[2][4];
        #pragma unroll
        for (int m = 0; m < 2; m++){
            LDSM4(AH[m], aH + rowoff + (uint32_t)(m*16*P) + co);
            LDSM4(AL[m], aL + rowoff + (uint32_t)(m*16*P) + co);
        }
        const uint4* bps = bp + (size_t)s*32;
        #pragma unroll
        for (int t = 0; t < NT; t++){
            uint4 bb = __ldg(bps + (size_t)t*KSTEPS*32);
            uint32_t BH[2] = {bb.x, bb.y};
            uint32_t BL[2] = {bb.z, bb.w};
            #pragma unroll
            for (int m = 0; m < 2; m++){
                MMA_BF16(acc[m][t], AH[m], BH);
                MMA_BF16(acc[m][t], AL[m], BH);
                MMA_BF16(acc[m][t], AH[m], BL);
            }
        }
    }
}

__global__ void __launch_bounds__(TPB, 2)
value_net_mma(const float* __restrict__ state,
              const float* __restrict__ b1a, const float* __restrict__ b1b,
              const float* __restrict__ b2a, const float* __restrict__ b2b,
              const float* __restrict__ wa1, const float* __restrict__ ba1,
              const float* __restrict__ ba2,
              const float* __restrict__ wa3, const float* __restrict__ ba3,
              const float* __restrict__ w3a, const float* __restrict__ b3a,
              const float* __restrict__ w3b, const float* __restrict__ b3b,
              const float* __restrict__ w3c, const float* __restrict__ b3c,
              float* __restrict__ out)
{
    extern __shared__ __align__(128) uint8_t sm[];
    float* F = (float*)(sm + OFF_F);
    const int tid  = threadIdx.x;
    const int lane = tid & 31;
    const int wid  = tid >> 5;
    const int mw   = wid & 1;          // M group (32 rows)
    const int nw   = wid >> 1;         // N group (0..3)
    const int g    = lane >> 2;
    const int tg   = lane & 3;
    const int R0   = mw * 32;

    const uint32_t sb = smem_u32(sm);
    const uint32_t BH_ = sb + OFF_BH, BL_ = sb + OFF_BL;
    const uint32_t MH_ = sb + OFF_MH, ML_ = sb + OFF_ML;
    uint8_t* pBH = sm + OFF_BH; uint8_t* pBL = sm + OFF_BL;
    uint8_t* pMH = sm + OFF_MH; uint8_t* pML = sm + OFF_ML;

    const uint4* B0 = (const uint4*)(g_wb + 0);
    const uint4* B1 = (const uint4*)(g_wb + 65536);
    const uint4* B2 = (const uint4*)(g_wb + 196608);
    const uint4* B3 = (const uint4*)(g_wb + 327680);
    const uint4* B4 = (const uint4*)(g_wb + 458752);
    const uint4* B5 = (const uint4*)(g_wb + 524288);

    // ---- stage x (64 rows x 64) + scalars ----
    {
        int row = tid >> 2, qd = tid & 3;
        const float* xr = state + (size_t)blockIdx.x*4096 + row*64 + qd*16;
        float xv[16];
        #pragma unroll
        for (int j = 0; j < 4; j++) ((float4*)xv)[j] = __ldg((const float4*)(xr + 4*j));
        #pragma unroll
        for (int j = 0; j < 8; j++){
            int nc = qd*16 + 2*j;
            swst(pMH, 256, row, nc, pack_hi(xv[2*j], xv[2*j+1]));
            swst(pML, 256, row, nc, pack_lo(xv[2*j], xv[2*j+1]));
        }
        if (qd == 3) F[F_VIS + row] = (xv[13] > 0.f) ? 1.f : 0.f;   // col 61
        if (tid == 0){
            #pragma unroll
            for (int i = 0; i < 9; i++) F[F_JOINT + i] = xv[i];
        }
        F[F_B1A + tid] = __ldg(&b1a[tid]);
        F[F_B2A + tid] = __ldg(&b2a[tid]);
        if (tid < 128){ F[F_B1B + tid] = __ldg(&b1b[tid]); F[F_B2B + tid] = __ldg(&b2b[tid]); }
        if (tid < 64){  F[F_BA2 + tid] = __ldg(&ba2[tid]); F[F_WA3 + tid] = __ldg(&wa3[tid]); }
    }
    __syncthreads();

    // ============ L0: h1 = relu(x @ w1a + b1a)  K=64 N=256 ============
    {
        float acc[2][8][4];
        gemm<4,8>(MH_, ML_, 256, B0, mw, nw, lane, acc);
        #pragma unroll
        for (int t = 0; t < 8; t++){
            int c = nw*64 + t*8 + 2*tg;
            float bb0 = F[F_B1A + c], bb1 = F[F_B1A + c + 1];
            #pragma unroll
            for (int m = 0; m < 2; m++){
                int rA = R0 + m*16 + g, rB = rA + 8;
                float v0 = fmaxf(acc[m][t][0] + bb0, 0.f);
                float v1 = fmaxf(acc[m][t][1] + bb1, 0.f);
                float v2 = fmaxf(acc[m][t][2] + bb0, 0.f);
                float v3 = fmaxf(acc[m][t][3] + bb1, 0.f);
                swst(pBH, 512, rA, c, pack_hi(v0, v1));
                swst(pBL, 512, rA, c, pack_lo(v0, v1));
                swst(pBH, 512, rB, c, pack_hi(v2, v3));
                swst(pBL, 512, rB, c, pack_lo(v2, v3));
            }
        }
    }
    __syncthreads();

    // ============ L1: m1 = relu(h1 @ w1b + b1b)  K=256 N=128 ============
    {
        float acc[2][4][4];
        gemm<16,4>(BH_, BL_, 512, B1, mw, nw, lane, acc);
        float visA[2], visB[2];
        #pragma unroll
        for (int m = 0; m < 2; m++){
            visA[m] = F[F_VIS + R0 + m*16 + g];
            visB[m] = F[F_VIS + R0 + m*16 + g + 8];
        }
        #pragma unroll
        for (int t = 0; t < 4; t++){
            int c = nw*32 + t*8 + 2*tg;
            float bb0 = F[F_B1B + c], bb1 = F[F_B1B + c + 1];
            float g0 = 0.f, g1 = 0.f;
            #pragma unroll
            for (int m = 0; m < 2; m++){
                int rA = R0 + m*16 + g, rB = rA + 8;
                float v0 = fmaxf(acc[m][t][0] + bb0, 0.f);
                float v1 = fmaxf(acc[m][t][1] + bb1, 0.f);
                float v2 = fmaxf(acc[m][t][2] + bb0, 0.f);
                float v3 = fmaxf(acc[m][t][3] + bb1, 0.f);
                swst(pMH, 256, rA, c, pack_hi(v0, v1));   // UNMASKED m1
                swst(pML, 256, rA, c, pack_lo(v0, v1));
                swst(pMH, 256, rB, c, pack_hi(v2, v3));
                swst(pML, 256, rB, c, pack_lo(v2, v3));
                g0 += v0*visA[m] + v2*visB[m];
                g1 += v1*visA[m] + v3*visB[m];
            }
            #pragma unroll
            for (int o = 4; o <= 16; o <<= 1){
                g0 += __shfl_xor_sync(0xffffffffu, g0, o);
                g1 += __shfl_xor_sync(0xffffffffu, g1, o);
            }
            if (lane < 4){   // g==0, tg==lane
                F[F_GSP + mw*128 + c]     = g0;
                F[F_GSP + mw*128 + c + 1] = g1;
            }
        }
    }
    __syncthreads();
    // gsb[n] = ba1[n] + (1/64) * sum_j (gsp[0][j]+gsp[1][j]) * wa1[128+j][n]
    if (tid < 128){
        int n = tid;
        const float* g0p = &F[F_GSP];
        const float* g1p = &F[F_GSP + 128];
        float a0 = 0.f, a1 = 0.f;
        #pragma unroll 8
        for (int j = 0; j < 128; j += 2){
            a0 += (g0p[j]   + g1p[j]  ) * __ldg(&wa1[(128 + j)*128 + n]);
            a1 += (g0p[j+1] + g1p[j+1]) * __ldg(&wa1[(129 + j)*128 + n]);
        }
        F[F_GSB + n] = (a0 + a1) * (1.f/64.f) + __ldg(&ba1[n]);
    }
    __syncthreads();

    // ============ L4: att1 = relu(vis*(m1 @ wa1a) + gsb)  K=128 N=128 ============
    {
        float acc[2][4][4];
        gemm<8,4>(MH_, ML_, 256, B4, mw, nw, lane, acc);
        float visA[2], visB[2];
        #pragma unroll
        for (int m = 0; m < 2; m++){
            visA[m] = F[F_VIS + R0 + m*16 + g];
            visB[m] = F[F_VIS + R0 + m*16 + g + 8];
        }
        #pragma unroll
        for (int t = 0; t < 4; t++){
            int c = nw*32 + t*8 + 2*tg;
            float g0 = F[F_GSB + c], g1 = F[F_GSB + c + 1];
            #pragma unroll
            for (int m = 0; m < 2; m++){
                int rA = R0 + m*16 + g, rB = rA + 8;
                float v0 = fmaxf(acc[m][t][0]*visA[m] + g0, 0.f);
                float v1 = fmaxf(acc[m][t][1]*visA[m] + g1, 0.f);
                float v2 = fmaxf(acc[m][t][2]*visB[m] + g0, 0.f);
                float v3 = fmaxf(acc[m][t][3]*visB[m] + g1, 0.f);
                swst(pBH, 512, rA, c, pack_hi(v0, v1));
                swst(pBL, 512, rA, c, pack_lo(v0, v1));
                swst(pBH, 512, rB, c, pack_hi(v2, v3));
                swst(pBL, 512, rB, c, pack_lo(v2, v3));
            }
        }
    }
    __syncthreads();

    // ============ L5: score partials  K=128 N=64 ============
    {
        float acc[2][2][4];
        gemm<8,2>(BH_, BL_, 512, B5, mw, nw, lane, acc);
        float pA[2] = {0,0}, pB[2] = {0,0};
        #pragma unroll
        for (int t = 0; t < 2; t++){
            int c = nw*16 + t*8 + 2*tg;
            float a2 = F[F_BA2 + c], a3 = F[F_BA2 + c + 1];
            float w0 = F[F_WA3 + c], w1 = F[F_WA3 + c + 1];
            #pragma unroll
            for (int m = 0; m < 2; m++){
                pA[m] += fmaxf(acc[m][t][0] + a2, 0.f)*w0 + fmaxf(acc[m][t][1] + a3, 0.f)*w1;
                pB[m] += fmaxf(acc[m][t][2] + a2, 0.f)*w0 + fmaxf(acc[m][t][3] + a3, 0.f)*w1;
            }
        }
        #pragma unroll
        for (int m = 0; m < 2; m++){
            #pragma unroll
            for (int o = 1; o <= 2; o <<= 1){
                pA[m] += __shfl_xor_sync(0xffffffffu, pA[m], o);
                pB[m] += __shfl_xor_sync(0xffffffffu, pB[m], o);
            }
        }
        if (tg == 0){
            #pragma unroll
            for (int m = 0; m < 2; m++){
                F[F_SPART + nw*64 + R0 + m*16 + g]     = pA[m];
                F[F_SPART + nw*64 + R0 + m*16 + g + 8] = pB[m];
            }
        }
    }
    __syncthreads();

    // ---- softmax + coefficients + joint init ----
    {
        float e = 0.f;
        if (tid < 64){
            float s = F[F_SPART + tid] + F[F_SPART + 64 + tid]
                    + F[F_SPART + 128 + tid] + F[F_SPART + 192 + tid] + __ldg(&ba3[0]);
            e = (s != 0.f) ? expf(s) : 0.f;
            float t1 = e;
            #pragma unroll
            for (int o = 16; o > 0; o >>= 1) t1 += __shfl_xor_sync(0xffffffffu, t1, o);
            if (lane == 0) F[F_RED + wid] = t1;
        }
        __syncthreads();
        if (tid < 64){
            float ssum = F[F_RED] + F[F_RED + 1];
            float coef = (e / ssum) * F[F_VIS + tid];
            F[F_COEF + tid] = coef;
            float t2 = coef;
            #pragma unroll
            for (int o = 16; o > 0; o >>= 1) t2 += __shfl_xor_sync(0xffffffffu, t2, o);
            if (lane == 0) F[F_RED + 4 + wid] = t2;
        }
        __syncthreads();
        if (tid < 128){
            float csum = F[F_RED + 4] + F[F_RED + 5];
            F[F_JOINT + 9 + tid] = csum * F[F_B2B + tid];
        }
    }
    __syncthreads();

    // ============ L2: h2 = relu(m1 @ w2a + b2a)  K=128 N=256 ============
    {
        float acc[2][8][4];
        gemm<8,8>(MH_, ML_, 256, B2, mw, nw, lane, acc);
        #pragma unroll
        for (int t = 0; t < 8; t++){
            int c = nw*64 + t*8 + 2*tg;
            float bb0 = F[F_B2A + c], bb1 = F[F_B2A + c + 1];
            #pragma unroll
            for (int m = 0; m < 2; m++){
                int rA = R0 + m*16 + g, rB = rA + 8;
                float v0 = fmaxf(acc[m][t][0] + bb0, 0.f);
                float v1 = fmaxf(acc[m][t][1] + bb1, 0.f);
                float v2 = fmaxf(acc[m][t][2] + bb0, 0.f);
                float v3 = fmaxf(acc[m][t][3] + bb1, 0.f);
                swst(pBH, 512, rA, c, pack_hi(v0, v1));
                swst(pBL, 512, rA, c, pack_lo(v0, v1));
                swst(pBH, 512, rB, c, pack_hi(v2, v3));
                swst(pBL, 512, rB, c, pack_lo(v2, v3));
            }
        }
    }
    __syncthreads();

    // ============ L3: jp[mw] = coef . (h2 @ w2b)  K=256 N=128 ============
    {
        float acc[2][4][4];
        gemm<16,4>(BH_, BL_, 512, B3, mw, nw, lane, acc);
        float cA[2], cB[2];
        #pragma unroll
        for (int m = 0; m < 2; m++){
            cA[m] = F[F_COEF + R0 + m*16 + g];
            cB[m] = F[F_COEF + R0 + m*16 + g + 8];
        }
        #pragma unroll
        for (int t = 0; t < 4; t++){
            int c = nw*32 + t*8 + 2*tg;
            float w0 = 0.f, w1 = 0.f;
            #pragma unroll
            for (int m = 0; m < 2; m++){
                w0 += cA[m]*acc[m][t][0] + cB[m]*acc[m][t][2];
                w1 += cA[m]*acc[m][t][1] + cB[m]*acc[m][t][3];
            }
            #pragma unroll
            for (int o = 4; o <= 16; o <<= 1){
                w0 += __shfl_xor_sync(0xffffffffu, w0, o);
                w1 += __shfl_xor_sync(0xffffffffu, w1, o);
            }
            if (lane < 4){
                F[F_JP + mw*128 + c]     = w0;
                F[F_JP + mw*128 + c + 1] = w1;
            }
        }
    }
    __syncthreads();
    if (tid < 128){
        F[F_JOINT + 9 + tid] += F[F_JP + tid] + F[F_JP + 128 + tid];
    }
    __syncthreads();

    // ============ final MLP: 137 -> 256 -> 128 -> 1 (fp32) ============
    {
        int n = tid;
        float a0 = __ldg(&b3a[n]), a1 = 0.f;
        const float* J = &F[F_JOINT];
        #pragma unroll 4
        for (int i = 0; i < 136; i += 2){
            a0 += J[i]   * __ldg(&w3a[i*256 + n]);
            a1 += J[i+1] * __ldg(&w3a[(i+1)*256 + n]);
        }
        a0 += J[136] * __ldg(&w3a[136*256 + n]);
        F[F_H3 + n] = fmaxf(a0 + a1, 0.f);
    }
    __syncthreads();
    if (tid < 128){
        int n = tid;
        float a0 = __ldg(&b3b[n]), a1 = 0.f;
        const float* H = &F[F_H3];
        #pragma unroll 4
        for (int i = 0; i < 256; i += 2){
            a0 += H[i]   * __ldg(&w3b[i*128 + n]);
            a1 += H[i+1] * __ldg(&w3b[(i+1)*128 + n]);
        }
        float p = fmaxf(a0 + a1, 0.f) * __ldg(&w3c[n]);
        #pragma unroll
        for (int o = 16; o > 0; o >>= 1) p += __shfl_xor_sync(0xffffffffu, p, o);
        if (lane == 0) F[F_RED + wid] = p;
    }
    __syncthreads();
    if (tid == 0){
        out[blockIdx.x] = F[F_RED] + F[F_RED + 1] + F[F_RED + 2] + F[F_RED + 3]
                        + __ldg(&b3c[0]);
    }
}

extern "C" void kernel_launch(void* const* d_in, const int* in_sizes, int n_in,
                              void* d_out, int out_size)
{
    (void)in_sizes; (void)n_in; (void)out_size;
    const float* state = (const float*)d_in[0];
    const float* w1a = (const float*)d_in[1];  const float* b1a = (const float*)d_in[2];
    const float* w1b = (const float*)d_in[3];  const float* b1b = (const float*)d_in[4];
    const float* w2a = (const float*)d_in[5];  const float* b2a = (const float*)d_in[6];
    const float* w2b = (const float*)d_in[7];  const float* b2b = (const float*)d_in[8];
    const float* wa1 = (const float*)d_in[9];  const float* ba1 = (const float*)d_in[10];
    const float* wa2 = (const float*)d_in[11]; const float* ba2 = (const float*)d_in[12];
    const float* wa3 = (const float*)d_in[13]; const float* ba3 = (const float*)d_in[14];
    const float* w3a = (const float*)d_in[15]; const float* b3a = (const float*)d_in[16];
    const float* w3b = (const float*)d_in[17]; const float* b3b = (const float*)d_in[18];
    const float* w3c = (const float*)d_in[19]; const float* b3c = (const float*)d_in[20];
    float* out = (float*)d_out;

    prep_kernel<<<(34816 + 255)/256, 256>>>(w1a, w1b, w2a, w2b, wa1, wa2);

    cudaFuncSetAttribute(value_net_mma,
                         cudaFuncAttributeMaxDynamicSharedMemorySize, SMEM_BYTES);
    value_net_mma<<<4096, TPB, SMEM_BYTES>>>(
        state, b1a, b1b, b2a, b2b, wa1, ba1, ba2, wa3, ba3,
        w3a, b3a, w3b, b3b, w3c, b3c, out);
}

// round 9
// speedup vs baseline: 3.9003x; 1.0698x over previous
#include <cuda_runtime.h>
#include <cuda_bf16.h>
#include <cstdint>

#define TPB 256

// ===================== PTX wrappers =====================
__device__ __forceinline__ uint32_t smem_u32(const void* p){
    uint32_t a;
    asm("{ .reg .u64 t; cvta.to.shared.u64 t, %1; cvt.u32.u64 %0, t; }":"=r"(a):"l"(p));
    return a;
}
#define LDSM4(r, a) \
    asm volatile("ldmatrix.sync.aligned.m8n8.x4.shared.b16 {%0,%1,%2,%3}, [%4];" \
        :"=r"((r)[0]),"=r"((r)[1]),"=r"((r)[2]),"=r"((r)[3]):"r"(a))
#define STSM2(a, r0, r1) \
    asm volatile("stmatrix.sync.aligned.m8n8.x2.shared.b16 [%0], {%1,%2};" \
        :: "r"(a), "r"(r0), "r"(r1) : "memory")
#define MMA_BF16(c, a, b) \
    asm volatile("mma.sync.aligned.m16n8k16.row.col.f32.bf16.bf16.f32 " \
        "{%0,%1,%2,%3},{%4,%5,%6,%7},{%8,%9},{%0,%1,%2,%3};" \
        :"+f"((c)[0]),"+f"((c)[1]),"+f"((c)[2]),"+f"((c)[3]) \
        :"r"((a)[0]),"r"((a)[1]),"r"((a)[2]),"r"((a)[3]),"r"((b)[0]),"r"((b)[1]))

__device__ __forceinline__ uint32_t pack_hi(float v0, float v1){
    return __byte_perm(__float_as_uint(v0), __float_as_uint(v1), 0x7632);
}
__device__ __forceinline__ uint32_t pack_lo(float v0, float v1){
    float l0 = v0 - __uint_as_float(__float_as_uint(v0) & 0xFFFF0000u);
    float l1 = v1 - __uint_as_float(__float_as_uint(v1) & 0xFFFF0000u);
    __nv_bfloat162 L = __floats2bfloat162_rn(l0, l1);
    return *(uint32_t*)&L;
}
__device__ __forceinline__ void swst(uint8_t* plane, int P, int r, int nc, uint32_t v){
    *(uint32_t*)(plane + r*P + ((((nc>>3) ^ (r&7)) << 4) | ((nc<<1) & 15))) = v;
}

// ===================== fragment-packed weights =====================
__device__ __align__(128) uint8_t g_wb[557056];

__global__ void prep_kernel(const float* __restrict__ w1a, const float* __restrict__ w1b,
                            const float* __restrict__ w2a, const float* __restrict__ w2b,
                            const float* __restrict__ wa1, const float* __restrict__ wa2)
{
    const float* W[6] = {w1a, w1b, w2a, w2b, wa1, wa2};
    const int   NN[6] = {256, 128, 256, 128, 128, 64};
    const int   KS[6] = {4, 16, 8, 16, 8, 8};
    const int   EO[7] = {0, 4096, 12288, 20480, 28672, 32768, 34816};
    const int   BO[6] = {0, 65536, 196608, 327680, 458752, 524288};
    int idx = blockIdx.x * blockDim.x + threadIdx.x;
    if (idx >= 34816) return;
    int l = 0;
    while (idx >= EO[l+1]) l++;
    int e = idx - EO[l];
    int lane = e & 31, qq = e >> 5;
    int s = qq % KS[l], T = qq / KS[l];
    int tg = lane & 3, g = lane >> 2;
    int n = T*8 + g;
    int k0 = s*16 + 2*tg;
    int N = NN[l];
    const float* Wl = W[l];
    float w0 = Wl[(k0  )*N + n], w1 = Wl[(k0+1)*N + n];
    float w2 = Wl[(k0+8)*N + n], w3 = Wl[(k0+9)*N + n];
    __nv_bfloat16 h0 = __float2bfloat16(w0), h1 = __float2bfloat16(w1);
    __nv_bfloat16 h2 = __float2bfloat16(w2), h3 = __float2bfloat16(w3);
    __nv_bfloat162 H0; H0.x = h0; H0.y = h1;
    __nv_bfloat162 H1; H1.x = h2; H1.y = h3;
    __nv_bfloat162 L0; L0.x = __float2bfloat16(w0 - __bfloat162float(h0));
                       L0.y = __float2bfloat16(w1 - __bfloat162float(h1));
    __nv_bfloat162 L1; L1.x = __float2bfloat16(w2 - __bfloat162float(h2));
                       L1.y = __float2bfloat16(w3 - __bfloat162float(h3));
    uint4 o;
    o.x = *(uint32_t*)&H0; o.y = *(uint32_t*)&H1;
    o.z = *(uint32_t*)&L0; o.w = *(uint32_t*)&L1;
    *(uint4*)(g_wb + BO[l] + (size_t)e*16) = o;
}

// ===================== smem layout (per CTA, ~105 KB) =====================
#define OFF_BH   0          // big act hi: 64 x 512B
#define OFF_BL   32768
#define OFF_MH   65536      // m1/x hi: 64 x 256B
#define OFF_ML   81920
#define OFF_F    98304
#define F_B1A   0
#define F_B1B   256
#define F_B2A   384
#define F_B2B   640
#define F_BA2   768
#define F_WA3   832
#define F_VIS   896
#define F_GSP   960       // [2][128] per-mw gs partials
#define F_SPART 1216      // [4][64]  (also reused as split-K scratch)
#define F_COEF  1472
#define F_GSB   1536      // [128]
#define F_JP    1664      // [2][128]
#define F_JOINT 1920      // [160]
#define F_RED   2080
#define F_H3    2096      // [256]
#define F_TOT   2352
#define SMEM_BYTES (OFF_F + F_TOT*4)   // 107712

// ========== GEMM: M=64, 8 warps 2(M)x4(N), warp tile 32 x NT*8 ==========
// bias != nullptr: accumulators initialized with bias[col] (bias fold)
template<int KSTEPS, int NT>
__device__ __forceinline__ void gemm(uint32_t aH, uint32_t aL, int P,
                                     const uint4* __restrict__ Bf,
                                     int mw, int nw, int lane,
                                     float (&acc)[2][NT][4],
                                     const float* __restrict__ bias)
{
    const int tg2 = (lane & 3) * 2;
    #pragma unroll
    for (int t = 0; t < NT; t++){
        float b0 = 0.f, b1 = 0.f;
        if (bias){
            int c = nw*(NT*8) + t*8 + tg2;
            b0 = bias[c]; b1 = bias[c + 1];
        }
        #pragma unroll
        for (int m = 0; m < 2; m++){
            acc[m][t][0] = b0; acc[m][t][1] = b1;
            acc[m][t][2] = b0; acc[m][t][3] = b1;
        }
    }

    const uint32_t rowoff = (uint32_t)((mw*32 + (lane & 15)) * P);
    const uint32_t chi = (uint32_t)(lane >> 4);
    const uint32_t swr = (uint32_t)(lane & 7);
    const uint4* bp = Bf + (size_t)(nw*NT)*KSTEPS*32 + lane;

    #pragma unroll 2
    for (int s = 0; s < KSTEPS; s++){
        uint32_t co = (((2u*s + chi) ^ swr) << 4);
        uint32_t AH[2][4], AL[2][4];
        #pragma unroll
        for (int m = 0; m < 2; m++){
            LDSM4(AH[m], aH + rowoff + (uint32_t)(m*16*P) + co);
            LDSM4(AL[m], aL + rowoff + (uint32_t)(m*16*P) + co);
        }
        const uint4* bps = bp + (size_t)s*32;
        #pragma unroll
        for (int t = 0; t < NT; t++){
            uint4 bb = __ldg(bps + (size_t)t*KSTEPS*32);
            uint32_t BH[2] = {bb.x, bb.y};
            uint32_t BL[2] = {bb.z, bb.w};
            #pragma unroll
            for (int m = 0; m < 2; m++){
                MMA_BF16(acc[m][t], AH[m], BH);
                MMA_BF16(acc[m][t], AL[m], BH);
                MMA_BF16(acc[m][t], AH[m], BL);
            }
        }
    }
}

__global__ void __launch_bounds__(TPB, 2)
value_net_mma(const float* __restrict__ state,
              const float* __restrict__ b1a, const float* __restrict__ b1b,
              const float* __restrict__ b2a, const float* __restrict__ b2b,
              const float* __restrict__ wa1, const float* __restrict__ ba1,
              const float* __restrict__ ba2,
              const float* __restrict__ wa3, const float* __restrict__ ba3,
              const float* __restrict__ w3a, const float* __restrict__ b3a,
              const float* __restrict__ w3b, const float* __restrict__ b3b,
              const float* __restrict__ w3c, const float* __restrict__ b3c,
              float* __restrict__ out)
{
    extern __shared__ __align__(128) uint8_t sm[];
    float* F = (float*)(sm + OFF_F);
    const int tid  = threadIdx.x;
    const int lane = tid & 31;
    const int wid  = tid >> 5;
    const int mw   = wid & 1;          // M group (32 rows)
    const int nw   = wid >> 1;         // N group (0..3)
    const int g    = lane >> 2;
    const int tg   = lane & 3;
    const int R0   = mw * 32;
    const int rl   = lane & 15;        // stmatrix row lane

    const uint32_t sb = smem_u32(sm);
    const uint32_t BH_ = sb + OFF_BH, BL_ = sb + OFF_BL;
    const uint32_t MH_ = sb + OFF_MH, ML_ = sb + OFF_ML;
    uint8_t* pMH = sm + OFF_MH; uint8_t* pML = sm + OFF_ML;

    const uint4* B0 = (const uint4*)(g_wb + 0);
    const uint4* B1 = (const uint4*)(g_wb + 65536);
    const uint4* B2 = (const uint4*)(g_wb + 196608);
    const uint4* B3 = (const uint4*)(g_wb + 327680);
    const uint4* B4 = (const uint4*)(g_wb + 458752);
    const uint4* B5 = (const uint4*)(g_wb + 524288);

    // ---- stage x (64 rows x 64) + scalars ----
    {
        int row = tid >> 2, qd = tid & 3;
        const float* xr = state + (size_t)blockIdx.x*4096 + row*64 + qd*16;
        float xv[16];
        #pragma unroll
        for (int j = 0; j < 4; j++) ((float4*)xv)[j] = __ldg((const float4*)(xr + 4*j));
        #pragma unroll
        for (int j = 0; j < 8; j++){
            int nc = qd*16 + 2*j;
            swst(pMH, 256, row, nc, pack_hi(xv[2*j], xv[2*j+1]));
            swst(pML, 256, row, nc, pack_lo(xv[2*j], xv[2*j+1]));
        }
        if (qd == 3) F[F_VIS + row] = (xv[13] > 0.f) ? 1.f : 0.f;   // col 61
        if (tid == 0){
            #pragma unroll
            for (int i = 0; i < 9; i++) F[F_JOINT + i] = xv[i];
        }
        F[F_B1A + tid] = __ldg(&b1a[tid]);
        F[F_B2A + tid] = __ldg(&b2a[tid]);
        if (tid < 128){ F[F_B1B + tid] = __ldg(&b1b[tid]); F[F_B2B + tid] = __ldg(&b2b[tid]); }
        if (tid < 64){  F[F_BA2 + tid] = __ldg(&ba2[tid]); F[F_WA3 + tid] = __ldg(&wa3[tid]); }
    }
    __syncthreads();

    // ============ L0: h1 = relu(x @ w1a + b1a)  K=64 N=256 ============
    {
        float acc[2][8][4];
        gemm<4,8>(MH_, ML_, 256, B0, mw, nw, lane, acc, &F[F_B1A]);
        #pragma unroll
        for (int m = 0; m < 2; m++){
            int rowm = R0 + m*16 + rl;
            uint32_t bH = BH_ + (uint32_t)rowm*512, bL = BL_ + (uint32_t)rowm*512;
            uint32_t swr = (uint32_t)(rowm & 7);
            #pragma unroll
            for (int t = 0; t < 8; t++){
                uint32_t off = (((uint32_t)(nw*8 + t) ^ swr) << 4);
                float v0 = fmaxf(acc[m][t][0], 0.f);
                float v1 = fmaxf(acc[m][t][1], 0.f);
                float v2 = fmaxf(acc[m][t][2], 0.f);
                float v3 = fmaxf(acc[m][t][3], 0.f);
                STSM2(bH + off, pack_hi(v0, v1), pack_hi(v2, v3));
                STSM2(bL + off, pack_lo(v0, v1), pack_lo(v2, v3));
            }
        }
    }
    __syncthreads();

    // ============ L1: m1 = relu(h1 @ w1b + b1b)  K=256 N=128 ============
    {
        float acc[2][4][4];
        gemm<16,4>(BH_, BL_, 512, B1, mw, nw, lane, acc, &F[F_B1B]);
        float visA[2], visB[2];
        #pragma unroll
        for (int m = 0; m < 2; m++){
            visA[m] = F[F_VIS + R0 + m*16 + g];
            visB[m] = F[F_VIS + R0 + m*16 + g + 8];
        }
        #pragma unroll
        for (int m = 0; m < 2; m++){
            int rowm = R0 + m*16 + rl;
            uint32_t bH = MH_ + (uint32_t)rowm*256, bL = ML_ + (uint32_t)rowm*256;
            uint32_t swr = (uint32_t)(rowm & 7);
            #pragma unroll
            for (int t = 0; t < 4; t++){
                float v0 = fmaxf(acc[m][t][0], 0.f);
                float v1 = fmaxf(acc[m][t][1], 0.f);
                float v2 = fmaxf(acc[m][t][2], 0.f);
                float v3 = fmaxf(acc[m][t][3], 0.f);
                uint32_t off = (((uint32_t)(nw*4 + t) ^ swr) << 4);
                STSM2(bH + off, pack_hi(v0, v1), pack_hi(v2, v3));   // UNMASKED m1
                STSM2(bL + off, pack_lo(v0, v1), pack_lo(v2, v3));
                // gs accumulation (masked)
                float g0 = v0*visA[m] + v2*visB[m];
                float g1 = v1*visA[m] + v3*visB[m];
                #pragma unroll
                for (int o = 4; o <= 16; o <<= 1){
                    g0 += __shfl_xor_sync(0xffffffffu, g0, o);
                    g1 += __shfl_xor_sync(0xffffffffu, g1, o);
                }
                if (lane < 4){   // g==0, tg==lane
                    int c = nw*32 + t*8 + 2*tg;
                    if (m == 0){
                        F[F_GSP + mw*128 + c]     = g0;
                        F[F_GSP + mw*128 + c + 1] = g1;
                    } else {
                        F[F_GSP + mw*128 + c]     += g0;
                        F[F_GSP + mw*128 + c + 1] += g1;
                    }
                }
            }
        }
    }
    __syncthreads();
    // gsb[n] = ba1[n] + (1/64) * sum_j (gsp[0][j]+gsp[1][j]) * wa1[128+j][n]  (split-K x2)
    {
        int n = tid & 127, half = tid >> 7;
        const float* g0p = &F[F_GSP];
        const float* g1p = &F[F_GSP + 128];
        float a0 = 0.f, a1 = 0.f;
        int j0 = half*64;
        #pragma unroll 8
        for (int j = j0; j < j0 + 64; j += 2){
            a0 += (g0p[j]   + g1p[j]  ) * __ldg(&wa1[(128 + j)*128 + n]);
            a1 += (g0p[j+1] + g1p[j+1]) * __ldg(&wa1[(129 + j)*128 + n]);
        }
        F[F_SPART + tid] = a0 + a1;
    }
    __syncthreads();
    if (tid < 128){
        F[F_GSB + tid] = (F[F_SPART + tid] + F[F_SPART + 128 + tid]) * (1.f/64.f)
                       + __ldg(&ba1[tid]);
    }
    __syncthreads();

    // ============ L4: att1 = relu(vis*(m1 @ wa1a) + gsb)  K=128 N=128 ============
    {
        float acc[2][4][4];
        gemm<8,4>(MH_, ML_, 256, B4, mw, nw, lane, acc, nullptr);
        float visA[2], visB[2];
        #pragma unroll
        for (int m = 0; m < 2; m++){
            visA[m] = F[F_VIS + R0 + m*16 + g];
            visB[m] = F[F_VIS + R0 + m*16 + g + 8];
        }
        #pragma unroll
        for (int m = 0; m < 2; m++){
            int rowm = R0 + m*16 + rl;
            uint32_t bH = BH_ + (uint32_t)rowm*512, bL = BL_ + (uint32_t)rowm*512;
            uint32_t swr = (uint32_t)(rowm & 7);
            #pragma unroll
            for (int t = 0; t < 4; t++){
                int c = nw*32 + t*8 + 2*tg;
                float g0 = F[F_GSB + c], g1 = F[F_GSB + c + 1];
                float v0 = fmaxf(acc[m][t][0]*visA[m] + g0, 0.f);
                float v1 = fmaxf(acc[m][t][1]*visA[m] + g1, 0.f);
                float v2 = fmaxf(acc[m][t][2]*visB[m] + g0, 0.f);
                float v3 = fmaxf(acc[m][t][3]*visB[m] + g1, 0.f);
                uint32_t off = (((uint32_t)(nw*4 + t) ^ swr) << 4);
                STSM2(bH + off, pack_hi(v0, v1), pack_hi(v2, v3));
                STSM2(bL + off, pack_lo(v0, v1), pack_lo(v2, v3));
            }
        }
    }
    __syncthreads();

    // ============ L5: score partials  K=128 N=64 (ba2 folded) ============
    {
        float acc[2][2][4];
        gemm<8,2>(BH_, BL_, 512, B5, mw, nw, lane, acc, &F[F_BA2]);
        float pA[2] = {0,0}, pB[2] = {0,0};
        #pragma unroll
        for (int t = 0; t < 2; t++){
            int c = nw*16 + t*8 + 2*tg;
            float w0 = F[F_WA3 + c], w1 = F[F_WA3 + c + 1];
            #pragma unroll
            for (int m = 0; m < 2; m++){
                pA[m] += fmaxf(acc[m][t][0], 0.f)*w0 + fmaxf(acc[m][t][1], 0.f)*w1;
                pB[m] += fmaxf(acc[m][t][2], 0.f)*w0 + fmaxf(acc[m][t][3], 0.f)*w1;
            }
        }
        #pragma unroll
        for (int m = 0; m < 2; m++){
            #pragma unroll
            for (int o = 1; o <= 2; o <<= 1){
                pA[m] += __shfl_xor_sync(0xffffffffu, pA[m], o);
                pB[m] += __shfl_xor_sync(0xffffffffu, pB[m], o);
            }
        }
        if (tg == 0){
            #pragma unroll
            for (int m = 0; m < 2; m++){
                F[F_SPART + nw*64 + R0 + m*16 + g]     = pA[m];
                F[F_SPART + nw*64 + R0 + m*16 + g + 8] = pB[m];
            }
        }
    }
    __syncthreads();

    // ---- softmax + coefficients + joint init ----
    {
        float e = 0.f;
        if (tid < 64){
            float s = F[F_SPART + tid] + F[F_SPART + 64 + tid]
                    + F[F_SPART + 128 + tid] + F[F_SPART + 192 + tid] + __ldg(&ba3[0]);
            e = (s != 0.f) ? expf(s) : 0.f;
            float t1 = e;
            #pragma unroll
            for (int o = 16; o > 0; o >>= 1) t1 += __shfl_xor_sync(0xffffffffu, t1, o);
            if (lane == 0) F[F_RED + wid] = t1;
        }
        __syncthreads();
        if (tid < 64){
            float ssum = F[F_RED] + F[F_RED + 1];
            float coef = (e / ssum) * F[F_VIS + tid];
            F[F_COEF + tid] = coef;
            float t2 = coef;
            #pragma unroll
            for (int o = 16; o > 0; o >>= 1) t2 += __shfl_xor_sync(0xffffffffu, t2, o);
            if (lane == 0) F[F_RED + 4 + wid] = t2;
        }
        __syncthreads();
        if (tid < 128){
            float csum = F[F_RED + 4] + F[F_RED + 5];
            F[F_JOINT + 9 + tid] = csum * F[F_B2B + tid];
        }
    }
    __syncthreads();

    // ============ L2: h2 = relu(m1 @ w2a + b2a)  K=128 N=256 ============
    {
        float acc[2][8][4];
        gemm<8,8>(MH_, ML_, 256, B2, mw, nw, lane, acc, &F[F_B2A]);
        #pragma unroll
        for (int m = 0; m < 2; m++){
            int rowm = R0 + m*16 + rl;
            uint32_t bH = BH_ + (uint32_t)rowm*512, bL = BL_ + (uint32_t)rowm*512;
            uint32_t swr = (uint32_t)(rowm & 7);
            #pragma unroll
            for (int t = 0; t < 8; t++){
                uint32_t off = (((uint32_t)(nw*8 + t) ^ swr) << 4);
                float v0 = fmaxf(acc[m][t][0], 0.f);
                float v1 = fmaxf(acc[m][t][1], 0.f);
                float v2 = fmaxf(acc[m][t][2], 0.f);
                float v3 = fmaxf(acc[m][t][3], 0.f);
                STSM2(bH + off, pack_hi(v0, v1), pack_hi(v2, v3));
                STSM2(bL + off, pack_lo(v0, v1), pack_lo(v2, v3));
            }
        }
    }
    __syncthreads();

    // ============ L3: jp[mw] = coef . (h2 @ w2b)  K=256 N=128 ============
    {
        float acc[2][4][4];
        gemm<16,4>(BH_, BL_, 512, B3, mw, nw, lane, acc, nullptr);
        float cA[2], cB[2];
        #pragma unroll
        for (int m = 0; m < 2; m++){
            cA[m] = F[F_COEF + R0 + m*16 + g];
            cB[m] = F[F_COEF + R0 + m*16 + g + 8];
        }
        #pragma unroll
        for (int t = 0; t < 4; t++){
            int c = nw*32 + t*8 + 2*tg;
            float w0 = 0.f, w1 = 0.f;
            #pragma unroll
            for (int m = 0; m < 2; m++){
                w0 += cA[m]*acc[m][t][0] + cB[m]*acc[m][t][2];
                w1 += cA[m]*acc[m][t][1] + cB[m]*acc[m][t][3];
            }
            #pragma unroll
            for (int o = 4; o <= 16; o <<= 1){
                w0 += __shfl_xor_sync(0xffffffffu, w0, o);
                w1 += __shfl_xor_sync(0xffffffffu, w1, o);
            }
            if (lane < 4){
                F[F_JP + mw*128 + c]     = w0;
                F[F_JP + mw*128 + c + 1] = w1;
            }
        }
    }
    __syncthreads();
    if (tid < 128){
        F[F_JOINT + 9 + tid] += F[F_JP + tid] + F[F_JP + 128 + tid];
    }
    __syncthreads();

    // ============ final MLP: 137 -> 256 -> 128 -> 1 (fp32) ============
    {
        int n = tid;
        float a0 = __ldg(&b3a[n]), a1 = 0.f;
        const float* J = &F[F_JOINT];
        #pragma unroll 4
        for (int i = 0; i < 136; i += 2){
            a0 += J[i]   * __ldg(&w3a[i*256 + n]);
            a1 += J[i+1] * __ldg(&w3a[(i+1)*256 + n]);
        }
        a0 += J[136] * __ldg(&w3a[136*256 + n]);
        F[F_H3 + n] = fmaxf(a0 + a1, 0.f);
    }
    __syncthreads();
    {   // layer 2: 128 outputs, split-K x2 over 256 threads
        int n = tid & 127, half = tid >> 7;
        float a0 = half ? 0.f : __ldg(&b3b[n]);
        float a1 = 0.f;
        const float* H = &F[F_H3 + half*128];
        #pragma unroll 4
        for (int i = 0; i < 128; i += 2){
            a0 += H[i]   * __ldg(&w3b[(half*128 + i)*128 + n]);
            a1 += H[i+1] * __ldg(&w3b[(half*128 + i + 1)*128 + n]);
        }
        F[F_JP + tid] = a0 + a1;
    }
    __syncthreads();
    if (tid < 128){
        float p = fmaxf(F[F_JP + tid] + F[F_JP + 128 + tid], 0.f) * __ldg(&w3c[tid]);
        #pragma unroll
        for (int o = 16; o > 0; o >>= 1) p += __shfl_xor_sync(0xffffffffu, p, o);
        if (lane == 0) F[F_RED + wid] = p;
    }
    __syncthreads();
    if (tid == 0){
        out[blockIdx.x] = F[F_RED] + F[F_RED + 1] + F[F_RED + 2] + F[F_RED + 3]
                        + __ldg(&b3c[0]);
    }
}

extern "C" void kernel_launch(void* const* d_in, const int* in_sizes, int n_in,
                              void* d_out, int out_size)
{
    (void)in_sizes; (void)n_in; (void)out_size;
    const float* state = (const float*)d_in[0];
    const float* w1a = (const float*)d_in[1];  const float* b1a = (const float*)d_in[2];
    const float* w1b = (const float*)d_in[3];  const float* b1b = (const float*)d_in[4];
    const float* w2a = (const float*)d_in[5];  const float* b2a = (const float*)d_in[6];
    const float* w2b = (const float*)d_in[7];  const float* b2b = (const float*)d_in[8];
    const float* wa1 = (const float*)d_in[9];  const float* ba1 = (const float*)d_in[10];
    const float* wa2 = (const float*)d_in[11]; const float* ba2 = (const float*)d_in[12];
    const float* wa3 = (const float*)d_in[13]; const float* ba3 = (const float*)d_in[14];
    const float* w3a = (const float*)d_in[15]; const float* b3a = (const float*)d_in[16];
    const float* w3b = (const float*)d_in[17]; const float* b3b = (const float*)d_in[18];
    const float* w3c = (const float*)d_in[19]; const float* b3c = (const float*)d_in[20];
    float* out = (float*)d_out;

    prep_kernel<<<(34816 + 255)/256, 256>>>(w1a, w1b, w2a, w2b, wa1, wa2);

    cudaFuncSetAttribute(value_net_mma,
                         cudaFuncAttributeMaxDynamicSharedMemorySize, SMEM_BYTES);
    value_net_mma<<<4096, TPB, SMEM_BYTES>>>(
        state, b1a, b1b, b2a, b2b, wa1, ba1, ba2, wa3, ba3,
        w3a, b3a, w3b, b3b, w3c, b3c, out);
}

// round 11
// speedup vs baseline: 4.8273x; 1.2377x over previous
#include <cuda_runtime.h>
#include <cuda_fp16.h>
#include <cstdint>

#define TPB 256

// ===================== PTX wrappers =====================
__device__ __forceinline__ uint32_t smem_u32(const void* p){
    uint32_t a;
    asm("{ .reg .u64 t; cvta.to.shared.u64 t, %1; cvt.u32.u64 %0, t; }":"=r"(a):"l"(p));
    return a;
}
#define LDSM4(r, a) \
    asm volatile("ldmatrix.sync.aligned.m8n8.x4.shared.b16 {%0,%1,%2,%3}, [%4];" \
        :"=r"((r)[0]),"=r"((r)[1]),"=r"((r)[2]),"=r"((r)[3]):"r"(a))
#define STSM2(a, r0, r1) \
    asm volatile("stmatrix.sync.aligned.m8n8.x2.shared.b16 [%0], {%1,%2};" \
        :: "r"(a), "r"(r0), "r"(r1) : "memory")
#define MMA_F16(c, a, b) \
    asm volatile("mma.sync.aligned.m16n8k16.row.col.f32.f16.f16.f32 " \
        "{%0,%1,%2,%3},{%4,%5,%6,%7},{%8,%9},{%0,%1,%2,%3};" \
        :"+f"((c)[0]),"+f"((c)[1]),"+f"((c)[2]),"+f"((c)[3]) \
        :"r"((a)[0]),"r"((a)[1]),"r"((a)[2]),"r"((a)[3]),"r"((b)[0]),"r"((b)[1]))

// fp16 hi/lo split of a float pair: hi = fp16(v), lo = fp16(v - float(hi))
__device__ __forceinline__ void pack2(float v0, float v1, uint32_t& hi, uint32_t& lo){
    __half h0 = __float2half_rn(v0), h1 = __float2half_rn(v1);
    __half2 H; H.x = h0; H.y = h1;
    hi = *(uint32_t*)&H;
    __half2 L = __floats2half2_rn(v0 - __half2float(h0), v1 - __half2float(h1));
    lo = *(uint32_t*)&L;
}
__device__ __forceinline__ void swst(uint8_t* plane, int P, int r, int nc, uint32_t v){
    *(uint32_t*)(plane + r*P + ((((nc>>3) ^ (r&7)) << 4) | ((nc<<1) & 15))) = v;
}

// ===================== fragment-packed weights (fp16 hi only, 8B/lane) =====================
__device__ __align__(128) uint8_t g_wb[278528];

__global__ void prep_kernel(const float* __restrict__ w1a, const float* __restrict__ w1b,
                            const float* __restrict__ w2a, const float* __restrict__ w2b,
                            const float* __restrict__ wa1, const float* __restrict__ wa2)
{
    const float* W[6] = {w1a, w1b, w2a, w2b, wa1, wa2};
    const int   NN[6] = {256, 128, 256, 128, 128, 64};
    const int   KS[6] = {4, 16, 8, 16, 8, 8};
    const int   EO[7] = {0, 4096, 12288, 20480, 28672, 32768, 34816};
    const int   BO[6] = {0, 32768, 98304, 163840, 229376, 262144};
    int idx = blockIdx.x * blockDim.x + threadIdx.x;
    if (idx >= 34816) return;
    int l = 0;
    while (idx >= EO[l+1]) l++;
    int e = idx - EO[l];
    int lane = e & 31, qq = e >> 5;
    int s = qq % KS[l], T = qq / KS[l];
    int tg = lane & 3, g = lane >> 2;
    int n = T*8 + g;
    int k0 = s*16 + 2*tg;
    int N = NN[l];
    const float* Wl = W[l];
    __half2 H0 = __floats2half2_rn(Wl[(k0  )*N + n], Wl[(k0+1)*N + n]);
    __half2 H1 = __floats2half2_rn(Wl[(k0+8)*N + n], Wl[(k0+9)*N + n]);
    uint2 o;
    o.x = *(uint32_t*)&H0; o.y = *(uint32_t*)&H1;
    *(uint2*)(g_wb + BO[l] + (size_t)e*8) = o;
}

// ===================== smem layout (per CTA, ~105 KB) =====================
#define OFF_BH   0          // big act hi: 64 x 512B
#define OFF_BL   32768
#define OFF_MH   65536      // m1/x hi: 64 x 256B
#define OFF_ML   81920
#define OFF_F    98304
#define F_B1A   0
#define F_B1B   256
#define F_B2A   384
#define F_B2B   640
#define F_BA2   768
#define F_WA3   832
#define F_VIS   896
#define F_GSP   960       // [2][128]
#define F_SPART 1216      // [4][64] (also split-K scratch)
#define F_COEF  1472
#define F_GSB   1536      // [128]
#define F_JP    1664      // [2][128]
#define F_JOINT 1920      // [160]
#define F_RED   2080
#define F_H3    2096      // [256]
#define F_TOT   2352
#define SMEM_BYTES (OFF_F + F_TOT*4)   // 107712

// ========== GEMM: M=64, 8 warps 2(M)x4(N), warp tile 32 x NT*8, 2-term fp16 ==========
template<int KSTEPS, int NT>
__device__ __forceinline__ void gemm(uint32_t aH, uint32_t aL, int P,
                                     const uint2* __restrict__ Bf,
                                     int mw, int nw, int lane,
                                     float (&acc)[2][NT][4],
                                     const float* __restrict__ bias)
{
    const int tg2 = (lane & 3) * 2;
    #pragma unroll
    for (int t = 0; t < NT; t++){
        float b0 = 0.f, b1 = 0.f;
        if (bias){
            int c = nw*(NT*8) + t*8 + tg2;
            b0 = bias[c]; b1 = bias[c + 1];
        }
        #pragma unroll
        for (int m = 0; m < 2; m++){
            acc[m][t][0] = b0; acc[m][t][1] = b1;
            acc[m][t][2] = b0; acc[m][t][3] = b1;
        }
    }

    const uint32_t rowoff = (uint32_t)((mw*32 + (lane & 15)) * P);
    const uint32_t chi = (uint32_t)(lane >> 4);
    const uint32_t swr = (uint32_t)(lane & 7);
    const uint2* bp = Bf + (size_t)(nw*NT)*KSTEPS*32 + lane;

    #pragma unroll 2
    for (int s = 0; s < KSTEPS; s++){
        uint32_t co = (((2u*s + chi) ^ swr) << 4);
        uint32_t AH[2][4], AL[2][4];
        #pragma unroll
        for (int m = 0; m < 2; m++){
            LDSM4(AH[m], aH + rowoff + (uint32_t)(m*16*P) + co);
            LDSM4(AL[m], aL + rowoff + (uint32_t)(m*16*P) + co);
        }
        const uint2* bps = bp + (size_t)s*32;
        #pragma unroll
        for (int t = 0; t < NT; t++){
            uint2 bb = __ldg(bps + (size_t)t*KSTEPS*32);
            uint32_t BH[2] = {bb.x, bb.y};
            #pragma unroll
            for (int m = 0; m < 2; m++){
                MMA_F16(acc[m][t], AH[m], BH);
                MMA_F16(acc[m][t], AL[m], BH);
            }
        }
    }
}

__global__ void __launch_bounds__(TPB, 2)
value_net_mma(const float* __restrict__ state,
              const float* __restrict__ b1a, const float* __restrict__ b1b,
              const float* __restrict__ b2a, const float* __restrict__ b2b,
              const float* __restrict__ wa1, const float* __restrict__ ba1,
              const float* __restrict__ ba2,
              const float* __restrict__ wa3, const float* __restrict__ ba3,
              const float* __restrict__ w3a, const float* __restrict__ b3a,
              const float* __restrict__ w3b, const float* __restrict__ b3b,
              const float* __restrict__ w3c, const float* __restrict__ b3c,
              float* __restrict__ out)
{
    extern __shared__ __align__(128) uint8_t sm[];
    float* F = (float*)(sm + OFF_F);
    const int tid  = threadIdx.x;
    const int lane = tid & 31;
    const int wid  = tid >> 5;
    const int mw   = wid & 1;
    const int nw   = wid >> 1;
    const int g    = lane >> 2;
    const int tg   = lane & 3;
    const int R0   = mw * 32;
    const int rl   = lane & 15;

    const uint32_t sb = smem_u32(sm);
    const uint32_t BH_ = sb + OFF_BH, BL_ = sb + OFF_BL;
    const uint32_t MH_ = sb + OFF_MH, ML_ = sb + OFF_ML;
    uint8_t* pMH = sm + OFF_MH; uint8_t* pML = sm + OFF_ML;

    const uint2* B0 = (const uint2*)(g_wb + 0);
    const uint2* B1 = (const uint2*)(g_wb + 32768);
    const uint2* B2 = (const uint2*)(g_wb + 98304);
    const uint2* B3 = (const uint2*)(g_wb + 163840);
    const uint2* B4 = (const uint2*)(g_wb + 229376);
    const uint2* B5 = (const uint2*)(g_wb + 262144);

    // ---- stage x (64 rows x 64) + scalars ----
    {
        int row = tid >> 2, qd = tid & 3;
        const float* xr = state + (size_t)blockIdx.x*4096 + row*64 + qd*16;
        float xv[16];
        #pragma unroll
        for (int j = 0; j < 4; j++) ((float4*)xv)[j] = __ldg((const float4*)(xr + 4*j));
        #pragma unroll
        for (int j = 0; j < 8; j++){
            int nc = qd*16 + 2*j;
            uint32_t h, l;
            pack2(xv[2*j], xv[2*j+1], h, l);
            swst(pMH, 256, row, nc, h);
            swst(pML, 256, row, nc, l);
        }
        if (qd == 3) F[F_VIS + row] = (xv[13] > 0.f) ? 1.f : 0.f;   // col 61
        if (tid == 0){
            #pragma unroll
            for (int i = 0; i < 9; i++) F[F_JOINT + i] = xv[i];
        }
        F[F_B1A + tid] = __ldg(&b1a[tid]);
        F[F_B2A + tid] = __ldg(&b2a[tid]);
        if (tid < 128){ F[F_B1B + tid] = __ldg(&b1b[tid]); F[F_B2B + tid] = __ldg(&b2b[tid]); }
        if (tid < 64){  F[F_BA2 + tid] = __ldg(&ba2[tid]); F[F_WA3 + tid] = __ldg(&wa3[tid]); }
    }
    __syncthreads();

    // ============ L0: h1 = relu(x @ w1a + b1a)  K=64 N=256 ============
    {
        float acc[2][8][4];
        gemm<4,8>(MH_, ML_, 256, B0, mw, nw, lane, acc, &F[F_B1A]);
        #pragma unroll
        for (int m = 0; m < 2; m++){
            int rowm = R0 + m*16 + rl;
            uint32_t bH = BH_ + (uint32_t)rowm*512, bL = BL_ + (uint32_t)rowm*512;
            uint32_t swr = (uint32_t)(rowm & 7);
            #pragma unroll
            for (int t = 0; t < 8; t++){
                uint32_t off = (((uint32_t)(nw*8 + t) ^ swr) << 4);
                float v0 = fmaxf(acc[m][t][0], 0.f);
                float v1 = fmaxf(acc[m][t][1], 0.f);
                float v2 = fmaxf(acc[m][t][2], 0.f);
                float v3 = fmaxf(acc[m][t][3], 0.f);
                uint32_t h01, l01, h23, l23;
                pack2(v0, v1, h01, l01);
                pack2(v2, v3, h23, l23);
                STSM2(bH + off, h01, h23);
                STSM2(bL + off, l01, l23);
            }
        }
    }
    __syncthreads();

    // ============ L1: m1 = relu(h1 @ w1b + b1b)  K=256 N=128 ============
    {
        float acc[2][4][4];
        gemm<16,4>(BH_, BL_, 512, B1, mw, nw, lane, acc, &F[F_B1B]);
        float visA[2], visB[2];
        #pragma unroll
        for (int m = 0; m < 2; m++){
            visA[m] = F[F_VIS + R0 + m*16 + g];
            visB[m] = F[F_VIS + R0 + m*16 + g + 8];
        }
        #pragma unroll
        for (int m = 0; m < 2; m++){
            int rowm = R0 + m*16 + rl;
            uint32_t bH = MH_ + (uint32_t)rowm*256, bL = ML_ + (uint32_t)rowm*256;
            uint32_t swr = (uint32_t)(rowm & 7);
            #pragma unroll
            for (int t = 0; t < 4; t++){
                float v0 = fmaxf(acc[m][t][0], 0.f);
                float v1 = fmaxf(acc[m][t][1], 0.f);
                float v2 = fmaxf(acc[m][t][2], 0.f);
                float v3 = fmaxf(acc[m][t][3], 0.f);
                uint32_t off = (((uint32_t)(nw*4 + t) ^ swr) << 4);
                uint32_t h01, l01, h23, l23;
                pack2(v0, v1, h01, l01);
                pack2(v2, v3, h23, l23);
                STSM2(bH + off, h01, h23);   // UNMASKED m1
                STSM2(bL + off, l01, l23);
                float g0 = v0*visA[m] + v2*visB[m];
                float g1 = v1*visA[m] + v3*visB[m];
                #pragma unroll
                for (int o = 4; o <= 16; o <<= 1){
                    g0 += __shfl_xor_sync(0xffffffffu, g0, o);
                    g1 += __shfl_xor_sync(0xffffffffu, g1, o);
                }
                if (lane < 4){
                    int c = nw*32 + t*8 + 2*tg;
                    if (m == 0){
                        F[F_GSP + mw*128 + c]     = g0;
                        F[F_GSP + mw*128 + c + 1] = g1;
                    } else {
                        F[F_GSP + mw*128 + c]     += g0;
                        F[F_GSP + mw*128 + c + 1] += g1;
                    }
                }
            }
        }
    }
    __syncthreads();
    // gsb[n] = ba1[n] + (1/64) * sum_j (gsp[0][j]+gsp[1][j]) * wa1[128+j][n]  (split-K x2)
    {
        int n = tid & 127, half = tid >> 7;
        const float* g0p = &F[F_GSP];
        const float* g1p = &F[F_GSP + 128];
        float a0 = 0.f, a1 = 0.f;
        int j0 = half*64;
        #pragma unroll 8
        for (int j = j0; j < j0 + 64; j += 2){
            a0 += (g0p[j]   + g1p[j]  ) * __ldg(&wa1[(128 + j)*128 + n]);
            a1 += (g0p[j+1] + g1p[j+1]) * __ldg(&wa1[(129 + j)*128 + n]);
        }
        F[F_SPART + tid] = a0 + a1;
    }
    __syncthreads();
    if (tid < 128){
        F[F_GSB + tid] = (F[F_SPART + tid] + F[F_SPART + 128 + tid]) * (1.f/64.f)
                       + __ldg(&ba1[tid]);
    }
    __syncthreads();

    // ============ L4: att1 = relu(vis*(m1 @ wa1a) + gsb)  K=128 N=128 ============
    {
        float acc[2][4][4];
        gemm<8,4>(MH_, ML_, 256, B4, mw, nw, lane, acc, nullptr);
        float visA[2], visB[2];
        #pragma unroll
        for (int m = 0; m < 2; m++){
            visA[m] = F[F_VIS + R0 + m*16 + g];
            visB[m] = F[F_VIS + R0 + m*16 + g + 8];
        }
        #pragma unroll
        for (int m = 0; m < 2; m++){
            int rowm = R0 + m*16 + rl;
            uint32_t bH = BH_ + (uint32_t)rowm*512, bL = BL_ + (uint32_t)rowm*512;
            uint32_t swr = (uint32_t)(rowm & 7);
            #pragma unroll
            for (int t = 0; t < 4; t++){
                int c = nw*32 + t*8 + 2*tg;
                float g0 = F[F_GSB + c], g1 = F[F_GSB + c + 1];
                float v0 = fmaxf(acc[m][t][0]*visA[m] + g0, 0.f);
                float v1 = fmaxf(acc[m][t][1]*visA[m] + g1, 0.f);
                float v2 = fmaxf(acc[m][t][2]*visB[m] + g0, 0.f);
                float v3 = fmaxf(acc[m][t][3]*visB[m] + g1, 0.f);
                uint32_t off = (((uint32_t)(nw*4 + t) ^ swr) << 4);
                uint32_t h01, l01, h23, l23;
                pack2(v0, v1, h01, l01);
                pack2(v2, v3, h23, l23);
                STSM2(bH + off, h01, h23);
                STSM2(bL + off, l01, l23);
            }
        }
    }
    __syncthreads();

    // ============ L5: score partials  K=128 N=64 (ba2 folded) ============
    {
        float acc[2][2][4];
        gemm<8,2>(BH_, BL_, 512, B5, mw, nw, lane, acc, &F[F_BA2]);
        float pA[2] = {0,0}, pB[2] = {0,0};
        #pragma unroll
        for (int t = 0; t < 2; t++){
            int c = nw*16 + t*8 + 2*tg;
            float w0 = F[F_WA3 + c], w1 = F[F_WA3 + c + 1];
            #pragma unroll
            for (int m = 0; m < 2; m++){
                pA[m] += fmaxf(acc[m][t][0], 0.f)*w0 + fmaxf(acc[m][t][1], 0.f)*w1;
                pB[m] += fmaxf(acc[m][t][2], 0.f)*w0 + fmaxf(acc[m][t][3], 0.f)*w1;
            }
        }
        #pragma unroll
        for (int m = 0; m < 2; m++){
            #pragma unroll
            for (int o = 1; o <= 2; o <<= 1){
                pA[m] += __shfl_xor_sync(0xffffffffu, pA[m], o);
                pB[m] += __shfl_xor_sync(0xffffffffu, pB[m], o);
            }
        }
        if (tg == 0){
            #pragma unroll
            for (int m = 0; m < 2; m++){
                F[F_SPART + nw*64 + R0 + m*16 + g]     = pA[m];
                F[F_SPART + nw*64 + R0 + m*16 + g + 8] = pB[m];
            }
        }
    }
    __syncthreads();

    // ---- softmax + coefficients + joint init ----
    {
        float e = 0.f;
        if (tid < 64){
            float s = F[F_SPART + tid] + F[F_SPART + 64 + tid]
                    + F[F_SPART + 128 + tid] + F[F_SPART + 192 + tid] + __ldg(&ba3[0]);
            e = (s != 0.f) ? expf(s) : 0.f;
            float t1 = e;
            #pragma unroll
            for (int o = 16; o > 0; o >>= 1) t1 += __shfl_xor_sync(0xffffffffu, t1, o);
            if (lane == 0) F[F_RED + wid] = t1;
        }
        __syncthreads();
        if (tid < 64){
            float ssum = F[F_RED] + F[F_RED + 1];
            float coef = (e / ssum) * F[F_VIS + tid];
            F[F_COEF + tid] = coef;
            float t2 = coef;
            #pragma unroll
            for (int o = 16; o > 0; o >>= 1) t2 += __shfl_xor_sync(0xffffffffu, t2, o);
            if (lane == 0) F[F_RED + 4 + wid] = t2;
        }
        __syncthreads();
        if (tid < 128){
            float csum = F[F_RED + 4] + F[F_RED + 5];
            F[F_JOINT + 9 + tid] = csum * F[F_B2B + tid];
        }
    }
    __syncthreads();

    // ============ L2: h2 = relu(m1 @ w2a + b2a)  K=128 N=256 ============
    {
        float acc[2][8][4];
        gemm<8,8>(MH_, ML_, 256, B2, mw, nw, lane, acc, &F[F_B2A]);
        #pragma unroll
        for (int m = 0; m < 2; m++){
            int rowm = R0 + m*16 + rl;
            uint32_t bH = BH_ + (uint32_t)rowm*512, bL = BL_ + (uint32_t)rowm*512;
            uint32_t swr = (uint32_t)(rowm & 7);
            #pragma unroll
            for (int t = 0; t < 8; t++){
                uint32_t off = (((uint32_t)(nw*8 + t) ^ swr) << 4);
                float v0 = fmaxf(acc[m][t][0], 0.f);
                float v1 = fmaxf(acc[m][t][1], 0.f);
                float v2 = fmaxf(acc[m][t][2], 0.f);
                float v3 = fmaxf(acc[m][t][3], 0.f);
                uint32_t h01, l01, h23, l23;
                pack2(v0, v1, h01, l01);
                pack2(v2, v3, h23, l23);
                STSM2(bH + off, h01, h23);
                STSM2(bL + off, l01, l23);
            }
        }
    }
    __syncthreads();

    // ============ L3: jp[mw] = coef . (h2 @ w2b)  K=256 N=128 ============
    {
        float acc[2][4][4];
        gemm<16,4>(BH_, BL_, 512, B3, mw, nw, lane, acc, nullptr);
        float cA[2], cB[2];
        #pragma unroll
        for (int m = 0; m < 2; m++){
            cA[m] = F[F_COEF + R0 + m*16 + g];
            cB[m] = F[F_COEF + R0 + m*16 + g + 8];
        }
        #pragma unroll
        for (int t = 0; t < 4; t++){
            int c = nw*32 + t*8 + 2*tg;
            float w0 = 0.f, w1 = 0.f;
            #pragma unroll
            for (int m = 0; m < 2; m++){
                w0 += cA[m]*acc[m][t][0] + cB[m]*acc[m][t][2];
                w1 += cA[m]*acc[m][t][1] + cB[m]*acc[m][t][3];
            }
            #pragma unroll
            for (int o = 4; o <= 16; o <<= 1){
                w0 += __shfl_xor_sync(0xffffffffu, w0, o);
                w1 += __shfl_xor_sync(0xffffffffu, w1, o);
            }
            if (lane < 4){
                F[F_JP + mw*128 + c]     = w0;
                F[F_JP + mw*128 + c + 1] = w1;
            }
        }
    }
    __syncthreads();
    if (tid < 128){
        F[F_JOINT + 9 + tid] += F[F_JP + tid] + F[F_JP + 128 + tid];
    }
    __syncthreads();

    // ============ final MLP: 137 -> 256 -> 128 -> 1 (fp32) ============
    {
        int n = tid;
        float a0 = __ldg(&b3a[n]), a1 = 0.f;
        const float* J = &F[F_JOINT];
        #pragma unroll 4
        for (int i = 0; i < 136; i += 2){
            a0 += J[i]   * __ldg(&w3a[i*256 + n]);
            a1 += J[i+1] * __ldg(&w3a[(i+1)*256 + n]);
        }
        a0 += J[136] * __ldg(&w3a[136*256 + n]);
        F[F_H3 + n] = fmaxf(a0 + a1, 0.f);
    }
    __syncthreads();
    {   // layer 2: 128 outputs, split-K x2 over 256 threads
        int n = tid & 127, half = tid >> 7;
        float a0 = half ? 0.f : __ldg(&b3b[n]);
        float a1 = 0.f;
        const float* H = &F[F_H3 + half*128];
        #pragma unroll 4
        for (int i = 0; i < 128; i += 2){
            a0 += H[i]   * __ldg(&w3b[(half*128 + i)*128 + n]);
            a1 += H[i+1] * __ldg(&w3b[(half*128 + i + 1)*128 + n]);
        }
        F[F_JP + tid] = a0 + a1;
    }
    __syncthreads();
    if (tid < 128){
        float p = fmaxf(F[F_JP + tid] + F[F_JP + 128 + tid], 0.f) * __ldg(&w3c[tid]);
        #pragma unroll
        for (int o = 16; o > 0; o >>= 1) p += __shfl_xor_sync(0xffffffffu, p, o);
        if (lane == 0) F[F_RED + wid] = p;
    }
    __syncthreads();
    if (tid == 0){
        out[blockIdx.x] = F[F_RED] + F[F_RED + 1] + F[F_RED + 2] + F[F_RED + 3]
                        + __ldg(&b3c[0]);
    }
}

extern "C" void kernel_launch(void* const* d_in, const int* in_sizes, int n_in,
                              void* d_out, int out_size)
{
    (void)in_sizes; (void)n_in; (void)out_size;
    const float* state = (const float*)d_in[0];
    const float* w1a = (const float*)d_in[1];  const float* b1a = (const float*)d_in[2];
    const float* w1b = (const float*)d_in[3];  const float* b1b = (const float*)d_in[4];
    const float* w2a = (const float*)d_in[5];  const float* b2a = (const float*)d_in[6];
    const float* w2b = (const float*)d_in[7];  const float* b2b = (const float*)d_in[8];
    const float* wa1 = (const float*)d_in[9];  const float* ba1 = (const float*)d_in[10];
    const float* wa2 = (const float*)d_in[11]; const float* ba2 = (const float*)d_in[12];
    const float* wa3 = (const float*)d_in[13]; const float* ba3 = (const float*)d_in[14];
    const float* w3a = (const float*)d_in[15]; const float* b3a = (const float*)d_in[16];
    const float* w3b = (const float*)d_in[17]; const float* b3b = (const float*)d_in[18];
    const float* w3c = (const float*)d_in[19]; const float* b3c = (const float*)d_in[20];
    float* out = (float*)d_out;

    prep_kernel<<<(34816 + 255)/256, 256>>>(w1a, w1b, w2a, w2b, wa1, wa2);

    cudaFuncSetAttribute(value_net_mma,
                         cudaFuncAttributeMaxDynamicSharedMemorySize, SMEM_BYTES);
    value_net_mma<<<4096, TPB, SMEM_BYTES>>>(
        state, b1a, b1b, b2a, b2b, wa1, ba1, ba2, wa3, ba3,
        w3a, b3a, w3b, b3b, w3c, b3c, out);
}

// round 13
// speedup vs baseline: 6.6447x; 1.3765x over previous
#include <cuda_runtime.h>
#include <cuda_fp16.h>
#include <cstdint>

#define TPB 256

// ===================== PTX wrappers =====================
__device__ __forceinline__ uint32_t smem_u32(const void* p){
    uint32_t a;
    asm("{ .reg .u64 t; cvta.to.shared.u64 t, %1; cvt.u32.u64 %0, t; }":"=r"(a):"l"(p));
    return a;
}
#define LDSM4(r, a) \
    asm volatile("ldmatrix.sync.aligned.m8n8.x4.shared.b16 {%0,%1,%2,%3}, [%4];" \
        :"=r"((r)[0]),"=r"((r)[1]),"=r"((r)[2]),"=r"((r)[3]):"r"(a))
#define STSM2(a, r0, r1) \
    asm volatile("stmatrix.sync.aligned.m8n8.x2.shared.b16 [%0], {%1,%2};" \
        :: "r"(a), "r"(r0), "r"(r1) : "memory")
#define MMA_F16(c, a, b) \
    asm volatile("mma.sync.aligned.m16n8k16.row.col.f32.f16.f16.f32 " \
        "{%0,%1,%2,%3},{%4,%5,%6,%7},{%8,%9},{%0,%1,%2,%3};" \
        :"+f"((c)[0]),"+f"((c)[1]),"+f"((c)[2]),"+f"((c)[3]) \
        :"r"((a)[0]),"r"((a)[1]),"r"((a)[2]),"r"((a)[3]),"r"((b)[0]),"r"((b)[1]))

__device__ __forceinline__ uint32_t packh(float v0, float v1){
    __half2 H = __floats2half2_rn(v0, v1);
    return *(uint32_t*)&H;
}
__device__ __forceinline__ void swst(uint8_t* plane, int P, int r, int nc, uint32_t v){
    *(uint32_t*)(plane + r*P + ((((nc>>3) ^ (r&7)) << 4) | ((nc<<1) & 15))) = v;
}

// ===================== fragment-packed weights (fp16, 8B/lane) =====================
__device__ __align__(128) uint8_t g_wb[278528];

__global__ void prep_kernel(const float* __restrict__ w1a, const float* __restrict__ w1b,
                            const float* __restrict__ w2a, const float* __restrict__ w2b,
                            const float* __restrict__ wa1, const float* __restrict__ wa2)
{
    const float* W[6] = {w1a, w1b, w2a, w2b, wa1, wa2};
    const int   NN[6] = {256, 128, 256, 128, 128, 64};
    const int   KS[6] = {4, 16, 8, 16, 8, 8};
    const int   EO[7] = {0, 4096, 12288, 20480, 28672, 32768, 34816};
    const int   BO[6] = {0, 32768, 98304, 163840, 229376, 262144};
    int idx = blockIdx.x * blockDim.x + threadIdx.x;
    if (idx >= 34816) return;
    int l = 0;
    while (idx >= EO[l+1]) l++;
    int e = idx - EO[l];
    int lane = e & 31, qq = e >> 5;
    int s = qq % KS[l], T = qq / KS[l];
    int tg = lane & 3, g = lane >> 2;
    int n = T*8 + g;
    int k0 = s*16 + 2*tg;
    int N = NN[l];
    const float* Wl = W[l];
    __half2 H0 = __floats2half2_rn(Wl[(k0  )*N + n], Wl[(k0+1)*N + n]);
    __half2 H1 = __floats2half2_rn(Wl[(k0+8)*N + n], Wl[(k0+9)*N + n]);
    uint2 o;
    o.x = *(uint32_t*)&H0; o.y = *(uint32_t*)&H1;
    *(uint2*)(g_wb + BO[l] + (size_t)e*8) = o;
}

// ===================== smem layout (per CTA, ~57 KB) =====================
#define OFF_BH   0          // big act: 64 x 512B
#define OFF_MH   32768      // m1/x act: 64 x 256B
#define OFF_F    49152
#define F_B1A   0
#define F_B1B   256
#define F_B2A   384
#define F_B2B   640
#define F_BA2   768
#define F_WA3   832
#define F_VIS   896
#define F_GSP   960       // [2][128]
#define F_SPART 1216      // [4][64] (also split-K scratch)
#define F_COEF  1472
#define F_GSB   1536      // [128]
#define F_JP    1664      // [2][128]
#define F_JOINT 1920      // [160]
#define F_RED   2080
#define F_H3    2096      // [256]
#define F_TOT   2352
#define SMEM_BYTES (OFF_F + F_TOT*4)   // 58560

// ========== GEMM: M=64, 8 warps 2(M)x4(N), warp tile 32 x NT*8, fp16 ==========
template<int KSTEPS, int NT>
__device__ __forceinline__ void gemm(uint32_t aH, int P,
                                     const uint2* __restrict__ Bf,
                                     int mw, int nw, int lane,
                                     float (&acc)[2][NT][4],
                                     const float* __restrict__ bias)
{
    const int tg2 = (lane & 3) * 2;
    #pragma unroll
    for (int t = 0; t < NT; t++){
        float b0 = 0.f, b1 = 0.f;
        if (bias){
            int c = nw*(NT*8) + t*8 + tg2;
            b0 = bias[c]; b1 = bias[c + 1];
        }
        #pragma unroll
        for (int m = 0; m < 2; m++){
            acc[m][t][0] = b0; acc[m][t][1] = b1;
            acc[m][t][2] = b0; acc[m][t][3] = b1;
        }
    }

    const uint32_t rowoff = (uint32_t)((mw*32 + (lane & 15)) * P);
    const uint32_t chi = (uint32_t)(lane >> 4);
    const uint32_t swr = (uint32_t)(lane & 7);
    const uint2* bp = Bf + (size_t)(nw*NT)*KSTEPS*32 + lane;

    #pragma unroll 2
    for (int s = 0; s < KSTEPS; s++){
        uint32_t co = (((2u*s + chi) ^ swr) << 4);
        uint32_t AH[2][4];
        #pragma unroll
        for (int m = 0; m < 2; m++)
            LDSM4(AH[m], aH + rowoff + (uint32_t)(m*16*P) + co);
        const uint2* bps = bp + (size_t)s*32;
        #pragma unroll
        for (int t = 0; t < NT; t++){
            uint2 bb = __ldg(bps + (size_t)t*KSTEPS*32);
            uint32_t BH[2] = {bb.x, bb.y};
            #pragma unroll
            for (int m = 0; m < 2; m++)
                MMA_F16(acc[m][t], AH[m], BH);
        }
    }
}

__global__ void __launch_bounds__(TPB, 2)
value_net_mma(const float* __restrict__ state,
              const float* __restrict__ b1a, const float* __restrict__ b1b,
              const float* __restrict__ b2a, const float* __restrict__ b2b,
              const float* __restrict__ wa1, const float* __restrict__ ba1,
              const float* __restrict__ ba2,
              const float* __restrict__ wa3, const float* __restrict__ ba3,
              const float* __restrict__ w3a, const float* __restrict__ b3a,
              const float* __restrict__ w3b, const float* __restrict__ b3b,
              const float* __restrict__ w3c, const float* __restrict__ b3c,
              float* __restrict__ out)
{
    extern __shared__ __align__(128) uint8_t sm[];
    float* F = (float*)(sm + OFF_F);
    const int tid  = threadIdx.x;
    const int lane = tid & 31;
    const int wid  = tid >> 5;
    const int mw   = wid & 1;
    const int nw   = wid >> 1;
    const int g    = lane >> 2;
    const int tg   = lane & 3;
    const int R0   = mw * 32;
    const int rl   = lane & 15;

    const uint32_t sb = smem_u32(sm);
    const uint32_t BH_ = sb + OFF_BH;
    const uint32_t MH_ = sb + OFF_MH;
    uint8_t* pMH = sm + OFF_MH;

    const uint2* B0 = (const uint2*)(g_wb + 0);
    const uint2* B1 = (const uint2*)(g_wb + 32768);
    const uint2* B2 = (const uint2*)(g_wb + 98304);
    const uint2* B3 = (const uint2*)(g_wb + 163840);
    const uint2* B4 = (const uint2*)(g_wb + 229376);
    const uint2* B5 = (const uint2*)(g_wb + 262144);

    // ---- stage x (64 rows x 64) + scalars ----
    {
        int row = tid >> 2, qd = tid & 3;
        const float* xr = state + (size_t)blockIdx.x*4096 + row*64 + qd*16;
        float xv[16];
        #pragma unroll
        for (int j = 0; j < 4; j++) ((float4*)xv)[j] = __ldg((const float4*)(xr + 4*j));
        #pragma unroll
        for (int j = 0; j < 8; j++){
            int nc = qd*16 + 2*j;
            swst(pMH, 256, row, nc, packh(xv[2*j], xv[2*j+1]));
        }
        if (qd == 3) F[F_VIS + row] = (xv[13] > 0.f) ? 1.f : 0.f;   // col 61
        if (tid == 0){
            #pragma unroll
            for (int i = 0; i < 9; i++) F[F_JOINT + i] = xv[i];
        }
        F[F_B1A + tid] = __ldg(&b1a[tid]);
        F[F_B2A + tid] = __ldg(&b2a[tid]);
        if (tid < 128){ F[F_B1B + tid] = __ldg(&b1b[tid]); F[F_B2B + tid] = __ldg(&b2b[tid]); }
        if (tid < 64){  F[F_BA2 + tid] = __ldg(&ba2[tid]); F[F_WA3 + tid] = __ldg(&wa3[tid]); }
    }
    __syncthreads();

    // ============ L0: h1 = relu(x @ w1a + b1a)  K=64 N=256 ============
    {
        float acc[2][8][4];
        gemm<4,8>(MH_, 256, B0, mw, nw, lane, acc, &F[F_B1A]);
        #pragma unroll
        for (int m = 0; m < 2; m++){
            int rowm = R0 + m*16 + rl;
            uint32_t bH = BH_ + (uint32_t)rowm*512;
            uint32_t swr = (uint32_t)(rowm & 7);
            #pragma unroll
            for (int t = 0; t < 8; t++){
                uint32_t off = (((uint32_t)(nw*8 + t) ^ swr) << 4);
                float v0 = fmaxf(acc[m][t][0], 0.f);
                float v1 = fmaxf(acc[m][t][1], 0.f);
                float v2 = fmaxf(acc[m][t][2], 0.f);
                float v3 = fmaxf(acc[m][t][3], 0.f);
                STSM2(bH + off, packh(v0, v1), packh(v2, v3));
            }
        }
    }
    __syncthreads();

    // ============ L1: m1 = relu(h1 @ w1b + b1b)  K=256 N=128 ============
    {
        float acc[2][4][4];
        gemm<16,4>(BH_, 512, B1, mw, nw, lane, acc, &F[F_B1B]);
        float visA[2], visB[2];
        #pragma unroll
        for (int m = 0; m < 2; m++){
            visA[m] = F[F_VIS + R0 + m*16 + g];
            visB[m] = F[F_VIS + R0 + m*16 + g + 8];
        }
        #pragma unroll
        for (int m = 0; m < 2; m++){
            int rowm = R0 + m*16 + rl;
            uint32_t bH = MH_ + (uint32_t)rowm*256;
            uint32_t swr = (uint32_t)(rowm & 7);
            #pragma unroll
            for (int t = 0; t < 4; t++){
                float v0 = fmaxf(acc[m][t][0], 0.f);
                float v1 = fmaxf(acc[m][t][1], 0.f);
                float v2 = fmaxf(acc[m][t][2], 0.f);
                float v3 = fmaxf(acc[m][t][3], 0.f);
                uint32_t off = (((uint32_t)(nw*4 + t) ^ swr) << 4);
                STSM2(bH + off, packh(v0, v1), packh(v2, v3));   // UNMASKED m1
                float g0 = v0*visA[m] + v2*visB[m];
                float g1 = v1*visA[m] + v3*visB[m];
                #pragma unroll
                for (int o = 4; o <= 16; o <<= 1){
                    g0 += __shfl_xor_sync(0xffffffffu, g0, o);
                    g1 += __shfl_xor_sync(0xffffffffu, g1, o);
                }
                if (lane < 4){
                    int c = nw*32 + t*8 + 2*tg;
                    if (m == 0){
                        F[F_GSP + mw*128 + c]     = g0;
                        F[F_GSP + mw*128 + c + 1] = g1;
                    } else {
                        F[F_GSP + mw*128 + c]     += g0;
                        F[F_GSP + mw*128 + c + 1] += g1;
                    }
                }
            }
        }
    }
    __syncthreads();
    // gsb[n] = ba1[n] + (1/64) * sum_j (gsp[0][j]+gsp[1][j]) * wa1[128+j][n]  (split-K x2)
    {
        int n = tid & 127, half = tid >> 7;
        const float* g0p = &F[F_GSP];
        const float* g1p = &F[F_GSP + 128];
        float a0 = 0.f, a1 = 0.f;
        int j0 = half*64;
        #pragma unroll 8
        for (int j = j0; j < j0 + 64; j += 2){
            a0 += (g0p[j]   + g1p[j]  ) * __ldg(&wa1[(128 + j)*128 + n]);
            a1 += (g0p[j+1] + g1p[j+1]) * __ldg(&wa1[(129 + j)*128 + n]);
        }
        F[F_SPART + tid] = a0 + a1;
    }
    __syncthreads();
    if (tid < 128){
        F[F_GSB + tid] = (F[F_SPART + tid] + F[F_SPART + 128 + tid]) * (1.f/64.f)
                       + __ldg(&ba1[tid]);
    }
    __syncthreads();

    // ============ L4: att1 = relu(vis*(m1 @ wa1a) + gsb)  K=128 N=128 ============
    {
        float acc[2][4][4];
        gemm<8,4>(MH_, 256, B4, mw, nw, lane, acc, nullptr);
        float visA[2], visB[2];
        #pragma unroll
        for (int m = 0; m < 2; m++){
            visA[m] = F[F_VIS + R0 + m*16 + g];
            visB[m] = F[F_VIS + R0 + m*16 + g + 8];
        }
        #pragma unroll
        for (int m = 0; m < 2; m++){
            int rowm = R0 + m*16 + rl;
            uint32_t bH = BH_ + (uint32_t)rowm*512;
            uint32_t swr = (uint32_t)(rowm & 7);
            #pragma unroll
            for (int t = 0; t < 4; t++){
                int c = nw*32 + t*8 + 2*tg;
                float g0 = F[F_GSB + c], g1 = F[F_GSB + c + 1];
                float v0 = fmaxf(acc[m][t][0]*visA[m] + g0, 0.f);
                float v1 = fmaxf(acc[m][t][1]*visA[m] + g1, 0.f);
                float v2 = fmaxf(acc[m][t][2]*visB[m] + g0, 0.f);
                float v3 = fmaxf(acc[m][t][3]*visB[m] + g1, 0.f);
                uint32_t off = (((uint32_t)(nw*4 + t) ^ swr) << 4);
                STSM2(bH + off, packh(v0, v1), packh(v2, v3));
            }
        }
    }
    __syncthreads();

    // ============ L5: score partials  K=128 N=64 (ba2 folded) ============
    {
        float acc[2][2][4];
        gemm<8,2>(BH_, 512, B5, mw, nw, lane, acc, &F[F_BA2]);
        float pA[2] = {0,0}, pB[2] = {0,0};
        #pragma unroll
        for (int t = 0; t < 2; t++){
            int c = nw*16 + t*8 + 2*tg;
            float w0 = F[F_WA3 + c], w1 = F[F_WA3 + c + 1];
            #pragma unroll
            for (int m = 0; m < 2; m++){
                pA[m] += fmaxf(acc[m][t][0], 0.f)*w0 + fmaxf(acc[m][t][1], 0.f)*w1;
                pB[m] += fmaxf(acc[m][t][2], 0.f)*w0 + fmaxf(acc[m][t][3], 0.f)*w1;
            }
        }
        #pragma unroll
        for (int m = 0; m < 2; m++){
            #pragma unroll
            for (int o = 1; o <= 2; o <<= 1){
                pA[m] += __shfl_xor_sync(0xffffffffu, pA[m], o);
                pB[m] += __shfl_xor_sync(0xffffffffu, pB[m], o);
            }
        }
        if (tg == 0){
            #pragma unroll
            for (int m = 0; m < 2; m++){
                F[F_SPART + nw*64 + R0 + m*16 + g]     = pA[m];
                F[F_SPART + nw*64 + R0 + m*16 + g + 8] = pB[m];
            }
        }
    }
    __syncthreads();

    // ---- softmax + coefficients + joint init ----
    {
        float e = 0.f;
        if (tid < 64){
            float s = F[F_SPART + tid] + F[F_SPART + 64 + tid]
                    + F[F_SPART + 128 + tid] + F[F_SPART + 192 + tid] + __ldg(&ba3[0]);
            e = (s != 0.f) ? expf(s) : 0.f;
            float t1 = e;
            #pragma unroll
            for (int o = 16; o > 0; o >>= 1) t1 += __shfl_xor_sync(0xffffffffu, t1, o);
            if (lane == 0) F[F_RED + wid] = t1;
        }
        __syncthreads();
        if (tid < 64){
            float ssum = F[F_RED] + F[F_RED + 1];
            float coef = (e / ssum) * F[F_VIS + tid];
            F[F_COEF + tid] = coef;
            float t2 = coef;
            #pragma unroll
            for (int o = 16; o > 0; o >>= 1) t2 += __shfl_xor_sync(0xffffffffu, t2, o);
            if (lane == 0) F[F_RED + 4 + wid] = t2;
        }
        __syncthreads();
        if (tid < 128){
            float csum = F[F_RED + 4] + F[F_RED + 5];
            F[F_JOINT + 9 + tid] = csum * F[F_B2B + tid];
        }
    }
    __syncthreads();

    // ============ L2: h2 = relu(m1 @ w2a + b2a)  K=128 N=256 ============
    {
        float acc[2][8][4];
        gemm<8,8>(MH_, 256, B2, mw, nw, lane, acc, &F[F_B2A]);
        #pragma unroll
        for (int m = 0; m < 2; m++){
            int rowm = R0 + m*16 + rl;
            uint32_t bH = BH_ + (uint32_t)rowm*512;
            uint32_t swr = (uint32_t)(rowm & 7);
            #pragma unroll
            for (int t = 0; t < 8; t++){
                uint32_t off = (((uint32_t)(nw*8 + t) ^ swr) << 4);
                float v0 = fmaxf(acc[m][t][0], 0.f);
                float v1 = fmaxf(acc[m][t][1], 0.f);
                float v2 = fmaxf(acc[m][t][2], 0.f);
                float v3 = fmaxf(acc[m][t][3], 0.f);
                STSM2(bH + off, packh(v0, v1), packh(v2, v3));
            }
        }
    }
    __syncthreads();

    // ============ L3: jp[mw] = coef . (h2 @ w2b)  K=256 N=128 ============
    {
        float acc[2][4][4];
        gemm<16,4>(BH_, 512, B3, mw, nw, lane, acc, nullptr);
        float cA[2], cB[2];
        #pragma unroll
        for (int m = 0; m < 2; m++){
            cA[m] = F[F_COEF + R0 + m*16 + g];
            cB[m] = F[F_COEF + R0 + m*16 + g + 8];
        }
        #pragma unroll
        for (int t = 0; t < 4; t++){
            int c = nw*32 + t*8 + 2*tg;
            float w0 = 0.f, w1 = 0.f;
            #pragma unroll
            for (int m = 0; m < 2; m++){
                w0 += cA[m]*acc[m][t][0] + cB[m]*acc[m][t][2];
                w1 += cA[m]*acc[m][t][1] + cB[m]*acc[m][t][3];
            }
            #pragma unroll
            for (int o = 4; o <= 16; o <<= 1){
                w0 += __shfl_xor_sync(0xffffffffu, w0, o);
                w1 += __shfl_xor_sync(0xffffffffu, w1, o);
            }
            if (lane < 4){
                F[F_JP + mw*128 + c]     = w0;
                F[F_JP + mw*128 + c + 1] = w1;
            }
        }
    }
    __syncthreads();
    if (tid < 128){
        F[F_JOINT + 9 + tid] += F[F_JP + tid] + F[F_JP + 128 + tid];
    }
    __syncthreads();

    // ============ final MLP: 137 -> 256 -> 128 -> 1 (fp32) ============
    {
        int n = tid;
        float a0 = __ldg(&b3a[n]), a1 = 0.f;
        const float* J = &F[F_JOINT];
        #pragma unroll 4
        for (int i = 0; i < 136; i += 2){
            a0 += J[i]   * __ldg(&w3a[i*256 + n]);
            a1 += J[i+1] * __ldg(&w3a[(i+1)*256 + n]);
        }
        a0 += J[136] * __ldg(&w3a[136*256 + n]);
        F[F_H3 + n] = fmaxf(a0 + a1, 0.f);
    }
    __syncthreads();
    {   // layer 2: 128 outputs, split-K x2 over 256 threads
        int n = tid & 127, half = tid >> 7;
        float a0 = half ? 0.f : __ldg(&b3b[n]);
        float a1 = 0.f;
        const float* H = &F[F_H3 + half*128];
        #pragma unroll 4
        for (int i = 0; i < 128; i += 2){
            a0 += H[i]   * __ldg(&w3b[(half*128 + i)*128 + n]);
            a1 += H[i+1] * __ldg(&w3b[(half*128 + i + 1)*128 + n]);
        }
        F[F_JP + tid] = a0 + a1;
    }
    __syncthreads();
    if (tid < 128){
        float p = fmaxf(F[F_JP + tid] + F[F_JP + 128 + tid], 0.f) * __ldg(&w3c[tid]);
        #pragma unroll
        for (int o = 16; o > 0; o >>= 1) p += __shfl_xor_sync(0xffffffffu, p, o);
        if (lane == 0) F[F_RED + wid] = p;
    }
    __syncthreads();
    if (tid == 0){
        out[blockIdx.x] = F[F_RED] + F[F_RED + 1] + F[F_RED + 2] + F[F_RED + 3]
                        + __ldg(&b3c[0]);
    }
}

extern "C" void kernel_launch(void* const* d_in, const int* in_sizes, int n_in,
                              void* d_out, int out_size)
{
    (void)in_sizes; (void)n_in; (void)out_size;
    const float* state = (const float*)d_in[0];
    const float* w1a = (const float*)d_in[1];  const float* b1a = (const float*)d_in[2];
    const float* w1b = (const float*)d_in[3];  const float* b1b = (const float*)d_in[4];
    const float* w2a = (const float*)d_in[5];  const float* b2a = (const float*)d_in[6];
    const float* w2b = (const float*)d_in[7];  const float* b2b = (const float*)d_in[8];
    const float* wa1 = (const float*)d_in[9];  const float* ba1 = (const float*)d_in[10];
    const float* wa2 = (const float*)d_in[11]; const float* ba2 = (const float*)d_in[12];
    const float* wa3 = (const float*)d_in[13]; const float* ba3 = (const float*)d_in[14];
    const float* w3a = (const float*)d_in[15]; const float* b3a = (const float*)d_in[16];
    const float* w3b = (const float*)d_in[17]; const float* b3b = (const float*)d_in[18];
    const float* w3c = (const float*)d_in[19]; const float* b3c = (const float*)d_in[20];
    float* out = (float*)d_out;

    prep_kernel<<<(34816 + 255)/256, 256>>>(w1a, w1b, w2a, w2b, wa1, wa2);

    cudaFuncSetAttribute(value_net_mma,
                         cudaFuncAttributeMaxDynamicSharedMemorySize, SMEM_BYTES);
    value_net_mma<<<4096, TPB, SMEM_BYTES>>>(
        state, b1a, b1b, b2a, b2b, wa1, ba1, ba2, wa3, ba3,
        w3a, b3a, w3b, b3b, w3c, b3c, out);
}

// round 14
// speedup vs baseline: 8.5631x; 1.2887x over previous
#include <cuda_runtime.h>
#include <cuda_fp16.h>
#include <cstdint>

#define TPB 256

// ===================== PTX wrappers =====================
__device__ __forceinline__ uint32_t smem_u32(const void* p){
    uint32_t a;
    asm("{ .reg .u64 t; cvta.to.shared.u64 t, %1; cvt.u32.u64 %0, t; }":"=r"(a):"l"(p));
    return a;
}
#define LDSM4(r, a) \
    asm volatile("ldmatrix.sync.aligned.m8n8.x4.shared.b16 {%0,%1,%2,%3}, [%4];" \
        :"=r"((r)[0]),"=r"((r)[1]),"=r"((r)[2]),"=r"((r)[3]):"r"(a))
#define STSM2(a, r0, r1) \
    asm volatile("stmatrix.sync.aligned.m8n8.x2.shared.b16 [%0], {%1,%2};" \
        :: "r"(a), "r"(r0), "r"(r1) : "memory")
#define MMA_F16(c, a, b) \
    asm volatile("mma.sync.aligned.m16n8k16.row.col.f32.f16.f16.f32 " \
        "{%0,%1,%2,%3},{%4,%5,%6,%7},{%8,%9},{%0,%1,%2,%3};" \
        :"+f"((c)[0]),"+f"((c)[1]),"+f"((c)[2]),"+f"((c)[3]) \
        :"r"((a)[0]),"r"((a)[1]),"r"((a)[2]),"r"((a)[3]),"r"((b)[0]),"r"((b)[1]))

__device__ __forceinline__ uint32_t packh(float v0, float v1){
    __half2 H = __floats2half2_rn(v0, v1);
    return *(uint32_t*)&H;
}
__device__ __forceinline__ void swst(uint8_t* plane, int P, int r, int nc, uint32_t v){
    *(uint32_t*)(plane + r*P + ((((nc>>3) ^ (r&7)) << 4) | ((nc<<1) & 15))) = v;
}

// ===================== packed weights =====================
// [0, 278528): MMA fragment-packed (fp16, 8B/lane)
// [278528, 350208): w3a quad-packed  (35 x 256 uint2; rows >=137 zero)
// [350208, 415744): w3b quad-packed  (64 x 128 uint2)
// [415744, 448512): wa1 tail rows 128..255 quad-packed (32 x 128 uint2)
#define W3A4_OFF 278528
#define W3B4_OFF 350208
#define WA1T_OFF 415744
__device__ __align__(128) uint8_t g_wb[448512];

__global__ void prep_kernel(const float* __restrict__ w1a, const float* __restrict__ w1b,
                            const float* __restrict__ w2a, const float* __restrict__ w2b,
                            const float* __restrict__ wa1, const float* __restrict__ wa2,
                            const float* __restrict__ w3a, const float* __restrict__ w3b)
{
    int idx = blockIdx.x * blockDim.x + threadIdx.x;
    if (idx < 34816){
        const float* W[6] = {w1a, w1b, w2a, w2b, wa1, wa2};
        const int   NN[6] = {256, 128, 256, 128, 128, 64};
        const int   KS[6] = {4, 16, 8, 16, 8, 8};
        const int   EO[7] = {0, 4096, 12288, 20480, 28672, 32768, 34816};
        const int   BO[6] = {0, 32768, 98304, 163840, 229376, 262144};
        int l = 0;
        while (idx >= EO[l+1]) l++;
        int e = idx - EO[l];
        int lane = e & 31, qq = e >> 5;
        int s = qq % KS[l], T = qq / KS[l];
        int tg = lane & 3, g = lane >> 2;
        int n = T*8 + g;
        int k0 = s*16 + 2*tg;
        int N = NN[l];
        const float* Wl = W[l];
        __half2 H0 = __floats2half2_rn(Wl[(k0  )*N + n], Wl[(k0+1)*N + n]);
        __half2 H1 = __floats2half2_rn(Wl[(k0+8)*N + n], Wl[(k0+9)*N + n]);
        uint2 o;
        o.x = *(uint32_t*)&H0; o.y = *(uint32_t*)&H1;
        *(uint2*)(g_wb + BO[l] + (size_t)e*8) = o;
        return;
    }
    int e = idx - 34816;
    if (e < 8960){           // w3a: q = e/256 (i-quad), n = e%256
        int q = e >> 8, n = e & 255;
        float v[4];
        #pragma unroll
        for (int r = 0; r < 4; r++){
            int i = 4*q + r;
            v[r] = (i < 137) ? w3a[i*256 + n] : 0.f;
        }
        __half2 H0 = __floats2half2_rn(v[0], v[1]);
        __half2 H1 = __floats2half2_rn(v[2], v[3]);
        uint2 o; o.x = *(uint32_t*)&H0; o.y = *(uint32_t*)&H1;
        *(uint2*)(g_wb + W3A4_OFF + (size_t)e*8) = o;
    } else if (e < 8960 + 8192){   // w3b
        int e2 = e - 8960;
        int q = e2 >> 7, n = e2 & 127;
        __half2 H0 = __floats2half2_rn(w3b[(4*q  )*128 + n], w3b[(4*q+1)*128 + n]);
        __half2 H1 = __floats2half2_rn(w3b[(4*q+2)*128 + n], w3b[(4*q+3)*128 + n]);
        uint2 o; o.x = *(uint32_t*)&H0; o.y = *(uint32_t*)&H1;
        *(uint2*)(g_wb + W3B4_OFF + (size_t)e2*8) = o;
    } else if (e < 8960 + 8192 + 4096){   // wa1 tail
        int e3 = e - 8960 - 8192;
        int q = e3 >> 7, n = e3 & 127;
        __half2 H0 = __floats2half2_rn(wa1[(128+4*q  )*128 + n], wa1[(129+4*q)*128 + n]);
        __half2 H1 = __floats2half2_rn(wa1[(130+4*q)*128 + n], wa1[(131+4*q)*128 + n]);
        uint2 o; o.x = *(uint32_t*)&H0; o.y = *(uint32_t*)&H1;
        *(uint2*)(g_wb + WA1T_OFF + (size_t)e3*8) = o;
    }
}

// ===================== smem layout (per CTA, ~57 KB) =====================
#define OFF_BH   0          // big act: 64 x 512B
#define OFF_MH   32768      // m1/x act: 64 x 256B
#define OFF_F    49152
#define F_B1A   0
#define F_B1B   256
#define F_B2A   384
#define F_B2B   640
#define F_BA2   768
#define F_WA3   832
#define F_VIS   896
#define F_GSP   960       // [2][128]
#define F_SPART 1216      // [4][64] (also split-K scratch)
#define F_COEF  1472
#define F_GSB   1536      // [128]
#define F_JP    1664      // [2][128]
#define F_JOINT 1920      // [160] (137..159 zeroed)
#define F_RED   2080
#define F_H3    2096      // [256]
#define F_TOT   2352
#define SMEM_BYTES (OFF_F + F_TOT*4)   // 58560

// ========== GEMM: M=64, 8 warps 2(M)x4(N), warp tile 32 x NT*8, fp16 ==========
template<int KSTEPS, int NT>
__device__ __forceinline__ void gemm(uint32_t aH, int P,
                                     const uint2* __restrict__ Bf,
                                     int mw, int nw, int lane,
                                     float (&acc)[2][NT][4],
                                     const float* __restrict__ bias)
{
    const int tg2 = (lane & 3) * 2;
    #pragma unroll
    for (int t = 0; t < NT; t++){
        float b0 = 0.f, b1 = 0.f;
        if (bias){
            int c = nw*(NT*8) + t*8 + tg2;
            b0 = bias[c]; b1 = bias[c + 1];
        }
        #pragma unroll
        for (int m = 0; m < 2; m++){
            acc[m][t][0] = b0; acc[m][t][1] = b1;
            acc[m][t][2] = b0; acc[m][t][3] = b1;
        }
    }

    const uint32_t rowoff = (uint32_t)((mw*32 + (lane & 15)) * P);
    const uint32_t chi = (uint32_t)(lane >> 4);
    const uint32_t swr = (uint32_t)(lane & 7);
    const uint2* bp = Bf + (size_t)(nw*NT)*KSTEPS*32 + lane;

    #pragma unroll 2
    for (int s = 0; s < KSTEPS; s++){
        uint32_t co = (((2u*s + chi) ^ swr) << 4);
        uint32_t AH[2][4];
        #pragma unroll
        for (int m = 0; m < 2; m++)
            LDSM4(AH[m], aH + rowoff + (uint32_t)(m*16*P) + co);
        const uint2* bps = bp + (size_t)s*32;
        #pragma unroll
        for (int t = 0; t < NT; t++){
            uint2 bb = __ldg(bps + (size_t)t*KSTEPS*32);
            uint32_t BH[2] = {bb.x, bb.y};
            #pragma unroll
            for (int m = 0; m < 2; m++)
                MMA_F16(acc[m][t], AH[m], BH);
        }
    }
}

__global__ void __launch_bounds__(TPB, 3)
value_net_mma(const float* __restrict__ state,
              const float* __restrict__ b1a, const float* __restrict__ b1b,
              const float* __restrict__ b2a, const float* __restrict__ b2b,
              const float* __restrict__ ba1, const float* __restrict__ ba2,
              const float* __restrict__ wa3, const float* __restrict__ ba3,
              const float* __restrict__ b3a, const float* __restrict__ b3b,
              const float* __restrict__ w3c, const float* __restrict__ b3c,
              float* __restrict__ out)
{
    extern __shared__ __align__(128) uint8_t sm[];
    float* F = (float*)(sm + OFF_F);
    const int tid  = threadIdx.x;
    const int lane = tid & 31;
    const int wid  = tid >> 5;
    const int mw   = wid & 1;
    const int nw   = wid >> 1;
    const int g    = lane >> 2;
    const int tg   = lane & 3;
    const int R0   = mw * 32;
    const int rl   = lane & 15;

    const uint32_t sb = smem_u32(sm);
    const uint32_t BH_ = sb + OFF_BH;
    const uint32_t MH_ = sb + OFF_MH;
    uint8_t* pMH = sm + OFF_MH;

    const uint2* B0 = (const uint2*)(g_wb + 0);
    const uint2* B1 = (const uint2*)(g_wb + 32768);
    const uint2* B2 = (const uint2*)(g_wb + 98304);
    const uint2* B3 = (const uint2*)(g_wb + 163840);
    const uint2* B4 = (const uint2*)(g_wb + 229376);
    const uint2* B5 = (const uint2*)(g_wb + 262144);

    // ---- stage x (64 rows x 64) + scalars ----
    {
        int row = tid >> 2, qd = tid & 3;
        const float* xr = state + (size_t)blockIdx.x*4096 + row*64 + qd*16;
        float xv[16];
        #pragma unroll
        for (int j = 0; j < 4; j++) ((float4*)xv)[j] = __ldg((const float4*)(xr + 4*j));
        #pragma unroll
        for (int j = 0; j < 8; j++){
            int nc = qd*16 + 2*j;
            swst(pMH, 256, row, nc, packh(xv[2*j], xv[2*j+1]));
        }
        if (qd == 3) F[F_VIS + row] = (xv[13] > 0.f) ? 1.f : 0.f;   // col 61
        if (tid == 0){
            #pragma unroll
            for (int i = 0; i < 9; i++) F[F_JOINT + i] = xv[i];
        }
        if (tid >= 137 && tid < 160) F[F_JOINT + tid] = 0.f;
        F[F_B1A + tid] = __ldg(&b1a[tid]);
        F[F_B2A + tid] = __ldg(&b2a[tid]);
        if (tid < 128){ F[F_B1B + tid] = __ldg(&b1b[tid]); F[F_B2B + tid] = __ldg(&b2b[tid]); }
        if (tid < 64){  F[F_BA2 + tid] = __ldg(&ba2[tid]); F[F_WA3 + tid] = __ldg(&wa3[tid]); }
    }
    __syncthreads();

    // ============ L0: h1 = relu(x @ w1a + b1a)  K=64 N=256, two NT=4 passes ====
    #pragma unroll
    for (int p = 0; p < 2; p++){
        float acc[2][4][4];
        gemm<4,4>(MH_, 256, B0 + p*2048, mw, nw, lane, acc, &F[F_B1A + p*128]);
        #pragma unroll
        for (int m = 0; m < 2; m++){
            int rowm = R0 + m*16 + rl;
            uint32_t bH = BH_ + (uint32_t)rowm*512;
            uint32_t swr = (uint32_t)(rowm & 7);
            #pragma unroll
            for (int t = 0; t < 4; t++){
                uint32_t off = (((uint32_t)(p*16 + nw*4 + t) ^ swr) << 4);
                float v0 = fmaxf(acc[m][t][0], 0.f);
                float v1 = fmaxf(acc[m][t][1], 0.f);
                float v2 = fmaxf(acc[m][t][2], 0.f);
                float v3 = fmaxf(acc[m][t][3], 0.f);
                STSM2(bH + off, packh(v0, v1), packh(v2, v3));
            }
        }
    }
    __syncthreads();

    // ============ L1: m1 = relu(h1 @ w1b + b1b)  K=256 N=128 ============
    {
        float acc[2][4][4];
        gemm<16,4>(BH_, 512, B1, mw, nw, lane, acc, &F[F_B1B]);
        float visA[2], visB[2];
        #pragma unroll
        for (int m = 0; m < 2; m++){
            visA[m] = F[F_VIS + R0 + m*16 + g];
            visB[m] = F[F_VIS + R0 + m*16 + g + 8];
        }
        #pragma unroll
        for (int m = 0; m < 2; m++){
            int rowm = R0 + m*16 + rl;
            uint32_t bH = MH_ + (uint32_t)rowm*256;
            uint32_t swr = (uint32_t)(rowm & 7);
            #pragma unroll
            for (int t = 0; t < 4; t++){
                float v0 = fmaxf(acc[m][t][0], 0.f);
                float v1 = fmaxf(acc[m][t][1], 0.f);
                float v2 = fmaxf(acc[m][t][2], 0.f);
                float v3 = fmaxf(acc[m][t][3], 0.f);
                uint32_t off = (((uint32_t)(nw*4 + t) ^ swr) << 4);
                STSM2(bH + off, packh(v0, v1), packh(v2, v3));   // UNMASKED m1
                float g0 = v0*visA[m] + v2*visB[m];
                float g1 = v1*visA[m] + v3*visB[m];
                #pragma unroll
                for (int o = 4; o <= 16; o <<= 1){
                    g0 += __shfl_xor_sync(0xffffffffu, g0, o);
                    g1 += __shfl_xor_sync(0xffffffffu, g1, o);
                }
                if (lane < 4){
                    int c = nw*32 + t*8 + 2*tg;
                    if (m == 0){
                        F[F_GSP + mw*128 + c]     = g0;
                        F[F_GSP + mw*128 + c + 1] = g1;
                    } else {
                        F[F_GSP + mw*128 + c]     += g0;
                        F[F_GSP + mw*128 + c + 1] += g1;
                    }
                }
            }
        }
    }
    __syncthreads();
    // gsb partials via packed wa1 tail (split-K x2, quad loads)
    {
        int n = tid & 127, half = tid >> 7;
        const float* g0p = &F[F_GSP];
        const float* g1p = &F[F_GSP + 128];
        const uint2* Wp = (const uint2*)(g_wb + WA1T_OFF) + half*16*128 + n;
        float a = 0.f;
        #pragma unroll 4
        for (int q = 0; q < 16; q++){
            uint2 w = __ldg(Wp + q*128);
            float2 f0 = __half22float2(*(__half2*)&w.x);
            float2 f1 = __half22float2(*(__half2*)&w.y);
            int j = half*64 + 4*q;
            a += (g0p[j]   + g1p[j]  ) * f0.x + (g0p[j+1] + g1p[j+1]) * f0.y
               + (g0p[j+2] + g1p[j+2]) * f1.x + (g0p[j+3] + g1p[j+3]) * f1.y;
        }
        F[F_SPART + tid] = a;
    }
    __syncthreads();
    if (tid < 128){
        F[F_GSB + tid] = (F[F_SPART + tid] + F[F_SPART + 128 + tid]) * (1.f/64.f)
                       + __ldg(&ba1[tid]);
    }
    __syncthreads();

    // ============ L4: att1 = relu(vis*(m1 @ wa1a) + gsb)  K=128 N=128 ============
    {
        float acc[2][4][4];
        gemm<8,4>(MH_, 256, B4, mw, nw, lane, acc, nullptr);
        float visA[2], visB[2];
        #pragma unroll
        for (int m = 0; m < 2; m++){
            visA[m] = F[F_VIS + R0 + m*16 + g];
            visB[m] = F[F_VIS + R0 + m*16 + g + 8];
        }
        #pragma unroll
        for (int m = 0; m < 2; m++){
            int rowm = R0 + m*16 + rl;
            uint32_t bH = BH_ + (uint32_t)rowm*512;
            uint32_t swr = (uint32_t)(rowm & 7);
            #pragma unroll
            for (int t = 0; t < 4; t++){
                int c = nw*32 + t*8 + 2*tg;
                float g0 = F[F_GSB + c], g1 = F[F_GSB + c + 1];
                float v0 = fmaxf(acc[m][t][0]*visA[m] + g0, 0.f);
                float v1 = fmaxf(acc[m][t][1]*visA[m] + g1, 0.f);
                float v2 = fmaxf(acc[m][t][2]*visB[m] + g0, 0.f);
                float v3 = fmaxf(acc[m][t][3]*visB[m] + g1, 0.f);
                uint32_t off = (((uint32_t)(nw*4 + t) ^ swr) << 4);
                STSM2(bH + off, packh(v0, v1), packh(v2, v3));
            }
        }
    }
    __syncthreads();

    // ============ L5: score partials  K=128 N=64 (ba2 folded) ============
    {
        float acc[2][2][4];
        gemm<8,2>(BH_, 512, B5, mw, nw, lane, acc, &F[F_BA2]);
        float pA[2] = {0,0}, pB[2] = {0,0};
        #pragma unroll
        for (int t = 0; t < 2; t++){
            int c = nw*16 + t*8 + 2*tg;
            float w0 = F[F_WA3 + c], w1 = F[F_WA3 + c + 1];
            #pragma unroll
            for (int m = 0; m < 2; m++){
                pA[m] += fmaxf(acc[m][t][0], 0.f)*w0 + fmaxf(acc[m][t][1], 0.f)*w1;
                pB[m] += fmaxf(acc[m][t][2], 0.f)*w0 + fmaxf(acc[m][t][3], 0.f)*w1;
            }
        }
        #pragma unroll
        for (int m = 0; m < 2; m++){
            #pragma unroll
            for (int o = 1; o <= 2; o <<= 1){
                pA[m] += __shfl_xor_sync(0xffffffffu, pA[m], o);
                pB[m] += __shfl_xor_sync(0xffffffffu, pB[m], o);
            }
        }
        if (tg == 0){
            #pragma unroll
            for (int m = 0; m < 2; m++){
                F[F_SPART + nw*64 + R0 + m*16 + g]     = pA[m];
                F[F_SPART + nw*64 + R0 + m*16 + g + 8] = pB[m];
            }
        }
    }
    __syncthreads();

    // ---- softmax + coefficients + joint init ----
    {
        float e = 0.f;
        if (tid < 64){
            float s = F[F_SPART + tid] + F[F_SPART + 64 + tid]
                    + F[F_SPART + 128 + tid] + F[F_SPART + 192 + tid] + __ldg(&ba3[0]);
            e = (s != 0.f) ? expf(s) : 0.f;
            float t1 = e;
            #pragma unroll
            for (int o = 16; o > 0; o >>= 1) t1 += __shfl_xor_sync(0xffffffffu, t1, o);
            if (lane == 0) F[F_RED + wid] = t1;
        }
        __syncthreads();
        if (tid < 64){
            float ssum = F[F_RED] + F[F_RED + 1];
            float coef = (e / ssum) * F[F_VIS + tid];
            F[F_COEF + tid] = coef;
            float t2 = coef;
            #pragma unroll
            for (int o = 16; o > 0; o >>= 1) t2 += __shfl_xor_sync(0xffffffffu, t2, o);
            if (lane == 0) F[F_RED + 4 + wid] = t2;
        }
        __syncthreads();
        if (tid < 128){
            float csum = F[F_RED + 4] + F[F_RED + 5];
            F[F_JOINT + 9 + tid] = csum * F[F_B2B + tid];
        }
    }
    __syncthreads();

    // ============ L2: h2 = relu(m1 @ w2a + b2a)  K=128 N=256, two NT=4 passes ===
    #pragma unroll
    for (int p = 0; p < 2; p++){
        float acc[2][4][4];
        gemm<8,4>(MH_, 256, B2 + p*4096, mw, nw, lane, acc, &F[F_B2A + p*128]);
        #pragma unroll
        for (int m = 0; m < 2; m++){
            int rowm = R0 + m*16 + rl;
            uint32_t bH = BH_ + (uint32_t)rowm*512;
            uint32_t swr = (uint32_t)(rowm & 7);
            #pragma unroll
            for (int t = 0; t < 4; t++){
                uint32_t off = (((uint32_t)(p*16 + nw*4 + t) ^ swr) << 4);
                float v0 = fmaxf(acc[m][t][0], 0.f);
                float v1 = fmaxf(acc[m][t][1], 0.f);
                float v2 = fmaxf(acc[m][t][2], 0.f);
                float v3 = fmaxf(acc[m][t][3], 0.f);
                STSM2(bH + off, packh(v0, v1), packh(v2, v3));
            }
        }
    }
    __syncthreads();

    // ============ L3: jp[mw] = coef . (h2 @ w2b)  K=256 N=128 ============
    {
        float acc[2][4][4];
        gemm<16,4>(BH_, 512, B3, mw, nw, lane, acc, nullptr);
        float cA[2], cB[2];
        #pragma unroll
        for (int m = 0; m < 2; m++){
            cA[m] = F[F_COEF + R0 + m*16 + g];
            cB[m] = F[F_COEF + R0 + m*16 + g + 8];
        }
        #pragma unroll
        for (int t = 0; t < 4; t++){
            int c = nw*32 + t*8 + 2*tg;
            float w0 = 0.f, w1 = 0.f;
            #pragma unroll
            for (int m = 0; m < 2; m++){
                w0 += cA[m]*acc[m][t][0] + cB[m]*acc[m][t][2];
                w1 += cA[m]*acc[m][t][1] + cB[m]*acc[m][t][3];
            }
            #pragma unroll
            for (int o = 4; o <= 16; o <<= 1){
                w0 += __shfl_xor_sync(0xffffffffu, w0, o);
                w1 += __shfl_xor_sync(0xffffffffu, w1, o);
            }
            if (lane < 4){
                F[F_JP + mw*128 + c]     = w0;
                F[F_JP + mw*128 + c + 1] = w1;
            }
        }
    }
    __syncthreads();
    if (tid < 128){
        F[F_JOINT + 9 + tid] += F[F_JP + tid] + F[F_JP + 128 + tid];
    }
    __syncthreads();

    // ============ final MLP: 137 -> 256 -> 128 -> 1 (fp16 quad weights) ========
    {
        int n = tid;
        float a = __ldg(&b3a[n]);
        const float* J = &F[F_JOINT];
        const uint2* Wp = (const uint2*)(g_wb + W3A4_OFF) + n;
        #pragma unroll 5
        for (int q = 0; q < 35; q++){
            uint2 w = __ldg(Wp + q*256);
            float2 f0 = __half22float2(*(__half2*)&w.x);
            float2 f1 = __half22float2(*(__half2*)&w.y);
            a += J[4*q]*f0.x + J[4*q+1]*f0.y + J[4*q+2]*f1.x + J[4*q+3]*f1.y;
        }
        F[F_H3 + n] = fmaxf(a, 0.f);
    }
    __syncthreads();
    {   // layer 2: 128 outputs, split-K x2 over 256 threads, quad loads
        int n = tid & 127, half = tid >> 7;
        float a = half ? 0.f : __ldg(&b3b[n]);
        const float* H = &F[F_H3 + half*128];
        const uint2* Wp = (const uint2*)(g_wb + W3B4_OFF) + half*32*128 + n;
        #pragma unroll 4
        for (int q = 0; q < 32; q++){
            uint2 w = __ldg(Wp + q*128);
            float2 f0 = __half22float2(*(__half2*)&w.x);
            float2 f1 = __half22float2(*(__half2*)&w.y);
            a += H[4*q]*f0.x + H[4*q+1]*f0.y + H[4*q+2]*f1.x + H[4*q+3]*f1.y;
        }
        F[F_JP + tid] = a;
    }
    __syncthreads();
    if (tid < 128){
        float p = fmaxf(F[F_JP + tid] + F[F_JP + 128 + tid], 0.f) * __ldg(&w3c[tid]);
        #pragma unroll
        for (int o = 16; o > 0; o >>= 1) p += __shfl_xor_sync(0xffffffffu, p, o);
        if (lane == 0) F[F_RED + wid] = p;
    }
    __syncthreads();
    if (tid == 0){
        out[blockIdx.x] = F[F_RED] + F[F_RED + 1] + F[F_RED + 2] + F[F_RED + 3]
                        + __ldg(&b3c[0]);
    }
}

extern "C" void kernel_launch(void* const* d_in, const int* in_sizes, int n_in,
                              void* d_out, int out_size)
{
    (void)in_sizes; (void)n_in; (void)out_size;
    const float* state = (const float*)d_in[0];
    const float* w1a = (const float*)d_in[1];  const float* b1a = (const float*)d_in[2];
    const float* w1b = (const float*)d_in[3];  const float* b1b = (const float*)d_in[4];
    const float* w2a = (const float*)d_in[5];  const float* b2a = (const float*)d_in[6];
    const float* w2b = (const float*)d_in[7];  const float* b2b = (const float*)d_in[8];
    const float* wa1 = (const float*)d_in[9];  const float* ba1 = (const float*)d_in[10];
    const float* wa2 = (const float*)d_in[11]; const float* ba2 = (const float*)d_in[12];
    const float* wa3 = (const float*)d_in[13]; const float* ba3 = (const float*)d_in[14];
    const float* w3a = (const float*)d_in[15]; const float* b3a = (const float*)d_in[16];
    const float* w3b = (const float*)d_in[17]; const float* b3b = (const float*)d_in[18];
    const float* w3c = (const float*)d_in[19]; const float* b3c = (const float*)d_in[20];
    float* out = (float*)d_out;

    prep_kernel<<<(56064 + 255)/256, 256>>>(w1a, w1b, w2a, w2b, wa1, wa2, w3a, w3b);

    cudaFuncSetAttribute(value_net_mma,
                         cudaFuncAttributeMaxDynamicSharedMemorySize, SMEM_BYTES);
    value_net_mma<<<4096, TPB, SMEM_BYTES>>>(
        state, b1a, b1b, b2a, b2b, ba1, ba2, wa3, ba3,
        b3a, b3b, w3c, b3c, out);
}